// round 7
// baseline (speedup 1.0000x reference)
#include <cuda_runtime.h>
#include <cuda.h>
#include <dlfcn.h>
#include <math.h>
#include <stdint.h>

// ---------------- problem constants ----------------
#define T_DIM 1024
#define B_DIM 8
#define C_DIM 1024
#define F_DIM 4096
#define H_DIM 16
#define K_TAPS 15
#define M_DIM (T_DIM * B_DIM)   // 8192
#define NPAD 256
#define LN_EPS 1e-5f

#define BK 32                   // floats per k-chunk (128 bytes per row)

// dynconv tiling
#define TT 32
#define HALO (K_TAPS - 1)
#define XS_ROWS (TT + HALO)
#define DC_SMEM ((XS_ROWS * C_DIM + TT * (H_DIM * K_TAPS) + 64) * 4)

// arch-specific feature gate (tcgen05/multicast only on the sm_103a pass)
#if defined(__CUDA_ARCH_FEAT_SM103_ALL) || defined(__CUDA_ARCH_FEAT_SM100_ALL) || \
    (defined(__CUDA_ARCH_SPECIFIC__) && (__CUDA_ARCH_SPECIFIC__ >= 1000)) ||      \
    (defined(__CUDA_ARCH_FAMILY_SPECIFIC__) && (__CUDA_ARCH_FAMILY_SPECIFIC__ >= 1000))
#define TC_OK 1
#else
#define TC_OK 0
#endif

// ---------------- scratch (device globals) ----------------
__device__ float g_wlinT[NPAD * C_DIM];
__device__ float g_fc1wT[(size_t)F_DIM * C_DIM];
__device__ float g_fc2wT[(size_t)C_DIM * F_DIM];
__device__ float g_wraw[(size_t)M_DIM * NPAD];
__device__ float g_y[(size_t)M_DIM * C_DIM];
__device__ float g_yrn[(size_t)M_DIM * C_DIM];
__device__ float g_h[(size_t)M_DIM * F_DIM];

// ---------------- helpers ----------------
__device__ __forceinline__ float to_tf32(float x) {
    float r;
    asm("cvt.rna.tf32.f32 %0, %1;" : "=f"(r) : "f"(x));
    return r;
}
__device__ __forceinline__ uint32_t smem_u32(const void* p) {
    uint32_t a;
    asm("{ .reg .u64 t; cvta.to.shared.u64 t, %1; cvt.u32.u64 %0, t; }" : "=r"(a) : "l"(p));
    return a;
}
__device__ __forceinline__ uint32_t elect_one() {
    uint32_t p;
    asm volatile("{ .reg .pred p; elect.sync _|p, 0xFFFFFFFF; selp.b32 %0, 1, 0, p; }" : "=r"(p));
    return p;
}
__device__ __forceinline__ void mbar_init(uint32_t a, uint32_t cnt) {
    asm volatile("mbarrier.init.shared.b64 [%0], %1;" :: "r"(a), "r"(cnt) : "memory");
}
__device__ __forceinline__ void mbar_expect_tx(uint32_t a, uint32_t bytes) {
    asm volatile("mbarrier.arrive.expect_tx.shared.b64 _, [%0], %1;" :: "r"(a), "r"(bytes) : "memory");
}
__device__ __forceinline__ void mbar_wait(uint32_t a, uint32_t parity) {
    uint32_t done;
    asm volatile(
        "{ .reg .pred p;\n\t"
        "mbarrier.try_wait.parity.acquire.cta.shared::cta.b64 p, [%1], %2;\n\t"
        "selp.b32 %0, 1, 0, p; }" : "=r"(done) : "r"(a), "r"(parity) : "memory");
    if (!done) {
        asm volatile(
            "{ .reg .pred P1;\n\t"
            "WL_%=:\n\t"
            "mbarrier.try_wait.parity.acquire.cta.shared::cta.b64 P1, [%0], %1, 0x989680;\n\t"
            "@P1 bra.uni WD_%=;\n\t"
            "bra.uni WL_%=;\n\t"
            "WD_%=: }" :: "r"(a), "r"(parity) : "memory");
    }
}
#if TC_OK
__device__ __forceinline__ uint32_t cluster_rank() {
    uint32_t r;
    asm("mov.u32 %0, %%cluster_ctarank;" : "=r"(r));
    return r;
}
__device__ __forceinline__ void mbar_arrive_cluster(uint32_t local_addr, uint32_t target_rank) {
    asm volatile(
        "{ .reg .b32 ra;\n\t"
        "mapa.shared::cluster.u32 ra, %0, %1;\n\t"
        "mbarrier.arrive.shared::cluster.b64 _, [ra]; }"
        :: "r"(local_addr), "r"(target_rank) : "memory");
}
#define CLUSTER_SYNC() do { \
    asm volatile("barrier.cluster.arrive.aligned;" ::: "memory"); \
    asm volatile("barrier.cluster.wait.aligned;" ::: "memory");   \
} while (0)

__device__ __forceinline__ void tma_2d(uint32_t dst, const void* map, int cx, int cy, uint32_t mbar) {
    asm volatile(
        "cp.async.bulk.tensor.2d.shared::cta.global.tile.mbarrier::complete_tx::bytes "
        "[%0], [%1, {%2, %3}], [%4];"
        :: "r"(dst), "l"(map), "r"(cx), "r"(cy), "r"(mbar) : "memory");
}
__device__ __forceinline__ void tma_2d_mcast(uint32_t dst, const void* map, int cx, int cy,
                                             uint32_t mbar, uint16_t mask) {
    asm volatile(
        "cp.async.bulk.tensor.2d.shared::cluster.global.tile.mbarrier::complete_tx::bytes"
        ".multicast::cluster [%0], [%1, {%2, %3}], [%4], %5;"
        :: "r"(dst), "l"(map), "r"(cx), "r"(cy), "r"(mbar), "h"(mask) : "memory");
}
__device__ __forceinline__ void mma_tf32_ss(uint32_t d, uint64_t adesc, uint64_t bdesc,
                                            uint32_t idesc, uint32_t en) {
    asm volatile(
        "{ .reg .pred p;\n\t"
        "setp.ne.u32 p, %4, 0;\n\t"
        "tcgen05.mma.cta_group::1.kind::tf32 [%0], %1, %2, %3, p; }"
        :: "r"(d), "l"(adesc), "l"(bdesc), "r"(idesc), "r"(en) : "memory");
}
__device__ __forceinline__ void tc_commit(uint32_t mbar) {
    asm volatile(
        "tcgen05.commit.cta_group::1.mbarrier::arrive::one.shared::cluster.b64 [%0];"
        :: "r"(mbar) : "memory");
}
#define TC_ALLOC(smem_addr, ncols) \
    asm volatile("tcgen05.alloc.cta_group::1.sync.aligned.shared::cta.b32 [%0], %1;" \
                 :: "r"(smem_addr), "r"(ncols) : "memory")
#define TC_RELINQ() \
    asm volatile("tcgen05.relinquish_alloc_permit.cta_group::1.sync.aligned;")
#define TC_DEALLOC(tmem, ncols) \
    asm volatile("tcgen05.dealloc.cta_group::1.sync.aligned.b32 %0, %1;" :: "r"(tmem), "r"(ncols))
#define TC_FENCE_AFTER()  asm volatile("tcgen05.fence::after_thread_sync;" ::: "memory")
#define TC_WAIT_LD()      asm volatile("tcgen05.wait::ld.sync.aligned;" ::: "memory")
#define TC_LD_X32(r, addr) \
    asm volatile("tcgen05.ld.sync.aligned.32x32b.x32.b32 " \
        "{%0, %1, %2, %3, %4, %5, %6, %7, %8, %9, %10, %11, %12, %13, %14, %15, " \
        " %16, %17, %18, %19, %20, %21, %22, %23, %24, %25, %26, %27, %28, %29, %30, %31}, [%32];" \
        : "=r"((r)[0]), "=r"((r)[1]), "=r"((r)[2]), "=r"((r)[3]), \
          "=r"((r)[4]), "=r"((r)[5]), "=r"((r)[6]), "=r"((r)[7]), \
          "=r"((r)[8]), "=r"((r)[9]), "=r"((r)[10]), "=r"((r)[11]), \
          "=r"((r)[12]), "=r"((r)[13]), "=r"((r)[14]), "=r"((r)[15]), \
          "=r"((r)[16]), "=r"((r)[17]), "=r"((r)[18]), "=r"((r)[19]), \
          "=r"((r)[20]), "=r"((r)[21]), "=r"((r)[22]), "=r"((r)[23]), \
          "=r"((r)[24]), "=r"((r)[25]), "=r"((r)[26]), "=r"((r)[27]), \
          "=r"((r)[28]), "=r"((r)[29]), "=r"((r)[30]), "=r"((r)[31]) \
        : "r"(addr))

__device__ __forceinline__ uint64_t smem_desc_sw128(uint32_t addr) {
    return ((uint64_t)2 << 61) | ((uint64_t)1 << 46) | ((uint64_t)64 << 32) |
           ((uint64_t)1 << 16) | (((uint64_t)addr >> 4) & 0x3FFF);
}
__device__ __forceinline__ constexpr uint32_t idesc_tf32(int bn) {
    return (1u << 4) | (2u << 7) | (2u << 10) | ((uint32_t)(bn / 8) << 17) | (8u << 24);
}
#endif  // TC_OK

// shared epilogue (TC_OK only)
#if TC_OK
template <int EPI, int MH, int BN_>
__device__ __forceinline__ void gemm_epilogue(uint32_t tmem, int tile_m, int tile_n,
                                              const float* __restrict__ bias,
                                              const float* __restrict__ res,
                                              float* __restrict__ C, int N,
                                              int warp, int lane) {
    const int half = warp >> 2;
    uint32_t dbase;
    int row, col0, nchunk;
    if (MH == 2) {
        dbase = tmem + half * BN_;
        row = tile_m + half * 128 + (warp & 3) * 32 + lane;
        col0 = tile_n;
        nchunk = BN_ / 32;
    } else {
        dbase = tmem + half * (BN_ / 2);
        row = tile_m + (warp & 3) * 32 + lane;
        col0 = tile_n + half * (BN_ / 2);
        nchunk = BN_ / 64;
    }
    #pragma unroll 1
    for (int cc = 0; cc < nchunk; cc++) {
        uint32_t r[32];
        TC_LD_X32(r, dbase + cc * 32);
        TC_WAIT_LD();
        const int colbase = col0 + cc * 32;
        float4* dst = reinterpret_cast<float4*>(&C[(size_t)row * N + colbase]);
        #pragma unroll
        for (int j = 0; j < 32; j += 4) {
            float4 v;
            v.x = __uint_as_float(r[j + 0]);
            v.y = __uint_as_float(r[j + 1]);
            v.z = __uint_as_float(r[j + 2]);
            v.w = __uint_as_float(r[j + 3]);
            if (EPI >= 1) {
                v.x += bias[colbase + j + 0]; v.y += bias[colbase + j + 1];
                v.z += bias[colbase + j + 2]; v.w += bias[colbase + j + 3];
            }
            if (EPI == 1) {
                v.x = to_tf32(fmaxf(v.x, 0.f)); v.y = to_tf32(fmaxf(v.y, 0.f));
                v.z = to_tf32(fmaxf(v.z, 0.f)); v.w = to_tf32(fmaxf(v.w, 0.f));
            }
            if (EPI == 2) {
                float4 rv = *reinterpret_cast<const float4*>(&res[(size_t)row * N + colbase + j]);
                v.x += rv.x; v.y += rv.y; v.z += rv.z; v.w += rv.w;
            }
            dst[j / 4] = v;
        }
    }
}
#endif

// ================= plain warp-specialized tcgen05 GEMM (no cluster) =================
template <int EPI, int MH, int BN_, int STG>
__global__ __launch_bounds__(256)
void tc_gemm_plain(const __grid_constant__ CUtensorMap tmA,
                   const __grid_constant__ CUtensorMap tmB,
                   const float* __restrict__ bias, const float* __restrict__ res,
                   float* __restrict__ C, int N, int NC) {
#if TC_OK
    constexpr int BMk = 128 * MH;
    constexpr int CA = BMk * BK * 4;
    constexpr int CB = BN_ * BK * 4;
    constexpr int CBYTES = CA + CB;
    constexpr int TCOLS = BN_ * MH;

    extern __shared__ __align__(1024) char smem[];
    const int tid  = threadIdx.x;
    const int warp = tid >> 5;
    const int lane = tid & 31;

    uint32_t sb = (smem_u32(smem) + 1023u) & ~1023u;
    const uint32_t tmem_ptr_addr = sb;
    const uint32_t mb_all = sb + 8 + 16 * STG;
    uint32_t mb_full[STG], mb_done[STG], bufA[STG], bufB[STG];
    #pragma unroll
    for (int s = 0; s < STG; s++) {
        mb_full[s] = sb + 8 + 8 * s;
        mb_done[s] = sb + 8 + 8 * STG + 8 * s;
        bufA[s] = sb + 1024 + s * CBYTES;
        bufB[s] = bufA[s] + CA;
    }

    if (warp == 0) { TC_ALLOC(tmem_ptr_addr, TCOLS); TC_RELINQ(); }
    if (tid == 0) {
        #pragma unroll
        for (int s = 0; s < STG; s++) { mbar_init(mb_full[s], 1); mbar_init(mb_done[s], 1); }
        mbar_init(mb_all, 1);
    }
    __syncthreads();

    uint32_t tmem;
    asm volatile("ld.shared.b32 %0, [%1];" : "=r"(tmem) : "r"(tmem_ptr_addr));

    const int tile_m = blockIdx.y * BMk;
    const int tile_n = blockIdx.x * BN_;

    if (warp == 1 && elect_one()) {
        uint32_t phd = 0;
        for (int j = 0; j < NC; j++) {
            const int s = j % STG;
            if (j >= STG) { mbar_wait(mb_done[s], (phd >> s) & 1); phd ^= 1u << s; }
            mbar_expect_tx(mb_full[s], CBYTES);
            tma_2d(bufA[s], &tmA, j * BK, tile_m, mb_full[s]);
            tma_2d(bufB[s], &tmB, j * BK, tile_n, mb_full[s]);
        }
    }
    if (warp == 0 && elect_one()) {
        uint64_t ad[STG][MH], bd[STG];
        #pragma unroll
        for (int s = 0; s < STG; s++) {
            #pragma unroll
            for (int hh = 0; hh < MH; hh++)
                ad[s][hh] = smem_desc_sw128(bufA[s] + hh * 128 * 128);
            bd[s] = smem_desc_sw128(bufB[s]);
        }
        uint32_t phf = 0;
        for (int kc = 0; kc < NC; kc++) {
            const int s = kc % STG;
            mbar_wait(mb_full[s], (phf >> s) & 1); phf ^= 1u << s;
            #pragma unroll
            for (int s2 = 0; s2 < 4; s2++) {
                const uint32_t en = (kc > 0 || s2 > 0) ? 1u : 0u;
                #pragma unroll
                for (int hh = 0; hh < MH; hh++)
                    mma_tf32_ss(tmem + hh * BN_, ad[s][hh] + 2 * s2, bd[s] + 2 * s2,
                                idesc_tf32(BN_), en);
            }
            tc_commit(mb_done[s]);
        }
        tc_commit(mb_all);
        mbar_wait(mb_all, 0);
    }
    __syncthreads();
    TC_FENCE_AFTER();
    gemm_epilogue<EPI, MH, BN_>(tmem, tile_m, tile_n, bias, res, C, N, warp, lane);
    __syncthreads();
    if (warp == 0) TC_DEALLOC(tmem, TCOLS);
#endif
}

// ================= clustered (2x4 = 8 CTA) multicast tcgen05 GEMM =================
// Tile 256x256 per CTA, 3-stage ring.
// A-tile differs per cy -> multicast across x-pairs {2cy, 2cy+1}.
// B-tile differs per cx -> multicast across cy-quads {cx, cx+2, cx+4, cx+6}:
// at effective multicast width 4, B L2 traffic drops ~4x (csz=8 regime).
template <int EPI>
__global__ __launch_bounds__(256) __cluster_dims__(2, 4, 1)
void tc_gemm_c8(const __grid_constant__ CUtensorMap tmA,
                const __grid_constant__ CUtensorMap tmB,
                const float* __restrict__ bias, const float* __restrict__ res,
                float* __restrict__ C, int N, int NC) {
#if TC_OK
    constexpr int STG = 3;
    constexpr int BN_ = 256;
    constexpr int CA = 256 * BK * 4;      // 32 KB
    constexpr int CB = 256 * BK * 4;      // 32 KB
    constexpr int CBYTES = CA + CB;
    constexpr int TCOLS = 512;

    extern __shared__ __align__(1024) char smem[];
    const int tid  = threadIdx.x;
    const int warp = tid >> 5;
    const int lane = tid & 31;

    uint32_t sb = (smem_u32(smem) + 1023u) & ~1023u;
    const uint32_t tmem_ptr_addr = sb;
    uint32_t mb_full[STG], mb_done[STG], mb_eA[STG], mb_eB[STG];
    uint32_t bufA[STG], bufB[STG];
    #pragma unroll
    for (int s = 0; s < STG; s++) {
        mb_full[s] = sb + 8 + 8 * s;
        mb_done[s] = sb + 32 + 8 * s;
        mb_eA[s]   = sb + 56 + 8 * s;
        mb_eB[s]   = sb + 80 + 8 * s;
        bufA[s] = sb + 1024 + s * CBYTES;
        bufB[s] = bufA[s] + CA;
    }
    const uint32_t mb_all = sb + 104;

    if (warp == 0) { TC_ALLOC(tmem_ptr_addr, TCOLS); TC_RELINQ(); }
    if (tid == 0) {
        #pragma unroll
        for (int s = 0; s < STG; s++) {
            mbar_init(mb_full[s], 1);
            mbar_init(mb_done[s], 1);
            mbar_init(mb_eA[s], 2);     // x-pair arrivals
            mbar_init(mb_eB[s], 4);     // cy-quad arrivals
        }
        mbar_init(mb_all, 1);
    }
    __syncthreads();
    CLUSTER_SYNC();   // all mbarriers live before any cross-CTA arrive / mcast

    uint32_t tmem;
    asm volatile("ld.shared.b32 %0, [%1];" : "=r"(tmem) : "r"(tmem_ptr_addr));

    const uint32_t rank = cluster_rank();    // cx + 2*cy, cluster (2,4)
    const int cx = (int)(rank & 1), cy = (int)(rank >> 1);
    const int tile_m = blockIdx.y * 256;
    const int tile_n = blockIdx.x * 256;

    if (warp == 1 && elect_one()) {
        const uint16_t maskA = (uint16_t)(0x3u << (2 * cy));     // pair {2cy, 2cy+1}
        const uint16_t maskB = (uint16_t)(0x55u << cx);          // quad {cx, cx+2, cx+4, cx+6}
        const uint32_t rankA = (uint32_t)(2 * cy);               // A issuer of my pair (cx==0)
        const uint32_t rankB = (uint32_t)cx;                     // B issuer of my quad (cy==0)
        uint32_t phd = 0, pheA = 0, pheB = 0;
        for (int j = 0; j < NC; j++) {
            const int s = j % STG;
            if (j >= STG) { mbar_wait(mb_done[s], (phd >> s) & 1); phd ^= 1u << s; }
            mbar_expect_tx(mb_full[s], CBYTES);
            mbar_arrive_cluster(mb_eA[s], rankA);
            mbar_arrive_cluster(mb_eB[s], rankB);
            if (cx == 0) {
                mbar_wait(mb_eA[s], (pheA >> s) & 1); pheA ^= 1u << s;
                tma_2d_mcast(bufA[s], &tmA, j * BK, tile_m, mb_full[s], maskA);
            }
            if (cy == 0) {
                mbar_wait(mb_eB[s], (pheB >> s) & 1); pheB ^= 1u << s;
                tma_2d_mcast(bufB[s], &tmB, j * BK, tile_n, mb_full[s], maskB);
            }
        }
    }
    if (warp == 0 && elect_one()) {
        uint64_t ad[STG][2], bd[STG];
        #pragma unroll
        for (int s = 0; s < STG; s++) {
            ad[s][0] = smem_desc_sw128(bufA[s]);
            ad[s][1] = smem_desc_sw128(bufA[s] + 128 * 128);
            bd[s] = smem_desc_sw128(bufB[s]);
        }
        uint32_t phf = 0;
        for (int kc = 0; kc < NC; kc++) {
            const int s = kc % STG;
            mbar_wait(mb_full[s], (phf >> s) & 1); phf ^= 1u << s;
            #pragma unroll
            for (int s2 = 0; s2 < 4; s2++) {
                const uint32_t en = (kc > 0 || s2 > 0) ? 1u : 0u;
                mma_tf32_ss(tmem,       ad[s][0] + 2 * s2, bd[s] + 2 * s2, idesc_tf32(BN_), en);
                mma_tf32_ss(tmem + 256, ad[s][1] + 2 * s2, bd[s] + 2 * s2, idesc_tf32(BN_), en);
            }
            tc_commit(mb_done[s]);
        }
        tc_commit(mb_all);
        mbar_wait(mb_all, 0);
    }
    __syncthreads();
    TC_FENCE_AFTER();
    gemm_epilogue<EPI, 2, BN_>(tmem, tile_m, tile_n, bias, res, C, N, warp, lane);
    __syncthreads();
    if (warp == 0) TC_DEALLOC(tmem, TCOLS);
    CLUSTER_SYNC();   // no CTA exits while peers may still arrive on its mbarriers
#endif
}

// ================= transpose (+pad rows, +tf32 round) =================
__global__ void transpose_rn_kernel(const float* __restrict__ in, float* __restrict__ out,
                                    int R, int Cc, int Cp) {
    __shared__ float tile[32][33];
    const int c0 = blockIdx.x * 32, r0 = blockIdx.y * 32;
    const int x = c0 + threadIdx.x;
    #pragma unroll
    for (int i = 0; i < 32; i += 8) {
        const int y = r0 + threadIdx.y + i;
        float v = 0.f;
        if (x < Cc && y < R) v = in[(size_t)y * Cc + x];
        tile[threadIdx.y + i][threadIdx.x] = v;
    }
    __syncthreads();
    const int ox = r0 + threadIdx.x;
    #pragma unroll
    for (int i = 0; i < 32; i += 8) {
        const int oy = c0 + threadIdx.y + i;
        if (oy < Cp && ox < R)
            out[(size_t)oy * R + ox] = to_tf32(tile[threadIdx.x][threadIdx.y + i]);
    }
}

// ================= t-tiled softmax + causal dynamic conv + LayerNorm =================
__global__ __launch_bounds__(512)
void dynconv_ln_kernel(const float* __restrict__ x, const float* __restrict__ wraw,
                       const float* __restrict__ b_lin,
                       const float* __restrict__ ln_g, const float* __restrict__ ln_b,
                       float* __restrict__ y, float* __restrict__ yrn) {
    extern __shared__ float sm[];
    float* xs  = sm;
    float* ws  = xs + XS_ROWS * C_DIM;
    float* red = ws + TT * (H_DIM * K_TAPS);

    const int t0  = blockIdx.x * TT;
    const int b   = blockIdx.y;
    const int tid = threadIdx.x;

    {
        float4* xs4 = reinterpret_cast<float4*>(xs);
        const int total4 = XS_ROWS * (C_DIM / 4);
        for (int i = tid; i < total4; i += 512) {
            const int r = i / (C_DIM / 4);
            const int cc = i % (C_DIM / 4);
            const int t = t0 - HALO + r;
            float4 v = make_float4(0.f, 0.f, 0.f, 0.f);
            if (t >= 0)
                v = reinterpret_cast<const float4*>(x)[((size_t)(t * B_DIM + b)) * (C_DIM / 4) + cc];
            xs4[i] = v;
        }
    }
    for (int i = tid; i < TT * (H_DIM * K_TAPS); i += 512) {
        const int lt = i / (H_DIM * K_TAPS);
        const int j  = i % (H_DIM * K_TAPS);
        ws[i] = wraw[(size_t)((t0 + lt) * B_DIM + b) * NPAD + j] + b_lin[j];
    }
    __syncthreads();

    {
        const int lt = tid >> 4;
        const int hd = tid & 15;
        float* p = ws + lt * (H_DIM * K_TAPS) + hd * K_TAPS;
        float mx = -1e30f;
        #pragma unroll
        for (int k = 0; k < K_TAPS; k++) mx = fmaxf(mx, p[k]);
        float e[K_TAPS]; float s = 0.f;
        #pragma unroll
        for (int k = 0; k < K_TAPS; k++) { e[k] = expf(p[k] - mx); s += e[k]; }
        const float inv = 1.0f / s;
        #pragma unroll
        for (int k = 0; k < K_TAPS; k++) p[k] = e[k] * inv;
    }
    __syncthreads();

    const int c0 = tid * 2;
    const int h  = c0 >> 6;
    const float g0 = ln_g[c0], g1 = ln_g[c0 + 1];
    const float bb0 = ln_b[c0], bb1 = ln_b[c0 + 1];
    const int wid = tid >> 5, lane = tid & 31;

    for (int lt = 0; lt < TT; lt++) {
        const float* wrow = ws + lt * (H_DIM * K_TAPS) + h * K_TAPS;
        float a0 = 0.f, a1 = 0.f;
        #pragma unroll
        for (int k = 0; k < K_TAPS; k++) {
            const float wgt = wrow[k];
            const float2 xv = *reinterpret_cast<const float2*>(&xs[(lt + k) * C_DIM + c0]);
            a0 += wgt * xv.x;
            a1 += wgt * xv.y;
        }
        float s1 = a0 + a1;
        float s2 = a0 * a0 + a1 * a1;
        #pragma unroll
        for (int off = 16; off > 0; off >>= 1) {
            s1 += __shfl_down_sync(0xFFFFFFFFu, s1, off);
            s2 += __shfl_down_sync(0xFFFFFFFFu, s2, off);
        }
        if (lane == 0) { red[wid] = s1; red[16 + wid] = s2; }
        __syncthreads();
        if (tid == 0) {
            float sa = 0.f, sb2 = 0.f;
            #pragma unroll
            for (int i = 0; i < 16; i++) { sa += red[i]; sb2 += red[16 + i]; }
            const float mu = sa * (1.0f / C_DIM);
            const float var = sb2 * (1.0f / C_DIM) - mu * mu;
            red[32] = mu;
            red[33] = rsqrtf(var + LN_EPS);
        }
        __syncthreads();
        const float mu = red[32], rstd = red[33];
        const float v0 = (a0 - mu) * rstd * g0 + bb0;
        const float v1 = (a1 - mu) * rstd * g1 + bb1;
        const size_t base = (size_t)((t0 + lt) * B_DIM + b) * C_DIM + c0;
        *reinterpret_cast<float2*>(&y[base])   = make_float2(v0, v1);
        *reinterpret_cast<float2*>(&yrn[base]) = make_float2(to_tf32(v0), to_tf32(v1));
    }
}

// ================= host side =================
typedef CUresult (*PFN_encodeTiled)(CUtensorMap*, CUtensorMapDataType, cuuint32_t, void*,
                                    const cuuint64_t*, const cuuint64_t*, const cuuint32_t*,
                                    const cuuint32_t*, CUtensorMapInterleave, CUtensorMapSwizzle,
                                    CUtensorMapL2promotion, CUtensorMapFloatOOBfill);

static PFN_encodeTiled get_encoder() {
    static PFN_encodeTiled fn = nullptr;
    if (!fn) {
        void* h = dlopen("libcuda.so.1", RTLD_LAZY | RTLD_GLOBAL);
        if (!h) h = dlopen("libcuda.so", RTLD_LAZY | RTLD_GLOBAL);
        if (h) fn = (PFN_encodeTiled)dlsym(h, "cuTensorMapEncodeTiled");
    }
    return fn;
}

static void make_map(CUtensorMap* m, const void* ptr, uint64_t d0, uint64_t d1,
                     uint32_t b0, uint32_t b1) {
    cuuint64_t dims[2] = { d0, d1 };
    cuuint64_t strides[1] = { d0 * 4 };
    cuuint32_t box[2] = { b0, b1 };
    cuuint32_t es[2] = { 1, 1 };
    PFN_encodeTiled enc = get_encoder();
    if (enc)
        enc(m, CU_TENSOR_MAP_DATA_TYPE_FLOAT32, 2, (void*)ptr, dims, strides, box, es,
            CU_TENSOR_MAP_INTERLEAVE_NONE, CU_TENSOR_MAP_SWIZZLE_128B,
            CU_TENSOR_MAP_L2_PROMOTION_L2_128B, CU_TENSOR_MAP_FLOAT_OOB_FILL_NONE);
}

extern "C" void kernel_launch(void* const* d_in, const int* in_sizes, int n_in,
                              void* d_out, int out_size) {
    const float* x     = (const float*)d_in[0];
    const float* w_lin = (const float*)d_in[1];
    const float* b_lin = (const float*)d_in[2];
    const float* ln_g  = (const float*)d_in[3];
    const float* ln_b  = (const float*)d_in[4];
    const float* fc1_w = (const float*)d_in[5];
    const float* fc1_b = (const float*)d_in[6];
    const float* fc2_w = (const float*)d_in[7];
    const float* fc2_b = (const float*)d_in[8];
    float* out = (float*)d_out;

    float *wlinT, *fc1wT, *fc2wT, *wraw, *y, *yrn, *h;
    cudaGetSymbolAddress((void**)&wlinT, g_wlinT);
    cudaGetSymbolAddress((void**)&fc1wT, g_fc1wT);
    cudaGetSymbolAddress((void**)&fc2wT, g_fc2wT);
    cudaGetSymbolAddress((void**)&wraw, g_wraw);
    cudaGetSymbolAddress((void**)&y, g_y);
    cudaGetSymbolAddress((void**)&yrn, g_yrn);
    cudaGetSymbolAddress((void**)&h, g_h);

    const int smem_g1 = 1024 + 5 * ((128 * BK + 128 * BK) * 4);   // 5 stages x 32KB
    const int smem_c8 = 1024 + 3 * ((256 * BK + 256 * BK) * 4);   // 3 stages x 64KB
    cudaFuncSetAttribute((const void*)tc_gemm_plain<0, 1, 128, 5>,
                         cudaFuncAttributeMaxDynamicSharedMemorySize, smem_g1);
    cudaFuncSetAttribute((const void*)tc_gemm_c8<1>,
                         cudaFuncAttributeMaxDynamicSharedMemorySize, smem_c8);
    cudaFuncSetAttribute((const void*)tc_gemm_c8<2>,
                         cudaFuncAttributeMaxDynamicSharedMemorySize, smem_c8);
    cudaFuncSetAttribute((const void*)dynconv_ln_kernel,
                         cudaFuncAttributeMaxDynamicSharedMemorySize, DC_SMEM);

    CUtensorMap mA1{}, mB1{}, mA2{}, mB2{}, mA3{}, mB3{};
    make_map(&mA1, x,     C_DIM, M_DIM, BK, 128);
    make_map(&mB1, wlinT, C_DIM, NPAD,  BK, 128);
    make_map(&mA2, yrn,   C_DIM, M_DIM, BK, 256);
    make_map(&mB2, fc1wT, C_DIM, F_DIM, BK, 256);
    make_map(&mA3, h,     F_DIM, M_DIM, BK, 256);
    make_map(&mB3, fc2wT, F_DIM, C_DIM, BK, 256);

    dim3 tb(32, 8);
    transpose_rn_kernel<<<dim3(NPAD / 32, C_DIM / 32), tb>>>(w_lin, wlinT, C_DIM, H_DIM * K_TAPS, NPAD);
    transpose_rn_kernel<<<dim3(F_DIM / 32, C_DIM / 32), tb>>>(fc1_w, fc1wT, C_DIM, F_DIM, F_DIM);
    transpose_rn_kernel<<<dim3(C_DIM / 32, F_DIM / 32), tb>>>(fc2_w, fc2wT, F_DIM, C_DIM, C_DIM);

    // conv-weight projection: 128x128 tiles, 128 CTAs, 5-stage ring
    tc_gemm_plain<0, 1, 128, 5><<<dim3(NPAD / 128, M_DIM / 128), 256, smem_g1>>>(
        mA1, mB1, nullptr, nullptr, wraw, NPAD, C_DIM / BK);

    dynconv_ln_kernel<<<dim3(T_DIM / TT, B_DIM), 512, DC_SMEM>>>(
        x, wraw, b_lin, ln_g, ln_b, y, yrn);

    // fc1 + ReLU: 256x256 tiles, cluster (2,4) multicast
    tc_gemm_c8<1><<<dim3(F_DIM / 256, M_DIM / 256), 256, smem_c8>>>(
        mA2, mB2, fc1_b, nullptr, h, F_DIM, C_DIM / BK);

    // fc2 + bias + residual: cluster (2,4) multicast
    tc_gemm_c8<2><<<dim3(C_DIM / 256, M_DIM / 256), 256, smem_c8>>>(
        mA3, mB3, fc2_b, y, out, C_DIM, F_DIM / BK);
}

// round 8
// speedup vs baseline: 1.5572x; 1.5572x over previous
#include <cuda_runtime.h>
#include <cuda.h>
#include <cuda_fp16.h>
#include <dlfcn.h>
#include <math.h>
#include <stdint.h>

// ---------------- problem constants ----------------
#define T_DIM 1024
#define B_DIM 8
#define C_DIM 1024
#define F_DIM 4096
#define H_DIM 16
#define K_TAPS 15
#define M_DIM (T_DIM * B_DIM)   // 8192
#define NPAD 256
#define LN_EPS 1e-5f

#define KE 64                   // fp16 elements per k-chunk (128 bytes per row)

// dynconv tiling
#define TT 32
#define HALO (K_TAPS - 1)
#define XS_ROWS (TT + HALO)
#define DC_SMEM ((XS_ROWS * C_DIM + TT * (H_DIM * K_TAPS) + 64) * 4)

// arch-specific feature gate (tcgen05/multicast only on the sm_103a pass)
#if defined(__CUDA_ARCH_FEAT_SM103_ALL) || defined(__CUDA_ARCH_FEAT_SM100_ALL) || \
    (defined(__CUDA_ARCH_SPECIFIC__) && (__CUDA_ARCH_SPECIFIC__ >= 1000)) ||      \
    (defined(__CUDA_ARCH_FAMILY_SPECIFIC__) && (__CUDA_ARCH_FAMILY_SPECIFIC__ >= 1000))
#define TC_OK 1
#else
#define TC_OK 0
#endif

// ---------------- scratch (device globals) ----------------
__device__ __half g_xh[(size_t)M_DIM * C_DIM];          // x in fp16 (GEMM1 A)
__device__ __half g_wlinT[NPAD * C_DIM];                // [256,1024] fp16
__device__ __half g_fc1wT[(size_t)F_DIM * C_DIM];       // [4096,1024] fp16
__device__ __half g_fc2wT[(size_t)C_DIM * F_DIM];       // [1024,4096] fp16
__device__ float  g_wraw[(size_t)M_DIM * NPAD];         // conv logits fp32
__device__ float  g_y[(size_t)M_DIM * C_DIM];           // post-LN fp32 (residual)
__device__ __half g_yh[(size_t)M_DIM * C_DIM];          // post-LN fp16 (fc1 A)
__device__ __half g_h[(size_t)M_DIM * F_DIM];           // fc1 out fp16 (fc2 A)

// ---------------- helpers ----------------
__device__ __forceinline__ uint32_t smem_u32(const void* p) {
    uint32_t a;
    asm("{ .reg .u64 t; cvta.to.shared.u64 t, %1; cvt.u32.u64 %0, t; }" : "=r"(a) : "l"(p));
    return a;
}
__device__ __forceinline__ uint32_t elect_one() {
    uint32_t p;
    asm volatile("{ .reg .pred p; elect.sync _|p, 0xFFFFFFFF; selp.b32 %0, 1, 0, p; }" : "=r"(p));
    return p;
}
__device__ __forceinline__ void mbar_init(uint32_t a, uint32_t cnt) {
    asm volatile("mbarrier.init.shared.b64 [%0], %1;" :: "r"(a), "r"(cnt) : "memory");
}
__device__ __forceinline__ void mbar_expect_tx(uint32_t a, uint32_t bytes) {
    asm volatile("mbarrier.arrive.expect_tx.shared.b64 _, [%0], %1;" :: "r"(a), "r"(bytes) : "memory");
}
__device__ __forceinline__ void mbar_wait(uint32_t a, uint32_t parity) {
    uint32_t done;
    asm volatile(
        "{ .reg .pred p;\n\t"
        "mbarrier.try_wait.parity.acquire.cta.shared::cta.b64 p, [%1], %2;\n\t"
        "selp.b32 %0, 1, 0, p; }" : "=r"(done) : "r"(a), "r"(parity) : "memory");
    if (!done) {
        asm volatile(
            "{ .reg .pred P1;\n\t"
            "WL_%=:\n\t"
            "mbarrier.try_wait.parity.acquire.cta.shared::cta.b64 P1, [%0], %1, 0x989680;\n\t"
            "@P1 bra.uni WD_%=;\n\t"
            "bra.uni WL_%=;\n\t"
            "WD_%=: }" :: "r"(a), "r"(parity) : "memory");
    }
}
#if TC_OK
__device__ __forceinline__ uint32_t cluster_rank() {
    uint32_t r;
    asm("mov.u32 %0, %%cluster_ctarank;" : "=r"(r));
    return r;
}
__device__ __forceinline__ void mbar_arrive_cluster(uint32_t local_addr, uint32_t target_rank) {
    asm volatile(
        "{ .reg .b32 ra;\n\t"
        "mapa.shared::cluster.u32 ra, %0, %1;\n\t"
        "mbarrier.arrive.shared::cluster.b64 _, [ra]; }"
        :: "r"(local_addr), "r"(target_rank) : "memory");
}
#define CLUSTER_SYNC() do { \
    asm volatile("barrier.cluster.arrive.aligned;" ::: "memory"); \
    asm volatile("barrier.cluster.wait.aligned;" ::: "memory");   \
} while (0)

__device__ __forceinline__ void tma_2d(uint32_t dst, const void* map, int cx, int cy, uint32_t mbar) {
    asm volatile(
        "cp.async.bulk.tensor.2d.shared::cta.global.tile.mbarrier::complete_tx::bytes "
        "[%0], [%1, {%2, %3}], [%4];"
        :: "r"(dst), "l"(map), "r"(cx), "r"(cy), "r"(mbar) : "memory");
}
__device__ __forceinline__ void tma_2d_mcast(uint32_t dst, const void* map, int cx, int cy,
                                             uint32_t mbar, uint16_t mask) {
    asm volatile(
        "cp.async.bulk.tensor.2d.shared::cluster.global.tile.mbarrier::complete_tx::bytes"
        ".multicast::cluster [%0], [%1, {%2, %3}], [%4], %5;"
        :: "r"(dst), "l"(map), "r"(cx), "r"(cy), "r"(mbar), "h"(mask) : "memory");
}
__device__ __forceinline__ void mma_f16_ss(uint32_t d, uint64_t adesc, uint64_t bdesc,
                                           uint32_t idesc, uint32_t en) {
    asm volatile(
        "{ .reg .pred p;\n\t"
        "setp.ne.u32 p, %4, 0;\n\t"
        "tcgen05.mma.cta_group::1.kind::f16 [%0], %1, %2, %3, p; }"
        :: "r"(d), "l"(adesc), "l"(bdesc), "r"(idesc), "r"(en) : "memory");
}
__device__ __forceinline__ void tc_commit(uint32_t mbar) {
    asm volatile(
        "tcgen05.commit.cta_group::1.mbarrier::arrive::one.shared::cluster.b64 [%0];"
        :: "r"(mbar) : "memory");
}
#define TC_ALLOC(smem_addr, ncols) \
    asm volatile("tcgen05.alloc.cta_group::1.sync.aligned.shared::cta.b32 [%0], %1;" \
                 :: "r"(smem_addr), "r"(ncols) : "memory")
#define TC_RELINQ() \
    asm volatile("tcgen05.relinquish_alloc_permit.cta_group::1.sync.aligned;")
#define TC_DEALLOC(tmem, ncols) \
    asm volatile("tcgen05.dealloc.cta_group::1.sync.aligned.b32 %0, %1;" :: "r"(tmem), "r"(ncols))
#define TC_FENCE_AFTER()  asm volatile("tcgen05.fence::after_thread_sync;" ::: "memory")
#define TC_WAIT_LD()      asm volatile("tcgen05.wait::ld.sync.aligned;" ::: "memory")
#define TC_LD_X32(r, addr) \
    asm volatile("tcgen05.ld.sync.aligned.32x32b.x32.b32 " \
        "{%0, %1, %2, %3, %4, %5, %6, %7, %8, %9, %10, %11, %12, %13, %14, %15, " \
        " %16, %17, %18, %19, %20, %21, %22, %23, %24, %25, %26, %27, %28, %29, %30, %31}, [%32];" \
        : "=r"((r)[0]), "=r"((r)[1]), "=r"((r)[2]), "=r"((r)[3]), \
          "=r"((r)[4]), "=r"((r)[5]), "=r"((r)[6]), "=r"((r)[7]), \
          "=r"((r)[8]), "=r"((r)[9]), "=r"((r)[10]), "=r"((r)[11]), \
          "=r"((r)[12]), "=r"((r)[13]), "=r"((r)[14]), "=r"((r)[15]), \
          "=r"((r)[16]), "=r"((r)[17]), "=r"((r)[18]), "=r"((r)[19]), \
          "=r"((r)[20]), "=r"((r)[21]), "=r"((r)[22]), "=r"((r)[23]), \
          "=r"((r)[24]), "=r"((r)[25]), "=r"((r)[26]), "=r"((r)[27]), \
          "=r"((r)[28]), "=r"((r)[29]), "=r"((r)[30]), "=r"((r)[31]) \
        : "r"(addr))

__device__ __forceinline__ uint64_t smem_desc_sw128(uint32_t addr) {
    return ((uint64_t)2 << 61) | ((uint64_t)1 << 46) | ((uint64_t)64 << 32) |
           ((uint64_t)1 << 16) | (((uint64_t)addr >> 4) & 0x3FFF);
}
// kind::f16: dtype=F32(1@4), atype=FP16(0@7), btype=FP16(0@10), N>>3 @17, M>>4 @24
__device__ __forceinline__ constexpr uint32_t idesc_f16(int bn) {
    return (1u << 4) | ((uint32_t)(bn / 8) << 17) | (8u << 24);
}
#endif  // TC_OK

// shared epilogue (TC_OK only)
// EPI 0: plain fp32 out.  EPI 1: bias+relu -> fp16 out.  EPI 2: bias+residual -> fp32 out.
#if TC_OK
template <int EPI, int MH, int BN_>
__device__ __forceinline__ void gemm_epilogue(uint32_t tmem, int tile_m, int tile_n,
                                              const float* __restrict__ bias,
                                              const float* __restrict__ res,
                                              void* __restrict__ Cv, int N,
                                              int warp, int lane) {
    const int half_ = warp >> 2;
    uint32_t dbase;
    int row, col0, nchunk;
    if (MH == 2) {
        dbase = tmem + half_ * BN_;
        row = tile_m + half_ * 128 + (warp & 3) * 32 + lane;
        col0 = tile_n;
        nchunk = BN_ / 32;
    } else {
        dbase = tmem + half_ * (BN_ / 2);
        row = tile_m + (warp & 3) * 32 + lane;
        col0 = tile_n + half_ * (BN_ / 2);
        nchunk = BN_ / 64;
    }
    #pragma unroll 1
    for (int cc = 0; cc < nchunk; cc++) {
        uint32_t r[32];
        TC_LD_X32(r, dbase + cc * 32);
        TC_WAIT_LD();
        const int colbase = col0 + cc * 32;
        if (EPI == 1) {
            __half* Ch = (__half*)Cv;
            __half2* dst = reinterpret_cast<__half2*>(&Ch[(size_t)row * N + colbase]);
            #pragma unroll
            for (int j = 0; j < 32; j += 2) {
                float v0 = fmaxf(__uint_as_float(r[j + 0]) + bias[colbase + j + 0], 0.f);
                float v1 = fmaxf(__uint_as_float(r[j + 1]) + bias[colbase + j + 1], 0.f);
                dst[j / 2] = __floats2half2_rn(v0, v1);
            }
        } else {
            float* C = (float*)Cv;
            float4* dst = reinterpret_cast<float4*>(&C[(size_t)row * N + colbase]);
            #pragma unroll
            for (int j = 0; j < 32; j += 4) {
                float4 v;
                v.x = __uint_as_float(r[j + 0]);
                v.y = __uint_as_float(r[j + 1]);
                v.z = __uint_as_float(r[j + 2]);
                v.w = __uint_as_float(r[j + 3]);
                if (EPI == 2) {
                    v.x += bias[colbase + j + 0]; v.y += bias[colbase + j + 1];
                    v.z += bias[colbase + j + 2]; v.w += bias[colbase + j + 3];
                    float4 rv = *reinterpret_cast<const float4*>(&res[(size_t)row * N + colbase + j]);
                    v.x += rv.x; v.y += rv.y; v.z += rv.z; v.w += rv.w;
                }
                dst[j / 4] = v;
            }
        }
    }
}
#endif

// ================= plain warp-specialized tcgen05 fp16 GEMM (no cluster) =================
template <int EPI, int MH, int BN_, int STG>
__global__ __launch_bounds__(256)
void tc_gemm_plain(const __grid_constant__ CUtensorMap tmA,
                   const __grid_constant__ CUtensorMap tmB,
                   const float* __restrict__ bias, const float* __restrict__ res,
                   void* __restrict__ C, int N, int NC) {
#if TC_OK
    constexpr int BMk = 128 * MH;
    constexpr int CA = BMk * 128;      // rows x 128B
    constexpr int CB = BN_ * 128;
    constexpr int CBYTES = CA + CB;
    constexpr int TCOLS = BN_ * MH;

    extern __shared__ __align__(1024) char smem[];
    const int tid  = threadIdx.x;
    const int warp = tid >> 5;
    const int lane = tid & 31;

    uint32_t sb = (smem_u32(smem) + 1023u) & ~1023u;
    const uint32_t tmem_ptr_addr = sb;
    const uint32_t mb_all = sb + 8 + 16 * STG;
    uint32_t mb_full[STG], mb_done[STG], bufA[STG], bufB[STG];
    #pragma unroll
    for (int s = 0; s < STG; s++) {
        mb_full[s] = sb + 8 + 8 * s;
        mb_done[s] = sb + 8 + 8 * STG + 8 * s;
        bufA[s] = sb + 1024 + s * CBYTES;
        bufB[s] = bufA[s] + CA;
    }

    if (warp == 0) { TC_ALLOC(tmem_ptr_addr, TCOLS); TC_RELINQ(); }
    if (tid == 0) {
        #pragma unroll
        for (int s = 0; s < STG; s++) { mbar_init(mb_full[s], 1); mbar_init(mb_done[s], 1); }
        mbar_init(mb_all, 1);
    }
    __syncthreads();

    uint32_t tmem;
    asm volatile("ld.shared.b32 %0, [%1];" : "=r"(tmem) : "r"(tmem_ptr_addr));

    const int tile_m = blockIdx.y * BMk;
    const int tile_n = blockIdx.x * BN_;

    if (warp == 1 && elect_one()) {
        uint32_t phd = 0;
        for (int j = 0; j < NC; j++) {
            const int s = j % STG;
            if (j >= STG) { mbar_wait(mb_done[s], (phd >> s) & 1); phd ^= 1u << s; }
            mbar_expect_tx(mb_full[s], CBYTES);
            tma_2d(bufA[s], &tmA, j * KE, tile_m, mb_full[s]);
            tma_2d(bufB[s], &tmB, j * KE, tile_n, mb_full[s]);
        }
    }
    if (warp == 0 && elect_one()) {
        uint64_t ad[STG][MH], bd[STG];
        #pragma unroll
        for (int s = 0; s < STG; s++) {
            #pragma unroll
            for (int hh = 0; hh < MH; hh++)
                ad[s][hh] = smem_desc_sw128(bufA[s] + hh * 128 * 128);
            bd[s] = smem_desc_sw128(bufB[s]);
        }
        uint32_t phf = 0;
        for (int kc = 0; kc < NC; kc++) {
            const int s = kc % STG;
            mbar_wait(mb_full[s], (phf >> s) & 1); phf ^= 1u << s;
            #pragma unroll
            for (int s2 = 0; s2 < 4; s2++) {       // KE=64 halfs = 4 x (K=16) f16 MMAs
                const uint32_t en = (kc > 0 || s2 > 0) ? 1u : 0u;
                #pragma unroll
                for (int hh = 0; hh < MH; hh++)
                    mma_f16_ss(tmem + hh * BN_, ad[s][hh] + 2 * s2, bd[s] + 2 * s2,
                               idesc_f16(BN_), en);
            }
            tc_commit(mb_done[s]);
        }
        tc_commit(mb_all);
        mbar_wait(mb_all, 0);
    }
    __syncthreads();
    TC_FENCE_AFTER();
    gemm_epilogue<EPI, MH, BN_>(tmem, tile_m, tile_n, bias, res, C, N, warp, lane);
    __syncthreads();
    if (warp == 0) TC_DEALLOC(tmem, TCOLS);
#endif
}

// ================= clustered (2x2) multicast tcgen05 fp16 GEMM =================
// (structure proven in Round 6; fp16 operands)
template <int EPI>
__global__ __launch_bounds__(256) __cluster_dims__(2, 2, 1)
void tc_gemm_c4(const __grid_constant__ CUtensorMap tmA,
                const __grid_constant__ CUtensorMap tmB,
                const float* __restrict__ bias, const float* __restrict__ res,
                void* __restrict__ C, int N, int NC) {
#if TC_OK
    constexpr int STG = 3;
    constexpr int BN_ = 256;
    constexpr int CA = 256 * 128;      // 32 KB
    constexpr int CB = 256 * 128;      // 32 KB
    constexpr int CBYTES = CA + CB;
    constexpr int TCOLS = 512;

    extern __shared__ __align__(1024) char smem[];
    const int tid  = threadIdx.x;
    const int warp = tid >> 5;
    const int lane = tid & 31;

    uint32_t sb = (smem_u32(smem) + 1023u) & ~1023u;
    const uint32_t tmem_ptr_addr = sb;
    uint32_t mb_full[STG], mb_done[STG], mb_eA[STG], mb_eB[STG];
    uint32_t bufA[STG], bufB[STG];
    #pragma unroll
    for (int s = 0; s < STG; s++) {
        mb_full[s] = sb + 8 + 8 * s;
        mb_done[s] = sb + 32 + 8 * s;
        mb_eA[s]   = sb + 56 + 8 * s;
        mb_eB[s]   = sb + 80 + 8 * s;
        bufA[s] = sb + 1024 + s * CBYTES;
        bufB[s] = bufA[s] + CA;
    }
    const uint32_t mb_all = sb + 104;

    if (warp == 0) { TC_ALLOC(tmem_ptr_addr, TCOLS); TC_RELINQ(); }
    if (tid == 0) {
        #pragma unroll
        for (int s = 0; s < STG; s++) {
            mbar_init(mb_full[s], 1);
            mbar_init(mb_done[s], 1);
            mbar_init(mb_eA[s], 2);
            mbar_init(mb_eB[s], 2);
        }
        mbar_init(mb_all, 1);
    }
    __syncthreads();
    CLUSTER_SYNC();

    uint32_t tmem;
    asm volatile("ld.shared.b32 %0, [%1];" : "=r"(tmem) : "r"(tmem_ptr_addr));

    const uint32_t rank = cluster_rank();    // cx + 2*cy
    const int cx = (int)(rank & 1), cy = (int)(rank >> 1);
    const int tile_m = blockIdx.y * 256;
    const int tile_n = blockIdx.x * 256;

    if (warp == 1 && elect_one()) {
        const uint16_t maskA = (uint16_t)(0x3u << (2 * cy));
        const uint16_t maskB = (uint16_t)(cx == 0 ? 0x5u : 0xAu);
        const uint32_t rankA = (uint32_t)(2 * cy);
        const uint32_t rankB = (uint32_t)cx;
        uint32_t phd = 0, pheA = 0, pheB = 0;
        for (int j = 0; j < NC; j++) {
            const int s = j % STG;
            if (j >= STG) { mbar_wait(mb_done[s], (phd >> s) & 1); phd ^= 1u << s; }
            mbar_expect_tx(mb_full[s], CBYTES);
            mbar_arrive_cluster(mb_eA[s], rankA);
            mbar_arrive_cluster(mb_eB[s], rankB);
            if (cx == 0) {
                mbar_wait(mb_eA[s], (pheA >> s) & 1); pheA ^= 1u << s;
                tma_2d_mcast(bufA[s], &tmA, j * KE, tile_m, mb_full[s], maskA);
            }
            if (cy == 0) {
                mbar_wait(mb_eB[s], (pheB >> s) & 1); pheB ^= 1u << s;
                tma_2d_mcast(bufB[s], &tmB, j * KE, tile_n, mb_full[s], maskB);
            }
        }
    }
    if (warp == 0 && elect_one()) {
        uint64_t ad[STG][2], bd[STG];
        #pragma unroll
        for (int s = 0; s < STG; s++) {
            ad[s][0] = smem_desc_sw128(bufA[s]);
            ad[s][1] = smem_desc_sw128(bufA[s] + 128 * 128);
            bd[s] = smem_desc_sw128(bufB[s]);
        }
        uint32_t phf = 0;
        for (int kc = 0; kc < NC; kc++) {
            const int s = kc % STG;
            mbar_wait(mb_full[s], (phf >> s) & 1); phf ^= 1u << s;
            #pragma unroll
            for (int s2 = 0; s2 < 4; s2++) {
                const uint32_t en = (kc > 0 || s2 > 0) ? 1u : 0u;
                mma_f16_ss(tmem,       ad[s][0] + 2 * s2, bd[s] + 2 * s2, idesc_f16(BN_), en);
                mma_f16_ss(tmem + 256, ad[s][1] + 2 * s2, bd[s] + 2 * s2, idesc_f16(BN_), en);
            }
            tc_commit(mb_done[s]);
        }
        tc_commit(mb_all);
        mbar_wait(mb_all, 0);
    }
    __syncthreads();
    TC_FENCE_AFTER();
    gemm_epilogue<EPI, 2, BN_>(tmem, tile_m, tile_n, bias, res, C, N, warp, lane);
    __syncthreads();
    if (warp == 0) TC_DEALLOC(tmem, TCOLS);
    CLUSTER_SYNC();
#endif
}

// ================= transpose to fp16 (+pad rows) =================
__global__ void transpose_h_kernel(const float* __restrict__ in, __half* __restrict__ out,
                                   int R, int Cc, int Cp) {
    __shared__ float tile[32][33];
    const int c0 = blockIdx.x * 32, r0 = blockIdx.y * 32;
    const int x = c0 + threadIdx.x;
    #pragma unroll
    for (int i = 0; i < 32; i += 8) {
        const int y = r0 + threadIdx.y + i;
        float v = 0.f;
        if (x < Cc && y < R) v = in[(size_t)y * Cc + x];
        tile[threadIdx.y + i][threadIdx.x] = v;
    }
    __syncthreads();
    const int ox = r0 + threadIdx.x;
    #pragma unroll
    for (int i = 0; i < 32; i += 8) {
        const int oy = c0 + threadIdx.y + i;
        if (oy < Cp && ox < R)
            out[(size_t)oy * R + ox] = __float2half(tile[threadIdx.x][threadIdx.y + i]);
    }
}

// ================= fp32 -> fp16 elementwise =================
__global__ void f2h_kernel(const float* __restrict__ in, __half* __restrict__ out, int n2) {
    int i = blockIdx.x * blockDim.x + threadIdx.x;
    if (i < n2) {
        float2 v = reinterpret_cast<const float2*>(in)[i];
        reinterpret_cast<__half2*>(out)[i] = __floats2half2_rn(v.x, v.y);
    }
}

// ================= t-tiled softmax + causal dynamic conv + LayerNorm =================
__global__ __launch_bounds__(512)
void dynconv_ln_kernel(const float* __restrict__ x, const float* __restrict__ wraw,
                       const float* __restrict__ b_lin,
                       const float* __restrict__ ln_g, const float* __restrict__ ln_b,
                       float* __restrict__ y, __half* __restrict__ yh) {
    extern __shared__ float sm[];
    float* xs  = sm;
    float* ws  = xs + XS_ROWS * C_DIM;
    float* red = ws + TT * (H_DIM * K_TAPS);

    const int t0  = blockIdx.x * TT;
    const int b   = blockIdx.y;
    const int tid = threadIdx.x;

    {
        float4* xs4 = reinterpret_cast<float4*>(xs);
        const int total4 = XS_ROWS * (C_DIM / 4);
        for (int i = tid; i < total4; i += 512) {
            const int r = i / (C_DIM / 4);
            const int cc = i % (C_DIM / 4);
            const int t = t0 - HALO + r;
            float4 v = make_float4(0.f, 0.f, 0.f, 0.f);
            if (t >= 0)
                v = reinterpret_cast<const float4*>(x)[((size_t)(t * B_DIM + b)) * (C_DIM / 4) + cc];
            xs4[i] = v;
        }
    }
    for (int i = tid; i < TT * (H_DIM * K_TAPS); i += 512) {
        const int lt = i / (H_DIM * K_TAPS);
        const int j  = i % (H_DIM * K_TAPS);
        ws[i] = wraw[(size_t)((t0 + lt) * B_DIM + b) * NPAD + j] + b_lin[j];
    }
    __syncthreads();

    {
        const int lt = tid >> 4;
        const int hd = tid & 15;
        float* p = ws + lt * (H_DIM * K_TAPS) + hd * K_TAPS;
        float mx = -1e30f;
        #pragma unroll
        for (int k = 0; k < K_TAPS; k++) mx = fmaxf(mx, p[k]);
        float e[K_TAPS]; float s = 0.f;
        #pragma unroll
        for (int k = 0; k < K_TAPS; k++) { e[k] = expf(p[k] - mx); s += e[k]; }
        const float inv = 1.0f / s;
        #pragma unroll
        for (int k = 0; k < K_TAPS; k++) p[k] = e[k] * inv;
    }
    __syncthreads();

    const int c0 = tid * 2;
    const int h  = c0 >> 6;
    const float g0 = ln_g[c0], g1 = ln_g[c0 + 1];
    const float bb0 = ln_b[c0], bb1 = ln_b[c0 + 1];
    const int wid = tid >> 5, lane = tid & 31;

    for (int lt = 0; lt < TT; lt++) {
        const float* wrow = ws + lt * (H_DIM * K_TAPS) + h * K_TAPS;
        float a0 = 0.f, a1 = 0.f;
        #pragma unroll
        for (int k = 0; k < K_TAPS; k++) {
            const float wgt = wrow[k];
            const float2 xv = *reinterpret_cast<const float2*>(&xs[(lt + k) * C_DIM + c0]);
            a0 += wgt * xv.x;
            a1 += wgt * xv.y;
        }
        float s1 = a0 + a1;
        float s2 = a0 * a0 + a1 * a1;
        #pragma unroll
        for (int off = 16; off > 0; off >>= 1) {
            s1 += __shfl_down_sync(0xFFFFFFFFu, s1, off);
            s2 += __shfl_down_sync(0xFFFFFFFFu, s2, off);
        }
        if (lane == 0) { red[wid] = s1; red[16 + wid] = s2; }
        __syncthreads();
        if (tid == 0) {
            float sa = 0.f, sb2 = 0.f;
            #pragma unroll
            for (int i = 0; i < 16; i++) { sa += red[i]; sb2 += red[16 + i]; }
            const float mu = sa * (1.0f / C_DIM);
            const float var = sb2 * (1.0f / C_DIM) - mu * mu;
            red[32] = mu;
            red[33] = rsqrtf(var + LN_EPS);
        }
        __syncthreads();
        const float mu = red[32], rstd = red[33];
        const float v0 = (a0 - mu) * rstd * g0 + bb0;
        const float v1 = (a1 - mu) * rstd * g1 + bb1;
        const size_t base = (size_t)((t0 + lt) * B_DIM + b) * C_DIM + c0;
        *reinterpret_cast<float2*>(&y[base]) = make_float2(v0, v1);
        *reinterpret_cast<__half2*>(&yh[base]) = __floats2half2_rn(v0, v1);
    }
}

// ================= host side =================
typedef CUresult (*PFN_encodeTiled)(CUtensorMap*, CUtensorMapDataType, cuuint32_t, void*,
                                    const cuuint64_t*, const cuuint64_t*, const cuuint32_t*,
                                    const cuuint32_t*, CUtensorMapInterleave, CUtensorMapSwizzle,
                                    CUtensorMapL2promotion, CUtensorMapFloatOOBfill);

static PFN_encodeTiled get_encoder() {
    static PFN_encodeTiled fn = nullptr;
    if (!fn) {
        void* h = dlopen("libcuda.so.1", RTLD_LAZY | RTLD_GLOBAL);
        if (!h) h = dlopen("libcuda.so", RTLD_LAZY | RTLD_GLOBAL);
        if (h) fn = (PFN_encodeTiled)dlsym(h, "cuTensorMapEncodeTiled");
    }
    return fn;
}

// fp16 map: d0 = K in elements, box0 = KE (=64 halfs = 128B, SW128 limit)
static void make_map_h(CUtensorMap* m, const void* ptr, uint64_t d0, uint64_t d1, uint32_t b1) {
    cuuint64_t dims[2] = { d0, d1 };
    cuuint64_t strides[1] = { d0 * 2 };
    cuuint32_t box[2] = { KE, b1 };
    cuuint32_t es[2] = { 1, 1 };
    PFN_encodeTiled enc = get_encoder();
    if (enc)
        enc(m, CU_TENSOR_MAP_DATA_TYPE_FLOAT16, 2, (void*)ptr, dims, strides, box, es,
            CU_TENSOR_MAP_INTERLEAVE_NONE, CU_TENSOR_MAP_SWIZZLE_128B,
            CU_TENSOR_MAP_L2_PROMOTION_L2_128B, CU_TENSOR_MAP_FLOAT_OOB_FILL_NONE);
}

extern "C" void kernel_launch(void* const* d_in, const int* in_sizes, int n_in,
                              void* d_out, int out_size) {
    const float* x     = (const float*)d_in[0];
    const float* w_lin = (const float*)d_in[1];
    const float* b_lin = (const float*)d_in[2];
    const float* ln_g  = (const float*)d_in[3];
    const float* ln_b  = (const float*)d_in[4];
    const float* fc1_w = (const float*)d_in[5];
    const float* fc1_b = (const float*)d_in[6];
    const float* fc2_w = (const float*)d_in[7];
    const float* fc2_b = (const float*)d_in[8];
    float* out = (float*)d_out;

    __half *xh, *wlinT, *fc1wT, *fc2wT, *yh, *h;
    float *wraw, *y;
    cudaGetSymbolAddress((void**)&xh, g_xh);
    cudaGetSymbolAddress((void**)&wlinT, g_wlinT);
    cudaGetSymbolAddress((void**)&fc1wT, g_fc1wT);
    cudaGetSymbolAddress((void**)&fc2wT, g_fc2wT);
    cudaGetSymbolAddress((void**)&wraw, g_wraw);
    cudaGetSymbolAddress((void**)&y, g_y);
    cudaGetSymbolAddress((void**)&yh, g_yh);
    cudaGetSymbolAddress((void**)&h, g_h);

    const int smem_g1 = 1024 + 5 * (128 * 128 + 128 * 128);   // 5 stages x 32KB = 161KB
    const int smem_c4 = 1024 + 3 * (256 * 128 + 256 * 128);   // 3 stages x 64KB = 193KB
    cudaFuncSetAttribute((const void*)tc_gemm_plain<0, 1, 128, 5>,
                         cudaFuncAttributeMaxDynamicSharedMemorySize, smem_g1);
    cudaFuncSetAttribute((const void*)tc_gemm_c4<1>,
                         cudaFuncAttributeMaxDynamicSharedMemorySize, smem_c4);
    cudaFuncSetAttribute((const void*)tc_gemm_c4<2>,
                         cudaFuncAttributeMaxDynamicSharedMemorySize, smem_c4);
    cudaFuncSetAttribute((const void*)dynconv_ln_kernel,
                         cudaFuncAttributeMaxDynamicSharedMemorySize, DC_SMEM);

    CUtensorMap mA1{}, mB1{}, mA2{}, mB2{}, mA3{}, mB3{};
    make_map_h(&mA1, xh,    C_DIM, M_DIM, 128);
    make_map_h(&mB1, wlinT, C_DIM, NPAD,  128);
    make_map_h(&mA2, yh,    C_DIM, M_DIM, 256);
    make_map_h(&mB2, fc1wT, C_DIM, F_DIM, 256);
    make_map_h(&mA3, h,     F_DIM, M_DIM, 256);
    make_map_h(&mB3, fc2wT, F_DIM, C_DIM, 256);

    dim3 tb(32, 8);
    // operand prep: x -> fp16; weights transposed to [N, K] fp16
    f2h_kernel<<<(M_DIM * C_DIM / 2 + 255) / 256, 256>>>(x, xh, M_DIM * C_DIM / 2);
    transpose_h_kernel<<<dim3(NPAD / 32, C_DIM / 32), tb>>>(w_lin, wlinT, C_DIM, H_DIM * K_TAPS, NPAD);
    transpose_h_kernel<<<dim3(F_DIM / 32, C_DIM / 32), tb>>>(fc1_w, fc1wT, C_DIM, F_DIM, F_DIM);
    transpose_h_kernel<<<dim3(C_DIM / 32, F_DIM / 32), tb>>>(fc2_w, fc2wT, F_DIM, C_DIM, C_DIM);

    // conv-weight projection: 128x128 tiles, 128 CTAs, 5-stage ring, NC = 1024/64 = 16
    tc_gemm_plain<0, 1, 128, 5><<<dim3(NPAD / 128, M_DIM / 128), 256, smem_g1>>>(
        mA1, mB1, nullptr, nullptr, wraw, NPAD, C_DIM / KE);

    dynconv_ln_kernel<<<dim3(T_DIM / TT, B_DIM), 512, DC_SMEM>>>(
        x, wraw, b_lin, ln_g, ln_b, y, yh);

    // fc1 + ReLU -> fp16 h: 256x256 tiles, cluster (2,2), NC = 16
    tc_gemm_c4<1><<<dim3(F_DIM / 256, M_DIM / 256), 256, smem_c4>>>(
        mA2, mB2, fc1_b, nullptr, h, F_DIM, C_DIM / KE);

    // fc2 + bias + residual -> fp32 out: NC = 4096/64 = 64
    tc_gemm_c4<2><<<dim3(C_DIM / 256, M_DIM / 256), 256, smem_c4>>>(
        mA3, mB3, fc2_b, y, out, C_DIM, F_DIM / KE);
}

// round 9
// speedup vs baseline: 1.6422x; 1.0546x over previous
#include <cuda_runtime.h>
#include <cuda.h>
#include <cuda_fp16.h>
#include <dlfcn.h>
#include <math.h>
#include <stdint.h>

// ---------------- problem constants ----------------
#define T_DIM 1024
#define B_DIM 8
#define C_DIM 1024
#define F_DIM 4096
#define H_DIM 16
#define K_TAPS 15
#define M_DIM (T_DIM * B_DIM)   // 8192
#define NPAD 256
#define LN_EPS 1e-5f

#define KE 64                   // fp16 elements per k-chunk (128 bytes per row)

// dynconv tiling
#define TT 32
#define HALO (K_TAPS - 1)
#define XS_ROWS (TT + HALO)
#define DC_SMEM ((XS_ROWS * C_DIM + TT * (H_DIM * K_TAPS) + 64) * 4)

// arch-specific feature gate (tcgen05 only on the sm_103a pass)
#if defined(__CUDA_ARCH_FEAT_SM103_ALL) || defined(__CUDA_ARCH_FEAT_SM100_ALL) || \
    (defined(__CUDA_ARCH_SPECIFIC__) && (__CUDA_ARCH_SPECIFIC__ >= 1000)) ||      \
    (defined(__CUDA_ARCH_FAMILY_SPECIFIC__) && (__CUDA_ARCH_FAMILY_SPECIFIC__ >= 1000))
#define TC_OK 1
#else
#define TC_OK 0
#endif

// ---------------- scratch (device globals) ----------------
__device__ __half g_xh[(size_t)M_DIM * C_DIM];
__device__ __half g_wlinT[NPAD * C_DIM];
__device__ __half g_fc1wT[(size_t)F_DIM * C_DIM];
__device__ __half g_fc2wT[(size_t)C_DIM * F_DIM];
__device__ float  g_wraw[(size_t)M_DIM * NPAD];
__device__ float  g_y[(size_t)M_DIM * C_DIM];
__device__ __half g_yh[(size_t)M_DIM * C_DIM];
__device__ __half g_h[(size_t)M_DIM * F_DIM];

// ---------------- helpers ----------------
__device__ __forceinline__ uint32_t smem_u32(const void* p) {
    uint32_t a;
    asm("{ .reg .u64 t; cvta.to.shared.u64 t, %1; cvt.u32.u64 %0, t; }" : "=r"(a) : "l"(p));
    return a;
}
__device__ __forceinline__ uint32_t elect_one() {
    uint32_t p;
    asm volatile("{ .reg .pred p; elect.sync _|p, 0xFFFFFFFF; selp.b32 %0, 1, 0, p; }" : "=r"(p));
    return p;
}
__device__ __forceinline__ void mbar_init(uint32_t a, uint32_t cnt) {
    asm volatile("mbarrier.init.shared.b64 [%0], %1;" :: "r"(a), "r"(cnt) : "memory");
}
__device__ __forceinline__ void mbar_expect_tx(uint32_t a, uint32_t bytes) {
    asm volatile("mbarrier.arrive.expect_tx.shared.b64 _, [%0], %1;" :: "r"(a), "r"(bytes) : "memory");
}
__device__ __forceinline__ void mbar_wait(uint32_t a, uint32_t parity) {
    uint32_t done;
    asm volatile(
        "{ .reg .pred p;\n\t"
        "mbarrier.try_wait.parity.acquire.cta.shared::cta.b64 p, [%1], %2;\n\t"
        "selp.b32 %0, 1, 0, p; }" : "=r"(done) : "r"(a), "r"(parity) : "memory");
    if (!done) {
        asm volatile(
            "{ .reg .pred P1;\n\t"
            "WL_%=:\n\t"
            "mbarrier.try_wait.parity.acquire.cta.shared::cta.b64 P1, [%0], %1, 0x989680;\n\t"
            "@P1 bra.uni WD_%=;\n\t"
            "bra.uni WL_%=;\n\t"
            "WD_%=: }" :: "r"(a), "r"(parity) : "memory");
    }
}
#if TC_OK
__device__ __forceinline__ uint32_t cluster_rank() {
    uint32_t r;
    asm("mov.u32 %0, %%cluster_ctarank;" : "=r"(r));
    return r;
}
#define CLUSTER_SYNC() do { \
    asm volatile("barrier.cluster.arrive.aligned;" ::: "memory"); \
    asm volatile("barrier.cluster.wait.aligned;" ::: "memory");   \
} while (0)

__device__ __forceinline__ void tma_2d(uint32_t dst, const void* map, int cx, int cy, uint32_t mbar) {
    asm volatile(
        "cp.async.bulk.tensor.2d.shared::cta.global.tile.mbarrier::complete_tx::bytes "
        "[%0], [%1, {%2, %3}], [%4];"
        :: "r"(dst), "l"(map), "r"(cx), "r"(cy), "r"(mbar) : "memory");
}
// cg2 TMA (3D form, example-proven): complete_tx targets leader CTA's barrier (bit 24 cleared)
__device__ __forceinline__ void tma_3d_cg2(uint32_t dst, const void* map, int cx, int cy,
                                           uint32_t mbar) {
    asm volatile(
        "{\n\t"
        ".reg .b32 leaderBar;\n\t"
        "and.b32 leaderBar, %4, 0xFEFFFFFF;\n\t"
        "cp.async.bulk.tensor.3d.cta_group::2.shared::cluster.global"
        ".tile.mbarrier::complete_tx::bytes "
        "[%0], [%1, {%2, %3, %5}], [leaderBar];\n\t"
        "}"
        :: "r"(dst), "l"(map), "r"(cx), "r"(cy), "r"(mbar), "r"(0) : "memory");
}
__device__ __forceinline__ void mma_f16_ss(uint32_t d, uint64_t adesc, uint64_t bdesc,
                                           uint32_t idesc, uint32_t en) {
    asm volatile(
        "{ .reg .pred p;\n\t"
        "setp.ne.u32 p, %4, 0;\n\t"
        "tcgen05.mma.cta_group::1.kind::f16 [%0], %1, %2, %3, p; }"
        :: "r"(d), "l"(adesc), "l"(bdesc), "r"(idesc), "r"(en) : "memory");
}
__device__ __forceinline__ void mma_f16_ss_cg2(uint32_t d, uint64_t adesc, uint64_t bdesc,
                                               uint32_t idesc, uint32_t en) {
    asm volatile(
        "{ .reg .pred p;\n\t"
        "setp.ne.u32 p, %5, 0;\n\t"
        "tcgen05.mma.cta_group::2.kind::f16 [%0], %1, %2, %3, "
        "{%4, %4, %4, %4, %4, %4, %4, %4}, p; }"
        :: "r"(d), "l"(adesc), "l"(bdesc), "r"(idesc), "r"(0u), "r"(en) : "memory");
}
__device__ __forceinline__ void tc_commit(uint32_t mbar) {
    asm volatile(
        "tcgen05.commit.cta_group::1.mbarrier::arrive::one.shared::cluster.b64 [%0];"
        :: "r"(mbar) : "memory");
}
__device__ __forceinline__ void tc_commit_mc_cg2(uint32_t mbar, uint16_t mask) {
    asm volatile(
        "tcgen05.commit.cta_group::2.mbarrier::arrive::one.shared::cluster.multicast::cluster.b64 "
        "[%0], %1;"
        :: "r"(mbar), "h"(mask) : "memory");
}
#define TC_ALLOC(smem_addr, ncols) \
    asm volatile("tcgen05.alloc.cta_group::1.sync.aligned.shared::cta.b32 [%0], %1;" \
                 :: "r"(smem_addr), "r"(ncols) : "memory")
#define TC_RELINQ() \
    asm volatile("tcgen05.relinquish_alloc_permit.cta_group::1.sync.aligned;")
#define TC_DEALLOC(tmem, ncols) \
    asm volatile("tcgen05.dealloc.cta_group::1.sync.aligned.b32 %0, %1;" :: "r"(tmem), "r"(ncols))
#define TC_ALLOC_CG2(smem_addr, ncols) \
    asm volatile("tcgen05.alloc.cta_group::2.sync.aligned.shared::cta.b32 [%0], %1;" \
                 :: "r"(smem_addr), "r"(ncols) : "memory")
#define TC_RELINQ_CG2() \
    asm volatile("tcgen05.relinquish_alloc_permit.cta_group::2.sync.aligned;")
#define TC_DEALLOC_CG2(tmem, ncols) \
    asm volatile("tcgen05.dealloc.cta_group::2.sync.aligned.b32 %0, %1;" :: "r"(tmem), "r"(ncols))
#define TC_FENCE_AFTER()  asm volatile("tcgen05.fence::after_thread_sync;" ::: "memory")
#define TC_WAIT_LD()      asm volatile("tcgen05.wait::ld.sync.aligned;" ::: "memory")
#define TC_LD_X32(r, addr) \
    asm volatile("tcgen05.ld.sync.aligned.32x32b.x32.b32 " \
        "{%0, %1, %2, %3, %4, %5, %6, %7, %8, %9, %10, %11, %12, %13, %14, %15, " \
        " %16, %17, %18, %19, %20, %21, %22, %23, %24, %25, %26, %27, %28, %29, %30, %31}, [%32];" \
        : "=r"((r)[0]), "=r"((r)[1]), "=r"((r)[2]), "=r"((r)[3]), \
          "=r"((r)[4]), "=r"((r)[5]), "=r"((r)[6]), "=r"((r)[7]), \
          "=r"((r)[8]), "=r"((r)[9]), "=r"((r)[10]), "=r"((r)[11]), \
          "=r"((r)[12]), "=r"((r)[13]), "=r"((r)[14]), "=r"((r)[15]), \
          "=r"((r)[16]), "=r"((r)[17]), "=r"((r)[18]), "=r"((r)[19]), \
          "=r"((r)[20]), "=r"((r)[21]), "=r"((r)[22]), "=r"((r)[23]), \
          "=r"((r)[24]), "=r"((r)[25]), "=r"((r)[26]), "=r"((r)[27]), \
          "=r"((r)[28]), "=r"((r)[29]), "=r"((r)[30]), "=r"((r)[31]) \
        : "r"(addr))

__device__ __forceinline__ uint64_t smem_desc_sw128(uint32_t addr) {
    return ((uint64_t)2 << 61) | ((uint64_t)1 << 46) | ((uint64_t)64 << 32) |
           ((uint64_t)1 << 16) | (((uint64_t)addr >> 4) & 0x3FFF);
}
// kind::f16: dtype=F32(1@4), atype=btype=FP16(0), N>>3 @17, M>>4 @24
__device__ __forceinline__ constexpr uint32_t idesc_f16(int bn, int m) {
    return (1u << 4) | ((uint32_t)(bn / 8) << 17) | ((uint32_t)(m / 16) << 24);
}
#endif  // TC_OK

#if TC_OK
// column-chunk writer shared by epilogues
template <int EPI>
__device__ __forceinline__ void epi_write_chunk(const uint32_t* r, int row, int colbase,
                                                const float* __restrict__ bias,
                                                const float* __restrict__ res,
                                                void* __restrict__ Cv, int N) {
    if (EPI == 1) {
        __half* Ch = (__half*)Cv;
        __half2* dst = reinterpret_cast<__half2*>(&Ch[(size_t)row * N + colbase]);
        #pragma unroll
        for (int j = 0; j < 32; j += 2) {
            float v0 = fmaxf(__uint_as_float(r[j + 0]) + bias[colbase + j + 0], 0.f);
            float v1 = fmaxf(__uint_as_float(r[j + 1]) + bias[colbase + j + 1], 0.f);
            dst[j / 2] = __floats2half2_rn(v0, v1);
        }
    } else {
        float* C = (float*)Cv;
        float4* dst = reinterpret_cast<float4*>(&C[(size_t)row * N + colbase]);
        #pragma unroll
        for (int j = 0; j < 32; j += 4) {
            float4 v;
            v.x = __uint_as_float(r[j + 0]);
            v.y = __uint_as_float(r[j + 1]);
            v.z = __uint_as_float(r[j + 2]);
            v.w = __uint_as_float(r[j + 3]);
            if (EPI == 2) {
                v.x += bias[colbase + j + 0]; v.y += bias[colbase + j + 1];
                v.z += bias[colbase + j + 2]; v.w += bias[colbase + j + 3];
                float4 rv = *reinterpret_cast<const float4*>(&res[(size_t)row * N + colbase + j]);
                v.x += rv.x; v.y += rv.y; v.z += rv.z; v.w += rv.w;
            }
            dst[j / 4] = v;
        }
    }
}
#endif

// ================= plain warp-specialized tcgen05 fp16 GEMM (GEMM1) =================
template <int EPI, int BN_, int STG>
__global__ __launch_bounds__(256)
void tc_gemm_plain(const __grid_constant__ CUtensorMap tmA,
                   const __grid_constant__ CUtensorMap tmB,
                   const float* __restrict__ bias, const float* __restrict__ res,
                   void* __restrict__ C, int N, int NC) {
#if TC_OK
    constexpr int CA = 128 * 128;
    constexpr int CB = BN_ * 128;
    constexpr int CBYTES = CA + CB;
    constexpr int TCOLS = BN_;

    extern __shared__ __align__(1024) char smem[];
    const int tid  = threadIdx.x;
    const int warp = tid >> 5;
    const int lane = tid & 31;

    uint32_t sb = (smem_u32(smem) + 1023u) & ~1023u;
    const uint32_t tmem_ptr_addr = sb;
    const uint32_t mb_all = sb + 8 + 16 * STG;
    uint32_t mb_full[STG], mb_done[STG], bufA[STG], bufB[STG];
    #pragma unroll
    for (int s = 0; s < STG; s++) {
        mb_full[s] = sb + 8 + 8 * s;
        mb_done[s] = sb + 8 + 8 * STG + 8 * s;
        bufA[s] = sb + 1024 + s * CBYTES;
        bufB[s] = bufA[s] + CA;
    }

    if (warp == 0) { TC_ALLOC(tmem_ptr_addr, TCOLS); TC_RELINQ(); }
    if (tid == 0) {
        #pragma unroll
        for (int s = 0; s < STG; s++) { mbar_init(mb_full[s], 1); mbar_init(mb_done[s], 1); }
        mbar_init(mb_all, 1);
    }
    __syncthreads();

    uint32_t tmem;
    asm volatile("ld.shared.b32 %0, [%1];" : "=r"(tmem) : "r"(tmem_ptr_addr));

    const int tile_m = blockIdx.y * 128;
    const int tile_n = blockIdx.x * BN_;

    if (warp == 1 && elect_one()) {
        uint32_t phd = 0;
        for (int j = 0; j < NC; j++) {
            const int s = j % STG;
            if (j >= STG) { mbar_wait(mb_done[s], (phd >> s) & 1); phd ^= 1u << s; }
            mbar_expect_tx(mb_full[s], CBYTES);
            tma_2d(bufA[s], &tmA, j * KE, tile_m, mb_full[s]);
            tma_2d(bufB[s], &tmB, j * KE, tile_n, mb_full[s]);
        }
    }
    if (warp == 0 && elect_one()) {
        uint64_t ad[STG], bd[STG];
        #pragma unroll
        for (int s = 0; s < STG; s++) {
            ad[s] = smem_desc_sw128(bufA[s]);
            bd[s] = smem_desc_sw128(bufB[s]);
        }
        uint32_t phf = 0;
        for (int kc = 0; kc < NC; kc++) {
            const int s = kc % STG;
            mbar_wait(mb_full[s], (phf >> s) & 1); phf ^= 1u << s;
            #pragma unroll
            for (int s2 = 0; s2 < 4; s2++) {
                const uint32_t en = (kc > 0 || s2 > 0) ? 1u : 0u;
                mma_f16_ss(tmem, ad[s] + 2 * s2, bd[s] + 2 * s2, idesc_f16(BN_, 128), en);
            }
            tc_commit(mb_done[s]);
        }
        tc_commit(mb_all);
        mbar_wait(mb_all, 0);
    }
    __syncthreads();
    TC_FENCE_AFTER();
    // epilogue: 8 warps, half=warp>>2 splits N
    {
        const int half_ = warp >> 2;
        const uint32_t dbase = tmem + half_ * (BN_ / 2);
        const int row = tile_m + (warp & 3) * 32 + lane;
        const int col0 = tile_n + half_ * (BN_ / 2);
        #pragma unroll 1
        for (int cc = 0; cc < BN_ / 64; cc++) {
            uint32_t r[32];
            TC_LD_X32(r, dbase + cc * 32);
            TC_WAIT_LD();
            epi_write_chunk<EPI>(r, row, col0 + cc * 32, bias, res, C, N);
        }
    }
    __syncthreads();
    if (warp == 0) TC_DEALLOC(tmem, TCOLS);
#endif
}

// ================= cg2 pair GEMM: 512(M) x 256(N) per 2-CTA cluster =================
// Each CTA holds: A rows [tile_m + rank*128, +128) and [tile_m+256+rank*128, +128) (32KB)
// and B rows [tile_n + rank*128, +128) (16KB) per chunk. Leader issues two M=256 cg2 MMAs
// per K-step into TMEM cols [0,256) and [256,512). 4-stage ring, pair expect_tx = 96KB.
template <int EPI>
__global__ __launch_bounds__(256) __cluster_dims__(2, 1, 1)
void tc_gemm_cg2(const __grid_constant__ CUtensorMap tmA,
                 const __grid_constant__ CUtensorMap tmB,
                 const float* __restrict__ bias, const float* __restrict__ res,
                 void* __restrict__ C, int N, int NC) {
#if TC_OK
    constexpr int STG = 4;
    constexpr int CA = 2 * 128 * 128;          // 32 KB
    constexpr int CB = 128 * 128;              // 16 KB
    constexpr int CBYTES = CA + CB;            // 48 KB per CTA
    constexpr int PAIR_BYTES = 2 * CBYTES;     // 96 KB per pair per stage
    constexpr int TCOLS = 512;

    extern __shared__ __align__(1024) char smem[];
    const int tid  = threadIdx.x;
    const int warp = tid >> 5;
    const int lane = tid & 31;

    uint32_t sb = (smem_u32(smem) + 1023u) & ~1023u;
    const uint32_t tmem_ptr_addr = sb;
    const uint32_t mb_all = sb + 8 + 16 * STG;
    uint32_t mb_full[STG], mb_done[STG], bufA[STG], bufB[STG];
    #pragma unroll
    for (int s = 0; s < STG; s++) {
        mb_full[s] = sb + 8 + 8 * s;
        mb_done[s] = sb + 8 + 8 * STG + 8 * s;
        bufA[s] = sb + 1024 + s * CBYTES;
        bufB[s] = bufA[s] + CA;
    }

    if (warp == 0) { TC_ALLOC_CG2(tmem_ptr_addr, TCOLS); TC_RELINQ_CG2(); }
    if (tid == 0) {
        #pragma unroll
        for (int s = 0; s < STG; s++) { mbar_init(mb_full[s], 1); mbar_init(mb_done[s], 1); }
        mbar_init(mb_all, 1);
    }
    __syncthreads();
    CLUSTER_SYNC();   // peer barriers live before cg2 TMA/commit can target them

    uint32_t tmem;
    asm volatile("ld.shared.b32 %0, [%1];" : "=r"(tmem) : "r"(tmem_ptr_addr));

    const int rank  = (int)cluster_rank();          // 0 = leader
    const int tile_m = blockIdx.y * 512;
    const int tile_n = (blockIdx.x >> 1) * 256;

    if (warp == 1 && elect_one()) {
        // producer (both CTAs): ring gated by local done (multicast commit arrives here)
        uint32_t phd = 0;
        const int rowA0 = tile_m + rank * 128;
        const int rowA1 = tile_m + 256 + rank * 128;
        const int rowB  = tile_n + rank * 128;
        for (int j = 0; j < NC; j++) {
            const int s = j % STG;
            if (j >= STG) { mbar_wait(mb_done[s], (phd >> s) & 1); phd ^= 1u << s; }
            if (rank == 0) mbar_expect_tx(mb_full[s], PAIR_BYTES);
            tma_3d_cg2(bufA[s],         &tmA, j * KE, rowA0, mb_full[s]);
            tma_3d_cg2(bufA[s] + 16384, &tmA, j * KE, rowA1, mb_full[s]);
            tma_3d_cg2(bufB[s],         &tmB, j * KE, rowB,  mb_full[s]);
        }
    }
    if (rank == 0 && warp == 0 && elect_one()) {
        // consumer (leader only): cg2 MMAs read both CTAs' smem at same offsets
        uint64_t adLo[STG], adHi[STG], bd[STG];
        #pragma unroll
        for (int s = 0; s < STG; s++) {
            adLo[s] = smem_desc_sw128(bufA[s]);
            adHi[s] = smem_desc_sw128(bufA[s] + 16384);
            bd[s]   = smem_desc_sw128(bufB[s]);
        }
        uint32_t phf = 0;
        for (int kc = 0; kc < NC; kc++) {
            const int s = kc % STG;
            mbar_wait(mb_full[s], (phf >> s) & 1); phf ^= 1u << s;
            #pragma unroll
            for (int s2 = 0; s2 < 4; s2++) {     // KE=64 halfs = 4 x (K=16) cg2 MMAs x 2 M-halves
                const uint32_t en = (kc > 0 || s2 > 0) ? 1u : 0u;
                mma_f16_ss_cg2(tmem,       adLo[s] + 2 * s2, bd[s] + 2 * s2,
                               idesc_f16(256, 256), en);
                mma_f16_ss_cg2(tmem + 256, adHi[s] + 2 * s2, bd[s] + 2 * s2,
                               idesc_f16(256, 256), en);
            }
            tc_commit_mc_cg2(mb_done[s], 0x3);
        }
        tc_commit_mc_cg2(mb_all, 0x3);
    }
    __syncthreads();
    mbar_wait(mb_all, 0);     // both CTAs: all MMAs (incl. peer-TMEM writes) complete
    TC_FENCE_AFTER();

    // epilogue: each CTA holds 128 rows per M-half. half=warp>>2 selects M-half/col-half.
    {
        const int half_ = warp >> 2;
        const uint32_t dbase = tmem + half_ * 256;
        const int row = tile_m + half_ * 256 + rank * 128 + (warp & 3) * 32 + lane;
        #pragma unroll 1
        for (int cc = 0; cc < 8; cc++) {
            uint32_t r[32];
            TC_LD_X32(r, dbase + cc * 32);
            TC_WAIT_LD();
            epi_write_chunk<EPI>(r, row, tile_n + cc * 32, bias, res, C, N);
        }
    }
    __syncthreads();
    if (warp == 0) TC_DEALLOC_CG2(tmem, TCOLS);
    CLUSTER_SYNC();   // no CTA exits while peer may still target its barriers/smem
#endif
}

// ================= transpose to fp16 (+pad rows) =================
__global__ void transpose_h_kernel(const float* __restrict__ in, __half* __restrict__ out,
                                   int R, int Cc, int Cp) {
    __shared__ float tile[32][33];
    const int c0 = blockIdx.x * 32, r0 = blockIdx.y * 32;
    const int x = c0 + threadIdx.x;
    #pragma unroll
    for (int i = 0; i < 32; i += 8) {
        const int y = r0 + threadIdx.y + i;
        float v = 0.f;
        if (x < Cc && y < R) v = in[(size_t)y * Cc + x];
        tile[threadIdx.y + i][threadIdx.x] = v;
    }
    __syncthreads();
    const int ox = r0 + threadIdx.x;
    #pragma unroll
    for (int i = 0; i < 32; i += 8) {
        const int oy = c0 + threadIdx.y + i;
        if (oy < Cp && ox < R)
            out[(size_t)oy * R + ox] = __float2half(tile[threadIdx.x][threadIdx.y + i]);
    }
}

// ================= fp32 -> fp16 elementwise =================
__global__ void f2h_kernel(const float* __restrict__ in, __half* __restrict__ out, int n2) {
    int i = blockIdx.x * blockDim.x + threadIdx.x;
    if (i < n2) {
        float2 v = reinterpret_cast<const float2*>(in)[i];
        reinterpret_cast<__half2*>(out)[i] = __floats2half2_rn(v.x, v.y);
    }
}

// ================= t-tiled softmax + causal dynamic conv + LayerNorm =================
__global__ __launch_bounds__(512)
void dynconv_ln_kernel(const float* __restrict__ x, const float* __restrict__ wraw,
                       const float* __restrict__ b_lin,
                       const float* __restrict__ ln_g, const float* __restrict__ ln_b,
                       float* __restrict__ y, __half* __restrict__ yh) {
    extern __shared__ float sm[];
    float* xs  = sm;
    float* ws  = xs + XS_ROWS * C_DIM;
    float* red = ws + TT * (H_DIM * K_TAPS);

    const int t0  = blockIdx.x * TT;
    const int b   = blockIdx.y;
    const int tid = threadIdx.x;

    {
        float4* xs4 = reinterpret_cast<float4*>(xs);
        const int total4 = XS_ROWS * (C_DIM / 4);
        for (int i = tid; i < total4; i += 512) {
            const int r = i / (C_DIM / 4);
            const int cc = i % (C_DIM / 4);
            const int t = t0 - HALO + r;
            float4 v = make_float4(0.f, 0.f, 0.f, 0.f);
            if (t >= 0)
                v = reinterpret_cast<const float4*>(x)[((size_t)(t * B_DIM + b)) * (C_DIM / 4) + cc];
            xs4[i] = v;
        }
    }
    for (int i = tid; i < TT * (H_DIM * K_TAPS); i += 512) {
        const int lt = i / (H_DIM * K_TAPS);
        const int j  = i % (H_DIM * K_TAPS);
        ws[i] = wraw[(size_t)((t0 + lt) * B_DIM + b) * NPAD + j] + b_lin[j];
    }
    __syncthreads();

    {
        const int lt = tid >> 4;
        const int hd = tid & 15;
        float* p = ws + lt * (H_DIM * K_TAPS) + hd * K_TAPS;
        float mx = -1e30f;
        #pragma unroll
        for (int k = 0; k < K_TAPS; k++) mx = fmaxf(mx, p[k]);
        float e[K_TAPS]; float s = 0.f;
        #pragma unroll
        for (int k = 0; k < K_TAPS; k++) { e[k] = expf(p[k] - mx); s += e[k]; }
        const float inv = 1.0f / s;
        #pragma unroll
        for (int k = 0; k < K_TAPS; k++) p[k] = e[k] * inv;
    }
    __syncthreads();

    const int c0 = tid * 2;
    const int h  = c0 >> 6;
    const float g0 = ln_g[c0], g1 = ln_g[c0 + 1];
    const float bb0 = ln_b[c0], bb1 = ln_b[c0 + 1];
    const int wid = tid >> 5, lane = tid & 31;

    for (int lt = 0; lt < TT; lt++) {
        const float* wrow = ws + lt * (H_DIM * K_TAPS) + h * K_TAPS;
        float a0 = 0.f, a1 = 0.f;
        #pragma unroll
        for (int k = 0; k < K_TAPS; k++) {
            const float wgt = wrow[k];
            const float2 xv = *reinterpret_cast<const float2*>(&xs[(lt + k) * C_DIM + c0]);
            a0 += wgt * xv.x;
            a1 += wgt * xv.y;
        }
        float s1 = a0 + a1;
        float s2 = a0 * a0 + a1 * a1;
        #pragma unroll
        for (int off = 16; off > 0; off >>= 1) {
            s1 += __shfl_down_sync(0xFFFFFFFFu, s1, off);
            s2 += __shfl_down_sync(0xFFFFFFFFu, s2, off);
        }
        if (lane == 0) { red[wid] = s1; red[16 + wid] = s2; }
        __syncthreads();
        if (tid == 0) {
            float sa = 0.f, sb2 = 0.f;
            #pragma unroll
            for (int i = 0; i < 16; i++) { sa += red[i]; sb2 += red[16 + i]; }
            const float mu = sa * (1.0f / C_DIM);
            const float var = sb2 * (1.0f / C_DIM) - mu * mu;
            red[32] = mu;
            red[33] = rsqrtf(var + LN_EPS);
        }
        __syncthreads();
        const float mu = red[32], rstd = red[33];
        const float v0 = (a0 - mu) * rstd * g0 + bb0;
        const float v1 = (a1 - mu) * rstd * g1 + bb1;
        const size_t base = (size_t)((t0 + lt) * B_DIM + b) * C_DIM + c0;
        *reinterpret_cast<float2*>(&y[base]) = make_float2(v0, v1);
        *reinterpret_cast<__half2*>(&yh[base]) = __floats2half2_rn(v0, v1);
    }
}

// ================= host side =================
typedef CUresult (*PFN_encodeTiled)(CUtensorMap*, CUtensorMapDataType, cuuint32_t, void*,
                                    const cuuint64_t*, const cuuint64_t*, const cuuint32_t*,
                                    const cuuint32_t*, CUtensorMapInterleave, CUtensorMapSwizzle,
                                    CUtensorMapL2promotion, CUtensorMapFloatOOBfill);

static PFN_encodeTiled get_encoder() {
    static PFN_encodeTiled fn = nullptr;
    if (!fn) {
        void* h = dlopen("libcuda.so.1", RTLD_LAZY | RTLD_GLOBAL);
        if (!h) h = dlopen("libcuda.so", RTLD_LAZY | RTLD_GLOBAL);
        if (h) fn = (PFN_encodeTiled)dlsym(h, "cuTensorMapEncodeTiled");
    }
    return fn;
}

// 2D fp16 map (GEMM1)
static void make_map_h2(CUtensorMap* m, const void* ptr, uint64_t d0, uint64_t d1, uint32_t b1) {
    cuuint64_t dims[2] = { d0, d1 };
    cuuint64_t strides[1] = { d0 * 2 };
    cuuint32_t box[2] = { KE, b1 };
    cuuint32_t es[2] = { 1, 1 };
    PFN_encodeTiled enc = get_encoder();
    if (enc)
        enc(m, CU_TENSOR_MAP_DATA_TYPE_FLOAT16, 2, (void*)ptr, dims, strides, box, es,
            CU_TENSOR_MAP_INTERLEAVE_NONE, CU_TENSOR_MAP_SWIZZLE_128B,
            CU_TENSOR_MAP_L2_PROMOTION_L2_128B, CU_TENSOR_MAP_FLOAT_OOB_FILL_NONE);
}
// 3D fp16 map (cg2 GEMMs), box [KE, 128, 1]
static void make_map_h3(CUtensorMap* m, const void* ptr, uint64_t d0, uint64_t d1) {
    cuuint64_t dims[3] = { d0, d1, 1 };
    cuuint64_t strides[2] = { d0 * 2, d0 * d1 * 2 };
    cuuint32_t box[3] = { KE, 128, 1 };
    cuuint32_t es[3] = { 1, 1, 1 };
    PFN_encodeTiled enc = get_encoder();
    if (enc)
        enc(m, CU_TENSOR_MAP_DATA_TYPE_FLOAT16, 3, (void*)ptr, dims, strides, box, es,
            CU_TENSOR_MAP_INTERLEAVE_NONE, CU_TENSOR_MAP_SWIZZLE_128B,
            CU_TENSOR_MAP_L2_PROMOTION_L2_128B, CU_TENSOR_MAP_FLOAT_OOB_FILL_NONE);
}

extern "C" void kernel_launch(void* const* d_in, const int* in_sizes, int n_in,
                              void* d_out, int out_size) {
    const float* x     = (const float*)d_in[0];
    const float* w_lin = (const float*)d_in[1];
    const float* b_lin = (const float*)d_in[2];
    const float* ln_g  = (const float*)d_in[3];
    const float* ln_b  = (const float*)d_in[4];
    const float* fc1_w = (const float*)d_in[5];
    const float* fc1_b = (const float*)d_in[6];
    const float* fc2_w = (const float*)d_in[7];
    const float* fc2_b = (const float*)d_in[8];
    float* out = (float*)d_out;

    __half *xh, *wlinT, *fc1wT, *fc2wT, *yh, *h;
    float *wraw, *y;
    cudaGetSymbolAddress((void**)&xh, g_xh);
    cudaGetSymbolAddress((void**)&wlinT, g_wlinT);
    cudaGetSymbolAddress((void**)&fc1wT, g_fc1wT);
    cudaGetSymbolAddress((void**)&fc2wT, g_fc2wT);
    cudaGetSymbolAddress((void**)&wraw, g_wraw);
    cudaGetSymbolAddress((void**)&y, g_y);
    cudaGetSymbolAddress((void**)&yh, g_yh);
    cudaGetSymbolAddress((void**)&h, g_h);

    const int smem_g1  = 1024 + 5 * (128 * 128 + 128 * 128);      // 5 x 32KB
    const int smem_cg2 = 1024 + 4 * (2 * 128 * 128 + 128 * 128);  // 4 x 48KB = 193KB
    cudaFuncSetAttribute((const void*)tc_gemm_plain<0, 128, 5>,
                         cudaFuncAttributeMaxDynamicSharedMemorySize, smem_g1);
    cudaFuncSetAttribute((const void*)tc_gemm_cg2<1>,
                         cudaFuncAttributeMaxDynamicSharedMemorySize, smem_cg2);
    cudaFuncSetAttribute((const void*)tc_gemm_cg2<2>,
                         cudaFuncAttributeMaxDynamicSharedMemorySize, smem_cg2);
    cudaFuncSetAttribute((const void*)dynconv_ln_kernel,
                         cudaFuncAttributeMaxDynamicSharedMemorySize, DC_SMEM);

    CUtensorMap mA1{}, mB1{}, mA2{}, mB2{}, mA3{}, mB3{};
    make_map_h2(&mA1, xh,    C_DIM, M_DIM, 128);
    make_map_h2(&mB1, wlinT, C_DIM, NPAD,  128);
    make_map_h3(&mA2, yh,    C_DIM, M_DIM);
    make_map_h3(&mB2, fc1wT, C_DIM, F_DIM);
    make_map_h3(&mA3, h,     F_DIM, M_DIM);
    make_map_h3(&mB3, fc2wT, F_DIM, C_DIM);

    dim3 tb(32, 8);
    f2h_kernel<<<(M_DIM * C_DIM / 2 + 255) / 256, 256>>>(x, xh, M_DIM * C_DIM / 2);
    transpose_h_kernel<<<dim3(NPAD / 32, C_DIM / 32), tb>>>(w_lin, wlinT, C_DIM, H_DIM * K_TAPS, NPAD);
    transpose_h_kernel<<<dim3(F_DIM / 32, C_DIM / 32), tb>>>(fc1_w, fc1wT, C_DIM, F_DIM, F_DIM);
    transpose_h_kernel<<<dim3(C_DIM / 32, F_DIM / 32), tb>>>(fc2_w, fc2wT, F_DIM, C_DIM, C_DIM);

    // conv-weight projection: 128x128 tiles, 128 CTAs, 5-stage ring
    tc_gemm_plain<0, 128, 5><<<dim3(NPAD / 128, M_DIM / 128), 256, smem_g1>>>(
        mA1, mB1, nullptr, nullptr, wraw, NPAD, C_DIM / KE);

    dynconv_ln_kernel<<<dim3(T_DIM / TT, B_DIM), 512, DC_SMEM>>>(
        x, wraw, b_lin, ln_g, ln_b, y, yh);

    // fc1 + ReLU -> fp16 h: 512x256 per cg2 pair; grid.x = 2 * (4096/256) = 32, grid.y = 16
    tc_gemm_cg2<1><<<dim3(2 * (F_DIM / 256), M_DIM / 512), 256, smem_cg2>>>(
        mA2, mB2, fc1_b, nullptr, h, F_DIM, C_DIM / KE);

    // fc2 + bias + residual -> fp32 out: grid.x = 2 * (1024/256) = 8, grid.y = 16
    tc_gemm_cg2<2><<<dim3(2 * (C_DIM / 256), M_DIM / 512), 256, smem_cg2>>>(
        mA3, mB3, fc2_b, y, out, C_DIM, F_DIM / KE);
}

// round 10
// speedup vs baseline: 1.7096x; 1.0410x over previous
#include <cuda_runtime.h>
#include <cuda.h>
#include <cuda_fp16.h>
#include <dlfcn.h>
#include <math.h>
#include <stdint.h>

// ---------------- problem constants ----------------
#define T_DIM 1024
#define B_DIM 8
#define C_DIM 1024
#define F_DIM 4096
#define H_DIM 16
#define K_TAPS 15
#define M_DIM (T_DIM * B_DIM)   // 8192
#define NPAD 256
#define LN_EPS 1e-5f

#define KE 64                   // fp16 elements per k-chunk (128 bytes per row)

// dynconv tiling
#define TT 32
#define HALO (K_TAPS - 1)
#define XS_ROWS (TT + HALO)
#define DC_SMEM ((XS_ROWS * C_DIM + TT * (H_DIM * K_TAPS) + 64) * 4)

// arch-specific feature gate (tcgen05 only on the sm_103a pass)
#if defined(__CUDA_ARCH_FEAT_SM103_ALL) || defined(__CUDA_ARCH_FEAT_SM100_ALL) || \
    (defined(__CUDA_ARCH_SPECIFIC__) && (__CUDA_ARCH_SPECIFIC__ >= 1000)) ||      \
    (defined(__CUDA_ARCH_FAMILY_SPECIFIC__) && (__CUDA_ARCH_FAMILY_SPECIFIC__ >= 1000))
#define TC_OK 1
#else
#define TC_OK 0
#endif

// ---------------- scratch (device globals) ----------------
__device__ __half g_xh[(size_t)M_DIM * C_DIM];
__device__ __half g_wlinT[NPAD * C_DIM];
__device__ __half g_fc1wT[(size_t)F_DIM * C_DIM];
__device__ __half g_fc2wT[(size_t)C_DIM * F_DIM];
__device__ float  g_wraw[(size_t)M_DIM * NPAD];
__device__ float  g_y[(size_t)M_DIM * C_DIM];
__device__ __half g_yh[(size_t)M_DIM * C_DIM];
__device__ __half g_h[(size_t)M_DIM * F_DIM];

// ---------------- helpers ----------------
__device__ __forceinline__ uint32_t smem_u32(const void* p) {
    uint32_t a;
    asm("{ .reg .u64 t; cvta.to.shared.u64 t, %1; cvt.u32.u64 %0, t; }" : "=r"(a) : "l"(p));
    return a;
}
__device__ __forceinline__ uint32_t elect_one() {
    uint32_t p;
    asm volatile("{ .reg .pred p; elect.sync _|p, 0xFFFFFFFF; selp.b32 %0, 1, 0, p; }" : "=r"(p));
    return p;
}
__device__ __forceinline__ void mbar_init(uint32_t a, uint32_t cnt) {
    asm volatile("mbarrier.init.shared.b64 [%0], %1;" :: "r"(a), "r"(cnt) : "memory");
}
__device__ __forceinline__ void mbar_expect_tx(uint32_t a, uint32_t bytes) {
    asm volatile("mbarrier.arrive.expect_tx.shared.b64 _, [%0], %1;" :: "r"(a), "r"(bytes) : "memory");
}
__device__ __forceinline__ void mbar_wait(uint32_t a, uint32_t parity) {
    uint32_t done;
    asm volatile(
        "{ .reg .pred p;\n\t"
        "mbarrier.try_wait.parity.acquire.cta.shared::cta.b64 p, [%1], %2;\n\t"
        "selp.b32 %0, 1, 0, p; }" : "=r"(done) : "r"(a), "r"(parity) : "memory");
    if (!done) {
        asm volatile(
            "{ .reg .pred P1;\n\t"
            "WL_%=:\n\t"
            "mbarrier.try_wait.parity.acquire.cta.shared::cta.b64 P1, [%0], %1, 0x989680;\n\t"
            "@P1 bra.uni WD_%=;\n\t"
            "bra.uni WL_%=;\n\t"
            "WD_%=: }" :: "r"(a), "r"(parity) : "memory");
    }
}
#if TC_OK
__device__ __forceinline__ uint32_t cluster_rank() {
    uint32_t r;
    asm("mov.u32 %0, %%cluster_ctarank;" : "=r"(r));
    return r;
}
#define CLUSTER_SYNC() do { \
    asm volatile("barrier.cluster.arrive.aligned;" ::: "memory"); \
    asm volatile("barrier.cluster.wait.aligned;" ::: "memory");   \
} while (0)

__device__ __forceinline__ void tma_2d(uint32_t dst, const void* map, int cx, int cy, uint32_t mbar) {
    asm volatile(
        "cp.async.bulk.tensor.2d.shared::cta.global.tile.mbarrier::complete_tx::bytes "
        "[%0], [%1, {%2, %3}], [%4];"
        :: "r"(dst), "l"(map), "r"(cx), "r"(cy), "r"(mbar) : "memory");
}
// cg2 TMA (3D form): complete_tx targets leader CTA's barrier (bit 24 cleared)
__device__ __forceinline__ void tma_3d_cg2(uint32_t dst, const void* map, int cx, int cy,
                                           uint32_t mbar) {
    asm volatile(
        "{\n\t"
        ".reg .b32 leaderBar;\n\t"
        "and.b32 leaderBar, %4, 0xFEFFFFFF;\n\t"
        "cp.async.bulk.tensor.3d.cta_group::2.shared::cluster.global"
        ".tile.mbarrier::complete_tx::bytes "
        "[%0], [%1, {%2, %3, %5}], [leaderBar];\n\t"
        "}"
        :: "r"(dst), "l"(map), "r"(cx), "r"(cy), "r"(mbar), "r"(0) : "memory");
}
__device__ __forceinline__ void mma_f16_ss(uint32_t d, uint64_t adesc, uint64_t bdesc,
                                           uint32_t idesc, uint32_t en) {
    asm volatile(
        "{ .reg .pred p;\n\t"
        "setp.ne.u32 p, %4, 0;\n\t"
        "tcgen05.mma.cta_group::1.kind::f16 [%0], %1, %2, %3, p; }"
        :: "r"(d), "l"(adesc), "l"(bdesc), "r"(idesc), "r"(en) : "memory");
}
__device__ __forceinline__ void mma_f16_ss_cg2(uint32_t d, uint64_t adesc, uint64_t bdesc,
                                               uint32_t idesc, uint32_t en) {
    asm volatile(
        "{ .reg .pred p;\n\t"
        "setp.ne.u32 p, %5, 0;\n\t"
        "tcgen05.mma.cta_group::2.kind::f16 [%0], %1, %2, %3, "
        "{%4, %4, %4, %4, %4, %4, %4, %4}, p; }"
        :: "r"(d), "l"(adesc), "l"(bdesc), "r"(idesc), "r"(0u), "r"(en) : "memory");
}
__device__ __forceinline__ void tc_commit(uint32_t mbar) {
    asm volatile(
        "tcgen05.commit.cta_group::1.mbarrier::arrive::one.shared::cluster.b64 [%0];"
        :: "r"(mbar) : "memory");
}
__device__ __forceinline__ void tc_commit_mc_cg2(uint32_t mbar, uint16_t mask) {
    asm volatile(
        "tcgen05.commit.cta_group::2.mbarrier::arrive::one.shared::cluster.multicast::cluster.b64 "
        "[%0], %1;"
        :: "r"(mbar), "h"(mask) : "memory");
}
#define TC_ALLOC(smem_addr, ncols) \
    asm volatile("tcgen05.alloc.cta_group::1.sync.aligned.shared::cta.b32 [%0], %1;" \
                 :: "r"(smem_addr), "r"(ncols) : "memory")
#define TC_RELINQ() \
    asm volatile("tcgen05.relinquish_alloc_permit.cta_group::1.sync.aligned;")
#define TC_DEALLOC(tmem, ncols) \
    asm volatile("tcgen05.dealloc.cta_group::1.sync.aligned.b32 %0, %1;" :: "r"(tmem), "r"(ncols))
#define TC_ALLOC_CG2(smem_addr, ncols) \
    asm volatile("tcgen05.alloc.cta_group::2.sync.aligned.shared::cta.b32 [%0], %1;" \
                 :: "r"(smem_addr), "r"(ncols) : "memory")
#define TC_RELINQ_CG2() \
    asm volatile("tcgen05.relinquish_alloc_permit.cta_group::2.sync.aligned;")
#define TC_DEALLOC_CG2(tmem, ncols) \
    asm volatile("tcgen05.dealloc.cta_group::2.sync.aligned.b32 %0, %1;" :: "r"(tmem), "r"(ncols))
#define TC_FENCE_AFTER()  asm volatile("tcgen05.fence::after_thread_sync;" ::: "memory")
#define TC_WAIT_LD()      asm volatile("tcgen05.wait::ld.sync.aligned;" ::: "memory")
#define TC_LD_X32(r, addr) \
    asm volatile("tcgen05.ld.sync.aligned.32x32b.x32.b32 " \
        "{%0, %1, %2, %3, %4, %5, %6, %7, %8, %9, %10, %11, %12, %13, %14, %15, " \
        " %16, %17, %18, %19, %20, %21, %22, %23, %24, %25, %26, %27, %28, %29, %30, %31}, [%32];" \
        : "=r"((r)[0]), "=r"((r)[1]), "=r"((r)[2]), "=r"((r)[3]), \
          "=r"((r)[4]), "=r"((r)[5]), "=r"((r)[6]), "=r"((r)[7]), \
          "=r"((r)[8]), "=r"((r)[9]), "=r"((r)[10]), "=r"((r)[11]), \
          "=r"((r)[12]), "=r"((r)[13]), "=r"((r)[14]), "=r"((r)[15]), \
          "=r"((r)[16]), "=r"((r)[17]), "=r"((r)[18]), "=r"((r)[19]), \
          "=r"((r)[20]), "=r"((r)[21]), "=r"((r)[22]), "=r"((r)[23]), \
          "=r"((r)[24]), "=r"((r)[25]), "=r"((r)[26]), "=r"((r)[27]), \
          "=r"((r)[28]), "=r"((r)[29]), "=r"((r)[30]), "=r"((r)[31]) \
        : "r"(addr))

__device__ __forceinline__ uint64_t smem_desc_sw128(uint32_t addr) {
    return ((uint64_t)2 << 61) | ((uint64_t)1 << 46) | ((uint64_t)64 << 32) |
           ((uint64_t)1 << 16) | (((uint64_t)addr >> 4) & 0x3FFF);
}
__device__ __forceinline__ constexpr uint32_t idesc_f16(int bn, int m) {
    return (1u << 4) | ((uint32_t)(bn / 8) << 17) | ((uint32_t)(m / 16) << 24);
}
#endif  // TC_OK

#if TC_OK
// column-chunk writer shared by epilogues
template <int EPI>
__device__ __forceinline__ void epi_write_chunk(const uint32_t* r, int row, int colbase,
                                                const float* __restrict__ bias,
                                                const float* __restrict__ res,
                                                void* __restrict__ Cv, int N) {
    if (EPI == 1) {
        __half* Ch = (__half*)Cv;
        __half2* dst = reinterpret_cast<__half2*>(&Ch[(size_t)row * N + colbase]);
        #pragma unroll
        for (int j = 0; j < 32; j += 2) {
            float v0 = fmaxf(__uint_as_float(r[j + 0]) + bias[colbase + j + 0], 0.f);
            float v1 = fmaxf(__uint_as_float(r[j + 1]) + bias[colbase + j + 1], 0.f);
            dst[j / 2] = __floats2half2_rn(v0, v1);
        }
    } else {
        float* C = (float*)Cv;
        float4* dst = reinterpret_cast<float4*>(&C[(size_t)row * N + colbase]);
        #pragma unroll
        for (int j = 0; j < 32; j += 4) {
            float4 v;
            v.x = __uint_as_float(r[j + 0]);
            v.y = __uint_as_float(r[j + 1]);
            v.z = __uint_as_float(r[j + 2]);
            v.w = __uint_as_float(r[j + 3]);
            if (EPI == 2) {
                v.x += bias[colbase + j + 0]; v.y += bias[colbase + j + 1];
                v.z += bias[colbase + j + 2]; v.w += bias[colbase + j + 3];
                float4 rv = *reinterpret_cast<const float4*>(&res[(size_t)row * N + colbase + j]);
                v.x += rv.x; v.y += rv.y; v.z += rv.z; v.w += rv.w;
            }
            dst[j / 4] = v;
        }
    }
}
#endif

// ================= plain warp-specialized tcgen05 fp16 GEMM (GEMM1) =================
template <int EPI, int BN_, int STG>
__global__ __launch_bounds__(256)
void tc_gemm_plain(const __grid_constant__ CUtensorMap tmA,
                   const __grid_constant__ CUtensorMap tmB,
                   const float* __restrict__ bias, const float* __restrict__ res,
                   void* __restrict__ C, int N, int NC) {
#if TC_OK
    constexpr int CA = 128 * 128;
    constexpr int CB = BN_ * 128;
    constexpr int CBYTES = CA + CB;
    constexpr int TCOLS = BN_;

    extern __shared__ __align__(1024) char smem[];
    const int tid  = threadIdx.x;
    const int warp = tid >> 5;
    const int lane = tid & 31;

    uint32_t sb = (smem_u32(smem) + 1023u) & ~1023u;
    const uint32_t tmem_ptr_addr = sb;
    const uint32_t mb_all = sb + 8 + 16 * STG;
    uint32_t mb_full[STG], mb_done[STG], bufA[STG], bufB[STG];
    #pragma unroll
    for (int s = 0; s < STG; s++) {
        mb_full[s] = sb + 8 + 8 * s;
        mb_done[s] = sb + 8 + 8 * STG + 8 * s;
        bufA[s] = sb + 1024 + s * CBYTES;
        bufB[s] = bufA[s] + CA;
    }

    if (warp == 0) { TC_ALLOC(tmem_ptr_addr, TCOLS); TC_RELINQ(); }
    if (tid == 0) {
        #pragma unroll
        for (int s = 0; s < STG; s++) { mbar_init(mb_full[s], 1); mbar_init(mb_done[s], 1); }
        mbar_init(mb_all, 1);
    }
    __syncthreads();

    uint32_t tmem;
    asm volatile("ld.shared.b32 %0, [%1];" : "=r"(tmem) : "r"(tmem_ptr_addr));

    const int tile_m = blockIdx.y * 128;
    const int tile_n = blockIdx.x * BN_;

    if (warp == 1 && elect_one()) {
        uint32_t phd = 0;
        for (int j = 0; j < NC; j++) {
            const int s = j % STG;
            if (j >= STG) { mbar_wait(mb_done[s], (phd >> s) & 1); phd ^= 1u << s; }
            mbar_expect_tx(mb_full[s], CBYTES);
            tma_2d(bufA[s], &tmA, j * KE, tile_m, mb_full[s]);
            tma_2d(bufB[s], &tmB, j * KE, tile_n, mb_full[s]);
        }
    }
    if (warp == 0 && elect_one()) {
        uint64_t ad[STG], bd[STG];
        #pragma unroll
        for (int s = 0; s < STG; s++) {
            ad[s] = smem_desc_sw128(bufA[s]);
            bd[s] = smem_desc_sw128(bufB[s]);
        }
        uint32_t phf = 0;
        for (int kc = 0; kc < NC; kc++) {
            const int s = kc % STG;
            mbar_wait(mb_full[s], (phf >> s) & 1); phf ^= 1u << s;
            #pragma unroll
            for (int s2 = 0; s2 < 4; s2++) {
                const uint32_t en = (kc > 0 || s2 > 0) ? 1u : 0u;
                mma_f16_ss(tmem, ad[s] + 2 * s2, bd[s] + 2 * s2, idesc_f16(BN_, 128), en);
            }
            tc_commit(mb_done[s]);
        }
        tc_commit(mb_all);
        mbar_wait(mb_all, 0);
    }
    __syncthreads();
    TC_FENCE_AFTER();
    {
        const int half_ = warp >> 2;
        const uint32_t dbase = tmem + half_ * (BN_ / 2);
        const int row = tile_m + (warp & 3) * 32 + lane;
        const int col0 = tile_n + half_ * (BN_ / 2);
        #pragma unroll 1
        for (int cc = 0; cc < BN_ / 64; cc++) {
            uint32_t r[32];
            TC_LD_X32(r, dbase + cc * 32);
            TC_WAIT_LD();
            epi_write_chunk<EPI>(r, row, col0 + cc * 32, bias, res, C, N);
        }
    }
    __syncthreads();
    if (warp == 0) TC_DEALLOC(tmem, TCOLS);
#endif
}

// ================= cg2 pair GEMM: 512(M) x 256(N) per 2-CTA cluster =================
template <int EPI>
__global__ __launch_bounds__(256) __cluster_dims__(2, 1, 1)
void tc_gemm_cg2(const __grid_constant__ CUtensorMap tmA,
                 const __grid_constant__ CUtensorMap tmB,
                 const float* __restrict__ bias, const float* __restrict__ res,
                 void* __restrict__ C, int N, int NC) {
#if TC_OK
    constexpr int STG = 4;
    constexpr int CA = 2 * 128 * 128;          // 32 KB
    constexpr int CB = 128 * 128;              // 16 KB
    constexpr int CBYTES = CA + CB;            // 48 KB per CTA
    constexpr int PAIR_BYTES = 2 * CBYTES;     // 96 KB per pair per stage
    constexpr int TCOLS = 512;

    extern __shared__ __align__(1024) char smem[];
    const int tid  = threadIdx.x;
    const int warp = tid >> 5;
    const int lane = tid & 31;

    uint32_t sb = (smem_u32(smem) + 1023u) & ~1023u;
    const uint32_t tmem_ptr_addr = sb;
    const uint32_t mb_all = sb + 8 + 16 * STG;
    uint32_t mb_full[STG], mb_done[STG], bufA[STG], bufB[STG];
    #pragma unroll
    for (int s = 0; s < STG; s++) {
        mb_full[s] = sb + 8 + 8 * s;
        mb_done[s] = sb + 8 + 8 * STG + 8 * s;
        bufA[s] = sb + 1024 + s * CBYTES;
        bufB[s] = bufA[s] + CA;
    }

    if (warp == 0) { TC_ALLOC_CG2(tmem_ptr_addr, TCOLS); TC_RELINQ_CG2(); }
    if (tid == 0) {
        #pragma unroll
        for (int s = 0; s < STG; s++) { mbar_init(mb_full[s], 1); mbar_init(mb_done[s], 1); }
        mbar_init(mb_all, 1);
    }
    __syncthreads();
    CLUSTER_SYNC();

    uint32_t tmem;
    asm volatile("ld.shared.b32 %0, [%1];" : "=r"(tmem) : "r"(tmem_ptr_addr));

    const int rank  = (int)cluster_rank();
    const int tile_m = blockIdx.y * 512;
    const int tile_n = (blockIdx.x >> 1) * 256;

    if (warp == 1 && elect_one()) {
        uint32_t phd = 0;
        const int rowA0 = tile_m + rank * 128;
        const int rowA1 = tile_m + 256 + rank * 128;
        const int rowB  = tile_n + rank * 128;
        for (int j = 0; j < NC; j++) {
            const int s = j % STG;
            if (j >= STG) { mbar_wait(mb_done[s], (phd >> s) & 1); phd ^= 1u << s; }
            if (rank == 0) mbar_expect_tx(mb_full[s], PAIR_BYTES);
            tma_3d_cg2(bufA[s],         &tmA, j * KE, rowA0, mb_full[s]);
            tma_3d_cg2(bufA[s] + 16384, &tmA, j * KE, rowA1, mb_full[s]);
            tma_3d_cg2(bufB[s],         &tmB, j * KE, rowB,  mb_full[s]);
        }
    }
    if (rank == 0 && warp == 0 && elect_one()) {
        uint64_t adLo[STG], adHi[STG], bd[STG];
        #pragma unroll
        for (int s = 0; s < STG; s++) {
            adLo[s] = smem_desc_sw128(bufA[s]);
            adHi[s] = smem_desc_sw128(bufA[s] + 16384);
            bd[s]   = smem_desc_sw128(bufB[s]);
        }
        uint32_t phf = 0;
        for (int kc = 0; kc < NC; kc++) {
            const int s = kc % STG;
            mbar_wait(mb_full[s], (phf >> s) & 1); phf ^= 1u << s;
            #pragma unroll
            for (int s2 = 0; s2 < 4; s2++) {
                const uint32_t en = (kc > 0 || s2 > 0) ? 1u : 0u;
                mma_f16_ss_cg2(tmem,       adLo[s] + 2 * s2, bd[s] + 2 * s2,
                               idesc_f16(256, 256), en);
                mma_f16_ss_cg2(tmem + 256, adHi[s] + 2 * s2, bd[s] + 2 * s2,
                               idesc_f16(256, 256), en);
            }
            tc_commit_mc_cg2(mb_done[s], 0x3);
        }
        tc_commit_mc_cg2(mb_all, 0x3);
    }
    __syncthreads();
    mbar_wait(mb_all, 0);
    TC_FENCE_AFTER();

    {
        const int half_ = warp >> 2;
        const uint32_t dbase = tmem + half_ * 256;
        const int row = tile_m + half_ * 256 + rank * 128 + (warp & 3) * 32 + lane;
        #pragma unroll 1
        for (int cc = 0; cc < 8; cc++) {
            uint32_t r[32];
            TC_LD_X32(r, dbase + cc * 32);
            TC_WAIT_LD();
            epi_write_chunk<EPI>(r, row, tile_n + cc * 32, bias, res, C, N);
        }
    }
    __syncthreads();
    if (warp == 0) TC_DEALLOC_CG2(tmem, TCOLS);
    CLUSTER_SYNC();
#endif
}

// ================= vectorized transpose to fp16 (+pad rows) =================
// in[R][Cc] fp32 -> out[Cp][R] fp16, half2 stores. Requires R % 64 == 0.
__global__ void transpose_h2_kernel(const float* __restrict__ in, __half* __restrict__ out,
                                    int R, int Cc, int Cp) {
    __shared__ float tile[64][33];
    const int c0 = blockIdx.x * 32;          // input cols / output rows
    const int r0 = blockIdx.y * 64;          // input rows / output cols
    const int tx = threadIdx.x, ty = threadIdx.y;

    #pragma unroll
    for (int i = 0; i < 64; i += 8) {
        const int y = r0 + ty + i;
        const int x = c0 + tx;
        float v = 0.f;
        if (x < Cc && y < R) v = in[(size_t)y * Cc + x];
        tile[ty + i][tx] = v;
    }
    __syncthreads();
    #pragma unroll
    for (int i = 0; i < 32; i += 8) {
        const int oy = c0 + ty + i;
        const int ox = r0 + 2 * tx;
        if (oy < Cp) {
            __half2 v = __floats2half2_rn(tile[2 * tx][ty + i], tile[2 * tx + 1][ty + i]);
            *reinterpret_cast<__half2*>(&out[(size_t)oy * R + ox]) = v;
        }
    }
}

// ================= fp32 -> fp16 elementwise =================
__global__ void f2h_kernel(const float* __restrict__ in, __half* __restrict__ out, int n2) {
    int i = blockIdx.x * blockDim.x + threadIdx.x;
    if (i < n2) {
        float2 v = reinterpret_cast<const float2*>(in)[i];
        reinterpret_cast<__half2*>(out)[i] = __floats2half2_rn(v.x, v.y);
    }
}

// ================= t-tiled softmax + causal dynamic conv + LayerNorm =================
// reads fp16 x (half the traffic); accumulates in fp32
__global__ __launch_bounds__(512)
void dynconv_ln_kernel(const __half* __restrict__ xh, const float* __restrict__ wraw,
                       const float* __restrict__ b_lin,
                       const float* __restrict__ ln_g, const float* __restrict__ ln_b,
                       float* __restrict__ y, __half* __restrict__ yh) {
    extern __shared__ float sm[];
    float* xs  = sm;
    float* ws  = xs + XS_ROWS * C_DIM;
    float* red = ws + TT * (H_DIM * K_TAPS);

    const int t0  = blockIdx.x * TT;
    const int b   = blockIdx.y;
    const int tid = threadIdx.x;

    {
        // load 8 halfs (16B) per iteration, expand to fp32 in smem
        const int total8 = XS_ROWS * (C_DIM / 8);
        for (int i = tid; i < total8; i += 512) {
            const int r = i / (C_DIM / 8);
            const int cc = i % (C_DIM / 8);
            const int t = t0 - HALO + r;
            float4 lo = make_float4(0.f, 0.f, 0.f, 0.f);
            float4 hi = lo;
            if (t >= 0) {
                const uint4 raw = reinterpret_cast<const uint4*>(
                    &xh[((size_t)(t * B_DIM + b)) * C_DIM])[cc];
                __half2 h0 = *reinterpret_cast<const __half2*>(&raw.x);
                __half2 h1 = *reinterpret_cast<const __half2*>(&raw.y);
                __half2 h2 = *reinterpret_cast<const __half2*>(&raw.z);
                __half2 h3 = *reinterpret_cast<const __half2*>(&raw.w);
                float2 f0 = __half22float2(h0), f1 = __half22float2(h1);
                float2 f2 = __half22float2(h2), f3 = __half22float2(h3);
                lo = make_float4(f0.x, f0.y, f1.x, f1.y);
                hi = make_float4(f2.x, f2.y, f3.x, f3.y);
            }
            reinterpret_cast<float4*>(&xs[r * C_DIM + cc * 8])[0] = lo;
            reinterpret_cast<float4*>(&xs[r * C_DIM + cc * 8])[1] = hi;
        }
    }
    for (int i = tid; i < TT * (H_DIM * K_TAPS); i += 512) {
        const int lt = i / (H_DIM * K_TAPS);
        const int j  = i % (H_DIM * K_TAPS);
        ws[i] = wraw[(size_t)((t0 + lt) * B_DIM + b) * NPAD + j] + b_lin[j];
    }
    __syncthreads();

    {
        const int lt = tid >> 4;
        const int hd = tid & 15;
        float* p = ws + lt * (H_DIM * K_TAPS) + hd * K_TAPS;
        float mx = -1e30f;
        #pragma unroll
        for (int k = 0; k < K_TAPS; k++) mx = fmaxf(mx, p[k]);
        float e[K_TAPS]; float s = 0.f;
        #pragma unroll
        for (int k = 0; k < K_TAPS; k++) { e[k] = expf(p[k] - mx); s += e[k]; }
        const float inv = 1.0f / s;
        #pragma unroll
        for (int k = 0; k < K_TAPS; k++) p[k] = e[k] * inv;
    }
    __syncthreads();

    const int c0 = tid * 2;
    const int h  = c0 >> 6;
    const float g0 = ln_g[c0], g1 = ln_g[c0 + 1];
    const float bb0 = ln_b[c0], bb1 = ln_b[c0 + 1];
    const int wid = tid >> 5, lane = tid & 31;

    for (int lt = 0; lt < TT; lt++) {
        const float* wrow = ws + lt * (H_DIM * K_TAPS) + h * K_TAPS;
        float a0 = 0.f, a1 = 0.f;
        #pragma unroll
        for (int k = 0; k < K_TAPS; k++) {
            const float wgt = wrow[k];
            const float2 xv = *reinterpret_cast<const float2*>(&xs[(lt + k) * C_DIM + c0]);
            a0 += wgt * xv.x;
            a1 += wgt * xv.y;
        }
        float s1 = a0 + a1;
        float s2 = a0 * a0 + a1 * a1;
        #pragma unroll
        for (int off = 16; off > 0; off >>= 1) {
            s1 += __shfl_down_sync(0xFFFFFFFFu, s1, off);
            s2 += __shfl_down_sync(0xFFFFFFFFu, s2, off);
        }
        if (lane == 0) { red[wid] = s1; red[16 + wid] = s2; }
        __syncthreads();
        if (tid == 0) {
            float sa = 0.f, sb2 = 0.f;
            #pragma unroll
            for (int i = 0; i < 16; i++) { sa += red[i]; sb2 += red[16 + i]; }
            const float mu = sa * (1.0f / C_DIM);
            const float var = sb2 * (1.0f / C_DIM) - mu * mu;
            red[32] = mu;
            red[33] = rsqrtf(var + LN_EPS);
        }
        __syncthreads();
        const float mu = red[32], rstd = red[33];
        const float v0 = (a0 - mu) * rstd * g0 + bb0;
        const float v1 = (a1 - mu) * rstd * g1 + bb1;
        const size_t base = (size_t)((t0 + lt) * B_DIM + b) * C_DIM + c0;
        *reinterpret_cast<float2*>(&y[base]) = make_float2(v0, v1);
        *reinterpret_cast<__half2*>(&yh[base]) = __floats2half2_rn(v0, v1);
    }
}

// ================= host side =================
typedef CUresult (*PFN_encodeTiled)(CUtensorMap*, CUtensorMapDataType, cuuint32_t, void*,
                                    const cuuint64_t*, const cuuint64_t*, const cuuint32_t*,
                                    const cuuint32_t*, CUtensorMapInterleave, CUtensorMapSwizzle,
                                    CUtensorMapL2promotion, CUtensorMapFloatOOBfill);

static PFN_encodeTiled get_encoder() {
    static PFN_encodeTiled fn = nullptr;
    if (!fn) {
        void* h = dlopen("libcuda.so.1", RTLD_LAZY | RTLD_GLOBAL);
        if (!h) h = dlopen("libcuda.so", RTLD_LAZY | RTLD_GLOBAL);
        if (h) fn = (PFN_encodeTiled)dlsym(h, "cuTensorMapEncodeTiled");
    }
    return fn;
}

static void make_map_h2(CUtensorMap* m, const void* ptr, uint64_t d0, uint64_t d1, uint32_t b1) {
    cuuint64_t dims[2] = { d0, d1 };
    cuuint64_t strides[1] = { d0 * 2 };
    cuuint32_t box[2] = { KE, b1 };
    cuuint32_t es[2] = { 1, 1 };
    PFN_encodeTiled enc = get_encoder();
    if (enc)
        enc(m, CU_TENSOR_MAP_DATA_TYPE_FLOAT16, 2, (void*)ptr, dims, strides, box, es,
            CU_TENSOR_MAP_INTERLEAVE_NONE, CU_TENSOR_MAP_SWIZZLE_128B,
            CU_TENSOR_MAP_L2_PROMOTION_L2_128B, CU_TENSOR_MAP_FLOAT_OOB_FILL_NONE);
}
static void make_map_h3(CUtensorMap* m, const void* ptr, uint64_t d0, uint64_t d1) {
    cuuint64_t dims[3] = { d0, d1, 1 };
    cuuint64_t strides[2] = { d0 * 2, d0 * d1 * 2 };
    cuuint32_t box[3] = { KE, 128, 1 };
    cuuint32_t es[3] = { 1, 1, 1 };
    PFN_encodeTiled enc = get_encoder();
    if (enc)
        enc(m, CU_TENSOR_MAP_DATA_TYPE_FLOAT16, 3, (void*)ptr, dims, strides, box, es,
            CU_TENSOR_MAP_INTERLEAVE_NONE, CU_TENSOR_MAP_SWIZZLE_128B,
            CU_TENSOR_MAP_L2_PROMOTION_L2_128B, CU_TENSOR_MAP_FLOAT_OOB_FILL_NONE);
}

extern "C" void kernel_launch(void* const* d_in, const int* in_sizes, int n_in,
                              void* d_out, int out_size) {
    const float* x     = (const float*)d_in[0];
    const float* w_lin = (const float*)d_in[1];
    const float* b_lin = (const float*)d_in[2];
    const float* ln_g  = (const float*)d_in[3];
    const float* ln_b  = (const float*)d_in[4];
    const float* fc1_w = (const float*)d_in[5];
    const float* fc1_b = (const float*)d_in[6];
    const float* fc2_w = (const float*)d_in[7];
    const float* fc2_b = (const float*)d_in[8];
    float* out = (float*)d_out;

    __half *xh, *wlinT, *fc1wT, *fc2wT, *yh, *h;
    float *wraw, *y;
    cudaGetSymbolAddress((void**)&xh, g_xh);
    cudaGetSymbolAddress((void**)&wlinT, g_wlinT);
    cudaGetSymbolAddress((void**)&fc1wT, g_fc1wT);
    cudaGetSymbolAddress((void**)&fc2wT, g_fc2wT);
    cudaGetSymbolAddress((void**)&wraw, g_wraw);
    cudaGetSymbolAddress((void**)&y, g_y);
    cudaGetSymbolAddress((void**)&yh, g_yh);
    cudaGetSymbolAddress((void**)&h, g_h);

    const int smem_g1  = 1024 + 5 * (128 * 128 + 128 * 128);
    const int smem_cg2 = 1024 + 4 * (2 * 128 * 128 + 128 * 128);
    cudaFuncSetAttribute((const void*)tc_gemm_plain<0, 128, 5>,
                         cudaFuncAttributeMaxDynamicSharedMemorySize, smem_g1);
    cudaFuncSetAttribute((const void*)tc_gemm_cg2<1>,
                         cudaFuncAttributeMaxDynamicSharedMemorySize, smem_cg2);
    cudaFuncSetAttribute((const void*)tc_gemm_cg2<2>,
                         cudaFuncAttributeMaxDynamicSharedMemorySize, smem_cg2);
    cudaFuncSetAttribute((const void*)dynconv_ln_kernel,
                         cudaFuncAttributeMaxDynamicSharedMemorySize, DC_SMEM);

    CUtensorMap mA1{}, mB1{}, mA2{}, mB2{}, mA3{}, mB3{};
    make_map_h2(&mA1, xh,    C_DIM, M_DIM, 128);
    make_map_h2(&mB1, wlinT, C_DIM, NPAD,  128);
    make_map_h3(&mA2, yh,    C_DIM, M_DIM);
    make_map_h3(&mB2, fc1wT, C_DIM, F_DIM);
    make_map_h3(&mA3, h,     F_DIM, M_DIM);
    make_map_h3(&mB3, fc2wT, F_DIM, C_DIM);

    dim3 tb(32, 8);
    // Launch order chosen so launch #6 (ncu -s 5 -c 1) is fc1 (tc_gemm_cg2<1>).
    // 1) x -> fp16
    f2h_kernel<<<(M_DIM * C_DIM / 2 + 255) / 256, 256>>>(x, xh, M_DIM * C_DIM / 2);
    // 2) w_lin^T fp16 (R=C_DIM=1024)
    transpose_h2_kernel<<<dim3(NPAD / 32, C_DIM / 64), tb>>>(w_lin, wlinT, C_DIM, H_DIM * K_TAPS, NPAD);
    // 3) conv-weight projection
    tc_gemm_plain<0, 128, 5><<<dim3(NPAD / 128, M_DIM / 128), 256, smem_g1>>>(
        mA1, mB1, nullptr, nullptr, wraw, NPAD, C_DIM / KE);
    // 4) softmax + conv + LN (fp16 x input)
    dynconv_ln_kernel<<<dim3(T_DIM / TT, B_DIM), 512, DC_SMEM>>>(
        xh, wraw, b_lin, ln_g, ln_b, y, yh);
    // 5) fc1_w^T fp16 (R=C_DIM=1024)
    transpose_h2_kernel<<<dim3(F_DIM / 32, C_DIM / 64), tb>>>(fc1_w, fc1wT, C_DIM, F_DIM, F_DIM);
    // 6) fc1 + ReLU -> fp16 h       <-- profiled launch
    tc_gemm_cg2<1><<<dim3(2 * (F_DIM / 256), M_DIM / 512), 256, smem_cg2>>>(
        mA2, mB2, fc1_b, nullptr, h, F_DIM, C_DIM / KE);
    // 7) fc2_w^T fp16 (R=F_DIM=4096)
    transpose_h2_kernel<<<dim3(C_DIM / 32, F_DIM / 64), tb>>>(fc2_w, fc2wT, F_DIM, C_DIM, C_DIM);
    // 8) fc2 + bias + residual -> fp32 out
    tc_gemm_cg2<2><<<dim3(2 * (C_DIM / 256), M_DIM / 512), 256, smem_cg2>>>(
        mA3, mB3, fc2_b, y, out, C_DIM, F_DIM / KE);
}

// round 11
// speedup vs baseline: 1.8653x; 1.0910x over previous
#include <cuda_runtime.h>
#include <cuda.h>
#include <cuda_fp16.h>
#include <dlfcn.h>
#include <math.h>
#include <stdint.h>

// ---------------- problem constants ----------------
#define T_DIM 1024
#define B_DIM 8
#define C_DIM 1024
#define F_DIM 4096
#define H_DIM 16
#define K_TAPS 15
#define M_DIM (T_DIM * B_DIM)   // 8192
#define NPAD 256
#define LN_EPS 1e-5f

#define KE 64                   // fp16 elements per k-chunk (128 bytes per row)

// dynconv tiling
#define TT 32
#define HALO (K_TAPS - 1)
#define XS_ROWS (TT + HALO)     // 46
// smem layout (bytes): xs fp16 | ws fp32 | ln_g | ln_b
#define DC_XS_BYTES (XS_ROWS * C_DIM * 2)            // 94208
#define DC_WS_OFF   DC_XS_BYTES
#define DC_WS_BYTES (TT * H_DIM * K_TAPS * 4)        // 30720
#define DC_G_OFF    (DC_WS_OFF + DC_WS_BYTES)
#define DC_B_OFF    (DC_G_OFF + C_DIM * 4)
#define DC_SMEM     (DC_B_OFF + C_DIM * 4)           // ~133 KB

// arch-specific feature gate (tcgen05 only on the sm_103a pass)
#if defined(__CUDA_ARCH_FEAT_SM103_ALL) || defined(__CUDA_ARCH_FEAT_SM100_ALL) || \
    (defined(__CUDA_ARCH_SPECIFIC__) && (__CUDA_ARCH_SPECIFIC__ >= 1000)) ||      \
    (defined(__CUDA_ARCH_FAMILY_SPECIFIC__) && (__CUDA_ARCH_FAMILY_SPECIFIC__ >= 1000))
#define TC_OK 1
#else
#define TC_OK 0
#endif

// ---------------- scratch (device globals) ----------------
__device__ __half g_xh[(size_t)M_DIM * C_DIM];
__device__ __half g_wlinT[NPAD * C_DIM];
__device__ __half g_fc1wT[(size_t)F_DIM * C_DIM];
__device__ __half g_fc2wT[(size_t)C_DIM * F_DIM];
__device__ float  g_wraw[(size_t)M_DIM * NPAD];
__device__ float  g_y[(size_t)M_DIM * C_DIM];
__device__ __half g_yh[(size_t)M_DIM * C_DIM];
__device__ __half g_h[(size_t)M_DIM * F_DIM];

// ---------------- helpers ----------------
__device__ __forceinline__ uint32_t smem_u32(const void* p) {
    uint32_t a;
    asm("{ .reg .u64 t; cvta.to.shared.u64 t, %1; cvt.u32.u64 %0, t; }" : "=r"(a) : "l"(p));
    return a;
}
__device__ __forceinline__ uint32_t elect_one() {
    uint32_t p;
    asm volatile("{ .reg .pred p; elect.sync _|p, 0xFFFFFFFF; selp.b32 %0, 1, 0, p; }" : "=r"(p));
    return p;
}
__device__ __forceinline__ void mbar_init(uint32_t a, uint32_t cnt) {
    asm volatile("mbarrier.init.shared.b64 [%0], %1;" :: "r"(a), "r"(cnt) : "memory");
}
__device__ __forceinline__ void mbar_expect_tx(uint32_t a, uint32_t bytes) {
    asm volatile("mbarrier.arrive.expect_tx.shared.b64 _, [%0], %1;" :: "r"(a), "r"(bytes) : "memory");
}
__device__ __forceinline__ void mbar_wait(uint32_t a, uint32_t parity) {
    uint32_t done;
    asm volatile(
        "{ .reg .pred p;\n\t"
        "mbarrier.try_wait.parity.acquire.cta.shared::cta.b64 p, [%1], %2;\n\t"
        "selp.b32 %0, 1, 0, p; }" : "=r"(done) : "r"(a), "r"(parity) : "memory");
    if (!done) {
        asm volatile(
            "{ .reg .pred P1;\n\t"
            "WL_%=:\n\t"
            "mbarrier.try_wait.parity.acquire.cta.shared::cta.b64 P1, [%0], %1, 0x989680;\n\t"
            "@P1 bra.uni WD_%=;\n\t"
            "bra.uni WL_%=;\n\t"
            "WD_%=: }" :: "r"(a), "r"(parity) : "memory");
    }
}
#if TC_OK
__device__ __forceinline__ uint32_t cluster_rank() {
    uint32_t r;
    asm("mov.u32 %0, %%cluster_ctarank;" : "=r"(r));
    return r;
}
#define CLUSTER_SYNC() do { \
    asm volatile("barrier.cluster.arrive.aligned;" ::: "memory"); \
    asm volatile("barrier.cluster.wait.aligned;" ::: "memory");   \
} while (0)

__device__ __forceinline__ void tma_2d(uint32_t dst, const void* map, int cx, int cy, uint32_t mbar) {
    asm volatile(
        "cp.async.bulk.tensor.2d.shared::cta.global.tile.mbarrier::complete_tx::bytes "
        "[%0], [%1, {%2, %3}], [%4];"
        :: "r"(dst), "l"(map), "r"(cx), "r"(cy), "r"(mbar) : "memory");
}
__device__ __forceinline__ void tma_3d_cg2(uint32_t dst, const void* map, int cx, int cy,
                                           uint32_t mbar) {
    asm volatile(
        "{\n\t"
        ".reg .b32 leaderBar;\n\t"
        "and.b32 leaderBar, %4, 0xFEFFFFFF;\n\t"
        "cp.async.bulk.tensor.3d.cta_group::2.shared::cluster.global"
        ".tile.mbarrier::complete_tx::bytes "
        "[%0], [%1, {%2, %3, %5}], [leaderBar];\n\t"
        "}"
        :: "r"(dst), "l"(map), "r"(cx), "r"(cy), "r"(mbar), "r"(0) : "memory");
}
__device__ __forceinline__ void mma_f16_ss(uint32_t d, uint64_t adesc, uint64_t bdesc,
                                           uint32_t idesc, uint32_t en) {
    asm volatile(
        "{ .reg .pred p;\n\t"
        "setp.ne.u32 p, %4, 0;\n\t"
        "tcgen05.mma.cta_group::1.kind::f16 [%0], %1, %2, %3, p; }"
        :: "r"(d), "l"(adesc), "l"(bdesc), "r"(idesc), "r"(en) : "memory");
}
__device__ __forceinline__ void mma_f16_ss_cg2(uint32_t d, uint64_t adesc, uint64_t bdesc,
                                               uint32_t idesc, uint32_t en) {
    asm volatile(
        "{ .reg .pred p;\n\t"
        "setp.ne.u32 p, %5, 0;\n\t"
        "tcgen05.mma.cta_group::2.kind::f16 [%0], %1, %2, %3, "
        "{%4, %4, %4, %4, %4, %4, %4, %4}, p; }"
        :: "r"(d), "l"(adesc), "l"(bdesc), "r"(idesc), "r"(0u), "r"(en) : "memory");
}
__device__ __forceinline__ void tc_commit(uint32_t mbar) {
    asm volatile(
        "tcgen05.commit.cta_group::1.mbarrier::arrive::one.shared::cluster.b64 [%0];"
        :: "r"(mbar) : "memory");
}
__device__ __forceinline__ void tc_commit_mc_cg2(uint32_t mbar, uint16_t mask) {
    asm volatile(
        "tcgen05.commit.cta_group::2.mbarrier::arrive::one.shared::cluster.multicast::cluster.b64 "
        "[%0], %1;"
        :: "r"(mbar), "h"(mask) : "memory");
}
#define TC_ALLOC(smem_addr, ncols) \
    asm volatile("tcgen05.alloc.cta_group::1.sync.aligned.shared::cta.b32 [%0], %1;" \
                 :: "r"(smem_addr), "r"(ncols) : "memory")
#define TC_RELINQ() \
    asm volatile("tcgen05.relinquish_alloc_permit.cta_group::1.sync.aligned;")
#define TC_DEALLOC(tmem, ncols) \
    asm volatile("tcgen05.dealloc.cta_group::1.sync.aligned.b32 %0, %1;" :: "r"(tmem), "r"(ncols))
#define TC_ALLOC_CG2(smem_addr, ncols) \
    asm volatile("tcgen05.alloc.cta_group::2.sync.aligned.shared::cta.b32 [%0], %1;" \
                 :: "r"(smem_addr), "r"(ncols) : "memory")
#define TC_RELINQ_CG2() \
    asm volatile("tcgen05.relinquish_alloc_permit.cta_group::2.sync.aligned;")
#define TC_DEALLOC_CG2(tmem, ncols) \
    asm volatile("tcgen05.dealloc.cta_group::2.sync.aligned.b32 %0, %1;" :: "r"(tmem), "r"(ncols))
#define TC_FENCE_AFTER()  asm volatile("tcgen05.fence::after_thread_sync;" ::: "memory")
#define TC_WAIT_LD()      asm volatile("tcgen05.wait::ld.sync.aligned;" ::: "memory")
#define TC_LD_X32(r, addr) \
    asm volatile("tcgen05.ld.sync.aligned.32x32b.x32.b32 " \
        "{%0, %1, %2, %3, %4, %5, %6, %7, %8, %9, %10, %11, %12, %13, %14, %15, " \
        " %16, %17, %18, %19, %20, %21, %22, %23, %24, %25, %26, %27, %28, %29, %30, %31}, [%32];" \
        : "=r"((r)[0]), "=r"((r)[1]), "=r"((r)[2]), "=r"((r)[3]), \
          "=r"((r)[4]), "=r"((r)[5]), "=r"((r)[6]), "=r"((r)[7]), \
          "=r"((r)[8]), "=r"((r)[9]), "=r"((r)[10]), "=r"((r)[11]), \
          "=r"((r)[12]), "=r"((r)[13]), "=r"((r)[14]), "=r"((r)[15]), \
          "=r"((r)[16]), "=r"((r)[17]), "=r"((r)[18]), "=r"((r)[19]), \
          "=r"((r)[20]), "=r"((r)[21]), "=r"((r)[22]), "=r"((r)[23]), \
          "=r"((r)[24]), "=r"((r)[25]), "=r"((r)[26]), "=r"((r)[27]), \
          "=r"((r)[28]), "=r"((r)[29]), "=r"((r)[30]), "=r"((r)[31]) \
        : "r"(addr))

__device__ __forceinline__ uint64_t smem_desc_sw128(uint32_t addr) {
    return ((uint64_t)2 << 61) | ((uint64_t)1 << 46) | ((uint64_t)64 << 32) |
           ((uint64_t)1 << 16) | (((uint64_t)addr >> 4) & 0x3FFF);
}
__device__ __forceinline__ constexpr uint32_t idesc_f16(int bn, int m) {
    return (1u << 4) | ((uint32_t)(bn / 8) << 17) | ((uint32_t)(m / 16) << 24);
}
#endif  // TC_OK

#if TC_OK
template <int EPI>
__device__ __forceinline__ void epi_write_chunk(const uint32_t* r, int row, int colbase,
                                                const float* __restrict__ bias,
                                                const float* __restrict__ res,
                                                void* __restrict__ Cv, int N) {
    if (EPI == 1) {
        __half* Ch = (__half*)Cv;
        __half2* dst = reinterpret_cast<__half2*>(&Ch[(size_t)row * N + colbase]);
        #pragma unroll
        for (int j = 0; j < 32; j += 2) {
            float v0 = fmaxf(__uint_as_float(r[j + 0]) + bias[colbase + j + 0], 0.f);
            float v1 = fmaxf(__uint_as_float(r[j + 1]) + bias[colbase + j + 1], 0.f);
            dst[j / 2] = __floats2half2_rn(v0, v1);
        }
    } else {
        float* C = (float*)Cv;
        float4* dst = reinterpret_cast<float4*>(&C[(size_t)row * N + colbase]);
        #pragma unroll
        for (int j = 0; j < 32; j += 4) {
            float4 v;
            v.x = __uint_as_float(r[j + 0]);
            v.y = __uint_as_float(r[j + 1]);
            v.z = __uint_as_float(r[j + 2]);
            v.w = __uint_as_float(r[j + 3]);
            if (EPI == 2) {
                v.x += bias[colbase + j + 0]; v.y += bias[colbase + j + 1];
                v.z += bias[colbase + j + 2]; v.w += bias[colbase + j + 3];
                float4 rv = *reinterpret_cast<const float4*>(&res[(size_t)row * N + colbase + j]);
                v.x += rv.x; v.y += rv.y; v.z += rv.z; v.w += rv.w;
            }
            dst[j / 4] = v;
        }
    }
}
#endif

// ================= plain warp-specialized tcgen05 fp16 GEMM (GEMM1) =================
template <int EPI, int BN_, int STG>
__global__ __launch_bounds__(256)
void tc_gemm_plain(const __grid_constant__ CUtensorMap tmA,
                   const __grid_constant__ CUtensorMap tmB,
                   const float* __restrict__ bias, const float* __restrict__ res,
                   void* __restrict__ C, int N, int NC) {
#if TC_OK
    constexpr int CA = 128 * 128;
    constexpr int CB = BN_ * 128;
    constexpr int CBYTES = CA + CB;
    constexpr int TCOLS = BN_;

    extern __shared__ __align__(1024) char smem[];
    const int tid  = threadIdx.x;
    const int warp = tid >> 5;
    const int lane = tid & 31;

    uint32_t sb = (smem_u32(smem) + 1023u) & ~1023u;
    const uint32_t tmem_ptr_addr = sb;
    const uint32_t mb_all = sb + 8 + 16 * STG;
    uint32_t mb_full[STG], mb_done[STG], bufA[STG], bufB[STG];
    #pragma unroll
    for (int s = 0; s < STG; s++) {
        mb_full[s] = sb + 8 + 8 * s;
        mb_done[s] = sb + 8 + 8 * STG + 8 * s;
        bufA[s] = sb + 1024 + s * CBYTES;
        bufB[s] = bufA[s] + CA;
    }

    if (warp == 0) { TC_ALLOC(tmem_ptr_addr, TCOLS); TC_RELINQ(); }
    if (tid == 0) {
        #pragma unroll
        for (int s = 0; s < STG; s++) { mbar_init(mb_full[s], 1); mbar_init(mb_done[s], 1); }
        mbar_init(mb_all, 1);
    }
    __syncthreads();

    uint32_t tmem;
    asm volatile("ld.shared.b32 %0, [%1];" : "=r"(tmem) : "r"(tmem_ptr_addr));

    const int tile_m = blockIdx.y * 128;
    const int tile_n = blockIdx.x * BN_;

    if (warp == 1 && elect_one()) {
        uint32_t phd = 0;
        for (int j = 0; j < NC; j++) {
            const int s = j % STG;
            if (j >= STG) { mbar_wait(mb_done[s], (phd >> s) & 1); phd ^= 1u << s; }
            mbar_expect_tx(mb_full[s], CBYTES);
            tma_2d(bufA[s], &tmA, j * KE, tile_m, mb_full[s]);
            tma_2d(bufB[s], &tmB, j * KE, tile_n, mb_full[s]);
        }
    }
    if (warp == 0 && elect_one()) {
        uint64_t ad[STG], bd[STG];
        #pragma unroll
        for (int s = 0; s < STG; s++) {
            ad[s] = smem_desc_sw128(bufA[s]);
            bd[s] = smem_desc_sw128(bufB[s]);
        }
        uint32_t phf = 0;
        for (int kc = 0; kc < NC; kc++) {
            const int s = kc % STG;
            mbar_wait(mb_full[s], (phf >> s) & 1); phf ^= 1u << s;
            #pragma unroll
            for (int s2 = 0; s2 < 4; s2++) {
                const uint32_t en = (kc > 0 || s2 > 0) ? 1u : 0u;
                mma_f16_ss(tmem, ad[s] + 2 * s2, bd[s] + 2 * s2, idesc_f16(BN_, 128), en);
            }
            tc_commit(mb_done[s]);
        }
        tc_commit(mb_all);
        mbar_wait(mb_all, 0);
    }
    __syncthreads();
    TC_FENCE_AFTER();
    {
        const int half_ = warp >> 2;
        const uint32_t dbase = tmem + half_ * (BN_ / 2);
        const int row = tile_m + (warp & 3) * 32 + lane;
        const int col0 = tile_n + half_ * (BN_ / 2);
        #pragma unroll 1
        for (int cc = 0; cc < BN_ / 64; cc++) {
            uint32_t r[32];
            TC_LD_X32(r, dbase + cc * 32);
            TC_WAIT_LD();
            epi_write_chunk<EPI>(r, row, col0 + cc * 32, bias, res, C, N);
        }
    }
    __syncthreads();
    if (warp == 0) TC_DEALLOC(tmem, TCOLS);
#endif
}

// ================= cg2 pair GEMM: 512(M) x 256(N) per 2-CTA cluster =================
template <int EPI>
__global__ __launch_bounds__(256) __cluster_dims__(2, 1, 1)
void tc_gemm_cg2(const __grid_constant__ CUtensorMap tmA,
                 const __grid_constant__ CUtensorMap tmB,
                 const float* __restrict__ bias, const float* __restrict__ res,
                 void* __restrict__ C, int N, int NC) {
#if TC_OK
    constexpr int STG = 4;
    constexpr int CA = 2 * 128 * 128;
    constexpr int CB = 128 * 128;
    constexpr int CBYTES = CA + CB;
    constexpr int PAIR_BYTES = 2 * CBYTES;
    constexpr int TCOLS = 512;

    extern __shared__ __align__(1024) char smem[];
    const int tid  = threadIdx.x;
    const int warp = tid >> 5;
    const int lane = tid & 31;

    uint32_t sb = (smem_u32(smem) + 1023u) & ~1023u;
    const uint32_t tmem_ptr_addr = sb;
    const uint32_t mb_all = sb + 8 + 16 * STG;
    uint32_t mb_full[STG], mb_done[STG], bufA[STG], bufB[STG];
    #pragma unroll
    for (int s = 0; s < STG; s++) {
        mb_full[s] = sb + 8 + 8 * s;
        mb_done[s] = sb + 8 + 8 * STG + 8 * s;
        bufA[s] = sb + 1024 + s * CBYTES;
        bufB[s] = bufA[s] + CA;
    }

    if (warp == 0) { TC_ALLOC_CG2(tmem_ptr_addr, TCOLS); TC_RELINQ_CG2(); }
    if (tid == 0) {
        #pragma unroll
        for (int s = 0; s < STG; s++) { mbar_init(mb_full[s], 1); mbar_init(mb_done[s], 1); }
        mbar_init(mb_all, 1);
    }
    __syncthreads();
    CLUSTER_SYNC();

    uint32_t tmem;
    asm volatile("ld.shared.b32 %0, [%1];" : "=r"(tmem) : "r"(tmem_ptr_addr));

    const int rank  = (int)cluster_rank();
    const int tile_m = blockIdx.y * 512;
    const int tile_n = (blockIdx.x >> 1) * 256;

    if (warp == 1 && elect_one()) {
        uint32_t phd = 0;
        const int rowA0 = tile_m + rank * 128;
        const int rowA1 = tile_m + 256 + rank * 128;
        const int rowB  = tile_n + rank * 128;
        for (int j = 0; j < NC; j++) {
            const int s = j % STG;
            if (j >= STG) { mbar_wait(mb_done[s], (phd >> s) & 1); phd ^= 1u << s; }
            if (rank == 0) mbar_expect_tx(mb_full[s], PAIR_BYTES);
            tma_3d_cg2(bufA[s],         &tmA, j * KE, rowA0, mb_full[s]);
            tma_3d_cg2(bufA[s] + 16384, &tmA, j * KE, rowA1, mb_full[s]);
            tma_3d_cg2(bufB[s],         &tmB, j * KE, rowB,  mb_full[s]);
        }
    }
    if (rank == 0 && warp == 0 && elect_one()) {
        uint64_t adLo[STG], adHi[STG], bd[STG];
        #pragma unroll
        for (int s = 0; s < STG; s++) {
            adLo[s] = smem_desc_sw128(bufA[s]);
            adHi[s] = smem_desc_sw128(bufA[s] + 16384);
            bd[s]   = smem_desc_sw128(bufB[s]);
        }
        uint32_t phf = 0;
        for (int kc = 0; kc < NC; kc++) {
            const int s = kc % STG;
            mbar_wait(mb_full[s], (phf >> s) & 1); phf ^= 1u << s;
            #pragma unroll
            for (int s2 = 0; s2 < 4; s2++) {
                const uint32_t en = (kc > 0 || s2 > 0) ? 1u : 0u;
                mma_f16_ss_cg2(tmem,       adLo[s] + 2 * s2, bd[s] + 2 * s2,
                               idesc_f16(256, 256), en);
                mma_f16_ss_cg2(tmem + 256, adHi[s] + 2 * s2, bd[s] + 2 * s2,
                               idesc_f16(256, 256), en);
            }
            tc_commit_mc_cg2(mb_done[s], 0x3);
        }
        tc_commit_mc_cg2(mb_all, 0x3);
    }
    __syncthreads();
    mbar_wait(mb_all, 0);
    TC_FENCE_AFTER();

    {
        const int half_ = warp >> 2;
        const uint32_t dbase = tmem + half_ * 256;
        const int row = tile_m + half_ * 256 + rank * 128 + (warp & 3) * 32 + lane;
        #pragma unroll 1
        for (int cc = 0; cc < 8; cc++) {
            uint32_t r[32];
            TC_LD_X32(r, dbase + cc * 32);
            TC_WAIT_LD();
            epi_write_chunk<EPI>(r, row, tile_n + cc * 32, bias, res, C, N);
        }
    }
    __syncthreads();
    if (warp == 0) TC_DEALLOC_CG2(tmem, TCOLS);
    CLUSTER_SYNC();
#endif
}

// ================= vectorized transpose to fp16 (+pad rows) =================
__global__ void transpose_h2_kernel(const float* __restrict__ in, __half* __restrict__ out,
                                    int R, int Cc, int Cp) {
    __shared__ float tile[64][33];
    const int c0 = blockIdx.x * 32;
    const int r0 = blockIdx.y * 64;
    const int tx = threadIdx.x, ty = threadIdx.y;

    #pragma unroll
    for (int i = 0; i < 64; i += 8) {
        const int y = r0 + ty + i;
        const int x = c0 + tx;
        float v = 0.f;
        if (x < Cc && y < R) v = in[(size_t)y * Cc + x];
        tile[ty + i][tx] = v;
    }
    __syncthreads();
    #pragma unroll
    for (int i = 0; i < 32; i += 8) {
        const int oy = c0 + ty + i;
        const int ox = r0 + 2 * tx;
        if (oy < Cp) {
            __half2 v = __floats2half2_rn(tile[2 * tx][ty + i], tile[2 * tx + 1][ty + i]);
            *reinterpret_cast<__half2*>(&out[(size_t)oy * R + ox]) = v;
        }
    }
}

// ================= fp32 -> fp16 elementwise =================
__global__ void f2h_kernel(const float* __restrict__ in, __half* __restrict__ out, int n2) {
    int i = blockIdx.x * blockDim.x + threadIdx.x;
    if (i < n2) {
        float2 v = reinterpret_cast<const float2*>(in)[i];
        reinterpret_cast<__half2*>(out)[i] = __floats2half2_rn(v.x, v.y);
    }
}

// ================= warp-per-timestep softmax + causal conv + LayerNorm =================
// 16 warps; warp w owns lt = w, w+16. Lane handles channel pairs c = 2*lane + 64*j
// (j = 0..15, head h = j). NO block barriers in the main loop; LN stats via shfl_xor.
// x tile staged in smem as fp16 (half2 loads).
__global__ __launch_bounds__(512)
void dynconv_ln_kernel(const __half* __restrict__ xh, const float* __restrict__ wraw,
                       const float* __restrict__ b_lin,
                       const float* __restrict__ ln_g, const float* __restrict__ ln_b,
                       float* __restrict__ y, __half* __restrict__ yh) {
    extern __shared__ char smc[];
    __half2* xs2 = reinterpret_cast<__half2*>(smc);                     // [46][512] half2
    float*   ws  = reinterpret_cast<float*>(smc + DC_WS_OFF);           // [32][240]
    float*   g_s = reinterpret_cast<float*>(smc + DC_G_OFF);            // [1024]
    float*   b_s = reinterpret_cast<float*>(smc + DC_B_OFF);            // [1024]

    const int t0  = blockIdx.x * TT;
    const int b   = blockIdx.y;
    const int tid = threadIdx.x;

    // stage x tile as fp16 (raw copy, 16B per thread-iter)
    {
        uint4* dst = reinterpret_cast<uint4*>(smc);
        const int total = XS_ROWS * (C_DIM / 8);      // 46*128 uint4
        for (int i = tid; i < total; i += 512) {
            const int r = i / (C_DIM / 8);
            const int cc = i % (C_DIM / 8);
            const int t = t0 - HALO + r;
            uint4 v = make_uint4(0u, 0u, 0u, 0u);
            if (t >= 0)
                v = reinterpret_cast<const uint4*>(&xh[((size_t)(t * B_DIM + b)) * C_DIM])[cc];
            dst[i] = v;
        }
    }
    // stage conv logits (+bias) and LN params
    for (int i = tid; i < TT * (H_DIM * K_TAPS); i += 512) {
        const int lt = i / (H_DIM * K_TAPS);
        const int j  = i % (H_DIM * K_TAPS);
        ws[i] = wraw[(size_t)((t0 + lt) * B_DIM + b) * NPAD + j] + b_lin[j];
    }
    for (int i = tid; i < C_DIM; i += 512) { g_s[i] = ln_g[i]; b_s[i] = ln_b[i]; }
    __syncthreads();

    // softmax: 32 rows x 16 heads = 512 tasks
    {
        const int lt = tid >> 4;
        const int hd = tid & 15;
        float* p = ws + lt * (H_DIM * K_TAPS) + hd * K_TAPS;
        float mx = -1e30f;
        #pragma unroll
        for (int k = 0; k < K_TAPS; k++) mx = fmaxf(mx, p[k]);
        float e[K_TAPS]; float s = 0.f;
        #pragma unroll
        for (int k = 0; k < K_TAPS; k++) { e[k] = expf(p[k] - mx); s += e[k]; }
        const float inv = 1.0f / s;
        #pragma unroll
        for (int k = 0; k < K_TAPS; k++) p[k] = e[k] * inv;
    }
    __syncthreads();

    const int w    = tid >> 5;
    const int lane = tid & 31;

    #pragma unroll
    for (int pass = 0; pass < 2; pass++) {
        const int lt = w + pass * 16;
        const float* wrow = ws + lt * (H_DIM * K_TAPS);
        float a0[16], a1[16];
        float s1 = 0.f, s2 = 0.f;
        #pragma unroll
        for (int j = 0; j < 16; j++) {     // head h = j; channels c = 2*lane + 64*j, +1
            float wk[K_TAPS];
            #pragma unroll
            for (int k = 0; k < K_TAPS; k++) wk[k] = wrow[j * K_TAPS + k];
            float acc0 = 0.f, acc1 = 0.f;
            #pragma unroll
            for (int k = 0; k < K_TAPS; k++) {
                const float2 xv = __half22float2(xs2[(lt + k) * (C_DIM / 2) + lane + 32 * j]);
                acc0 += wk[k] * xv.x;
                acc1 += wk[k] * xv.y;
            }
            a0[j] = acc0; a1[j] = acc1;
            s1 += acc0 + acc1;
            s2 += acc0 * acc0 + acc1 * acc1;
        }
        #pragma unroll
        for (int off = 16; off > 0; off >>= 1) {
            s1 += __shfl_xor_sync(0xFFFFFFFFu, s1, off);
            s2 += __shfl_xor_sync(0xFFFFFFFFu, s2, off);
        }
        const float mu   = s1 * (1.0f / C_DIM);
        const float var  = s2 * (1.0f / C_DIM) - mu * mu;
        const float rstd = rsqrtf(var + LN_EPS);

        const size_t base = (size_t)((t0 + lt) * B_DIM + b) * C_DIM;
        #pragma unroll
        for (int j = 0; j < 16; j++) {
            const int c = 2 * lane + 64 * j;
            const float v0 = (a0[j] - mu) * rstd * g_s[c]     + b_s[c];
            const float v1 = (a1[j] - mu) * rstd * g_s[c + 1] + b_s[c + 1];
            *reinterpret_cast<float2*>(&y[base + c])  = make_float2(v0, v1);
            *reinterpret_cast<__half2*>(&yh[base + c]) = __floats2half2_rn(v0, v1);
        }
    }
}

// ================= host side =================
typedef CUresult (*PFN_encodeTiled)(CUtensorMap*, CUtensorMapDataType, cuuint32_t, void*,
                                    const cuuint64_t*, const cuuint64_t*, const cuuint32_t*,
                                    const cuuint32_t*, CUtensorMapInterleave, CUtensorMapSwizzle,
                                    CUtensorMapL2promotion, CUtensorMapFloatOOBfill);

static PFN_encodeTiled get_encoder() {
    static PFN_encodeTiled fn = nullptr;
    if (!fn) {
        void* h = dlopen("libcuda.so.1", RTLD_LAZY | RTLD_GLOBAL);
        if (!h) h = dlopen("libcuda.so", RTLD_LAZY | RTLD_GLOBAL);
        if (h) fn = (PFN_encodeTiled)dlsym(h, "cuTensorMapEncodeTiled");
    }
    return fn;
}

static void make_map_h2(CUtensorMap* m, const void* ptr, uint64_t d0, uint64_t d1, uint32_t b1) {
    cuuint64_t dims[2] = { d0, d1 };
    cuuint64_t strides[1] = { d0 * 2 };
    cuuint32_t box[2] = { KE, b1 };
    cuuint32_t es[2] = { 1, 1 };
    PFN_encodeTiled enc = get_encoder();
    if (enc)
        enc(m, CU_TENSOR_MAP_DATA_TYPE_FLOAT16, 2, (void*)ptr, dims, strides, box, es,
            CU_TENSOR_MAP_INTERLEAVE_NONE, CU_TENSOR_MAP_SWIZZLE_128B,
            CU_TENSOR_MAP_L2_PROMOTION_L2_128B, CU_TENSOR_MAP_FLOAT_OOB_FILL_NONE);
}
static void make_map_h3(CUtensorMap* m, const void* ptr, uint64_t d0, uint64_t d1) {
    cuuint64_t dims[3] = { d0, d1, 1 };
    cuuint64_t strides[2] = { d0 * 2, d0 * d1 * 2 };
    cuuint32_t box[3] = { KE, 128, 1 };
    cuuint32_t es[3] = { 1, 1, 1 };
    PFN_encodeTiled enc = get_encoder();
    if (enc)
        enc(m, CU_TENSOR_MAP_DATA_TYPE_FLOAT16, 3, (void*)ptr, dims, strides, box, es,
            CU_TENSOR_MAP_INTERLEAVE_NONE, CU_TENSOR_MAP_SWIZZLE_128B,
            CU_TENSOR_MAP_L2_PROMOTION_L2_128B, CU_TENSOR_MAP_FLOAT_OOB_FILL_NONE);
}

extern "C" void kernel_launch(void* const* d_in, const int* in_sizes, int n_in,
                              void* d_out, int out_size) {
    const float* x     = (const float*)d_in[0];
    const float* w_lin = (const float*)d_in[1];
    const float* b_lin = (const float*)d_in[2];
    const float* ln_g  = (const float*)d_in[3];
    const float* ln_b  = (const float*)d_in[4];
    const float* fc1_w = (const float*)d_in[5];
    const float* fc1_b = (const float*)d_in[6];
    const float* fc2_w = (const float*)d_in[7];
    const float* fc2_b = (const float*)d_in[8];
    float* out = (float*)d_out;

    __half *xh, *wlinT, *fc1wT, *fc2wT, *yh, *h;
    float *wraw, *y;
    cudaGetSymbolAddress((void**)&xh, g_xh);
    cudaGetSymbolAddress((void**)&wlinT, g_wlinT);
    cudaGetSymbolAddress((void**)&fc1wT, g_fc1wT);
    cudaGetSymbolAddress((void**)&fc2wT, g_fc2wT);
    cudaGetSymbolAddress((void**)&wraw, g_wraw);
    cudaGetSymbolAddress((void**)&y, g_y);
    cudaGetSymbolAddress((void**)&yh, g_yh);
    cudaGetSymbolAddress((void**)&h, g_h);

    const int smem_g1  = 1024 + 5 * (128 * 128 + 128 * 128);
    const int smem_cg2 = 1024 + 4 * (2 * 128 * 128 + 128 * 128);
    cudaFuncSetAttribute((const void*)tc_gemm_plain<0, 128, 5>,
                         cudaFuncAttributeMaxDynamicSharedMemorySize, smem_g1);
    cudaFuncSetAttribute((const void*)tc_gemm_cg2<1>,
                         cudaFuncAttributeMaxDynamicSharedMemorySize, smem_cg2);
    cudaFuncSetAttribute((const void*)tc_gemm_cg2<2>,
                         cudaFuncAttributeMaxDynamicSharedMemorySize, smem_cg2);
    cudaFuncSetAttribute((const void*)dynconv_ln_kernel,
                         cudaFuncAttributeMaxDynamicSharedMemorySize, DC_SMEM);

    CUtensorMap mA1{}, mB1{}, mA2{}, mB2{}, mA3{}, mB3{};
    make_map_h2(&mA1, xh,    C_DIM, M_DIM, 128);
    make_map_h2(&mB1, wlinT, C_DIM, NPAD,  128);
    make_map_h3(&mA2, yh,    C_DIM, M_DIM);
    make_map_h3(&mB2, fc1wT, C_DIM, F_DIM);
    make_map_h3(&mA3, h,     F_DIM, M_DIM);
    make_map_h3(&mB3, fc2wT, F_DIM, C_DIM);

    dim3 tb(32, 8);
    // 1) x -> fp16
    f2h_kernel<<<(M_DIM * C_DIM / 2 + 255) / 256, 256>>>(x, xh, M_DIM * C_DIM / 2);
    // 2) w_lin^T fp16
    transpose_h2_kernel<<<dim3(NPAD / 32, C_DIM / 64), tb>>>(w_lin, wlinT, C_DIM, H_DIM * K_TAPS, NPAD);
    // 3) conv-weight projection
    tc_gemm_plain<0, 128, 5><<<dim3(NPAD / 128, M_DIM / 128), 256, smem_g1>>>(
        mA1, mB1, nullptr, nullptr, wraw, NPAD, C_DIM / KE);
    // 4) softmax + conv + LN (warp-per-timestep, barrier-free loop)
    dynconv_ln_kernel<<<dim3(T_DIM / TT, B_DIM), 512, DC_SMEM>>>(
        xh, wraw, b_lin, ln_g, ln_b, y, yh);
    // 5) fc1_w^T fp16
    transpose_h2_kernel<<<dim3(F_DIM / 32, C_DIM / 64), tb>>>(fc1_w, fc1wT, C_DIM, F_DIM, F_DIM);
    // 6) fc1 + ReLU -> fp16 h
    tc_gemm_cg2<1><<<dim3(2 * (F_DIM / 256), M_DIM / 512), 256, smem_cg2>>>(
        mA2, mB2, fc1_b, nullptr, h, F_DIM, C_DIM / KE);
    // 7) fc2_w^T fp16
    transpose_h2_kernel<<<dim3(C_DIM / 32, F_DIM / 64), tb>>>(fc2_w, fc2wT, F_DIM, C_DIM, C_DIM);
    // 8) fc2 + bias + residual -> fp32 out
    tc_gemm_cg2<2><<<dim3(2 * (C_DIM / 256), M_DIM / 512), 256, smem_cg2>>>(
        mA3, mB3, fc2_b, y, out, C_DIM, F_DIM / KE);
}

// round 12
// speedup vs baseline: 1.9080x; 1.0229x over previous
#include <cuda_runtime.h>
#include <cuda.h>
#include <cuda_fp16.h>
#include <dlfcn.h>
#include <math.h>
#include <stdint.h>

// ---------------- problem constants ----------------
#define T_DIM 1024
#define B_DIM 8
#define C_DIM 1024
#define F_DIM 4096
#define H_DIM 16
#define K_TAPS 15
#define M_DIM (T_DIM * B_DIM)   // 8192
#define NPAD 256
#define LN_EPS 1e-5f

#define KE 64                   // fp16 elements per k-chunk (128 bytes per row)

// dynconv tiling: 16 timesteps per block, 2 CTAs/SM
#define TT 16
#define HALO (K_TAPS - 1)
#define XS_ROWS (TT + HALO)                          // 30
#define DC_XS_BYTES (XS_ROWS * C_DIM * 2)            // 61440
#define DC_WS_OFF   DC_XS_BYTES
#define DC_WS_BYTES (TT * H_DIM * K_TAPS * 4)        // 15360
#define DC_G_OFF    (DC_WS_OFF + DC_WS_BYTES)
#define DC_B_OFF    (DC_G_OFF + C_DIM * 4)
#define DC_SMEM     (DC_B_OFF + C_DIM * 4)           // 84992

// arch-specific feature gate (tcgen05 only on the sm_103a pass)
#if defined(__CUDA_ARCH_FEAT_SM103_ALL) || defined(__CUDA_ARCH_FEAT_SM100_ALL) || \
    (defined(__CUDA_ARCH_SPECIFIC__) && (__CUDA_ARCH_SPECIFIC__ >= 1000)) ||      \
    (defined(__CUDA_ARCH_FAMILY_SPECIFIC__) && (__CUDA_ARCH_FAMILY_SPECIFIC__ >= 1000))
#define TC_OK 1
#else
#define TC_OK 0
#endif

// ---------------- scratch (device globals) ----------------
__device__ __half g_xh[(size_t)M_DIM * C_DIM];
__device__ __half g_wlinT[NPAD * C_DIM];
__device__ __half g_fc1wT[(size_t)F_DIM * C_DIM];
__device__ __half g_fc2wT[(size_t)C_DIM * F_DIM];
__device__ float  g_wraw[(size_t)M_DIM * NPAD];
__device__ float  g_y[(size_t)M_DIM * C_DIM];
__device__ __half g_yh[(size_t)M_DIM * C_DIM];
__device__ __half g_h[(size_t)M_DIM * F_DIM];

// ---------------- helpers ----------------
__device__ __forceinline__ uint32_t smem_u32(const void* p) {
    uint32_t a;
    asm("{ .reg .u64 t; cvta.to.shared.u64 t, %1; cvt.u32.u64 %0, t; }" : "=r"(a) : "l"(p));
    return a;
}
__device__ __forceinline__ uint32_t elect_one() {
    uint32_t p;
    asm volatile("{ .reg .pred p; elect.sync _|p, 0xFFFFFFFF; selp.b32 %0, 1, 0, p; }" : "=r"(p));
    return p;
}
__device__ __forceinline__ void mbar_init(uint32_t a, uint32_t cnt) {
    asm volatile("mbarrier.init.shared.b64 [%0], %1;" :: "r"(a), "r"(cnt) : "memory");
}
__device__ __forceinline__ void mbar_expect_tx(uint32_t a, uint32_t bytes) {
    asm volatile("mbarrier.arrive.expect_tx.shared.b64 _, [%0], %1;" :: "r"(a), "r"(bytes) : "memory");
}
__device__ __forceinline__ void mbar_wait(uint32_t a, uint32_t parity) {
    uint32_t done;
    asm volatile(
        "{ .reg .pred p;\n\t"
        "mbarrier.try_wait.parity.acquire.cta.shared::cta.b64 p, [%1], %2;\n\t"
        "selp.b32 %0, 1, 0, p; }" : "=r"(done) : "r"(a), "r"(parity) : "memory");
    if (!done) {
        asm volatile(
            "{ .reg .pred P1;\n\t"
            "WL_%=:\n\t"
            "mbarrier.try_wait.parity.acquire.cta.shared::cta.b64 P1, [%0], %1, 0x989680;\n\t"
            "@P1 bra.uni WD_%=;\n\t"
            "bra.uni WL_%=;\n\t"
            "WD_%=: }" :: "r"(a), "r"(parity) : "memory");
    }
}
#if TC_OK
__device__ __forceinline__ uint32_t cluster_rank() {
    uint32_t r;
    asm("mov.u32 %0, %%cluster_ctarank;" : "=r"(r));
    return r;
}
#define CLUSTER_SYNC() do { \
    asm volatile("barrier.cluster.arrive.aligned;" ::: "memory"); \
    asm volatile("barrier.cluster.wait.aligned;" ::: "memory");   \
} while (0)

__device__ __forceinline__ void tma_2d(uint32_t dst, const void* map, int cx, int cy, uint32_t mbar) {
    asm volatile(
        "cp.async.bulk.tensor.2d.shared::cta.global.tile.mbarrier::complete_tx::bytes "
        "[%0], [%1, {%2, %3}], [%4];"
        :: "r"(dst), "l"(map), "r"(cx), "r"(cy), "r"(mbar) : "memory");
}
__device__ __forceinline__ void tma_3d_cg2(uint32_t dst, const void* map, int cx, int cy,
                                           uint32_t mbar) {
    asm volatile(
        "{\n\t"
        ".reg .b32 leaderBar;\n\t"
        "and.b32 leaderBar, %4, 0xFEFFFFFF;\n\t"
        "cp.async.bulk.tensor.3d.cta_group::2.shared::cluster.global"
        ".tile.mbarrier::complete_tx::bytes "
        "[%0], [%1, {%2, %3, %5}], [leaderBar];\n\t"
        "}"
        :: "r"(dst), "l"(map), "r"(cx), "r"(cy), "r"(mbar), "r"(0) : "memory");
}
__device__ __forceinline__ void mma_f16_ss(uint32_t d, uint64_t adesc, uint64_t bdesc,
                                           uint32_t idesc, uint32_t en) {
    asm volatile(
        "{ .reg .pred p;\n\t"
        "setp.ne.u32 p, %4, 0;\n\t"
        "tcgen05.mma.cta_group::1.kind::f16 [%0], %1, %2, %3, p; }"
        :: "r"(d), "l"(adesc), "l"(bdesc), "r"(idesc), "r"(en) : "memory");
}
__device__ __forceinline__ void mma_f16_ss_cg2(uint32_t d, uint64_t adesc, uint64_t bdesc,
                                               uint32_t idesc, uint32_t en) {
    asm volatile(
        "{ .reg .pred p;\n\t"
        "setp.ne.u32 p, %5, 0;\n\t"
        "tcgen05.mma.cta_group::2.kind::f16 [%0], %1, %2, %3, "
        "{%4, %4, %4, %4, %4, %4, %4, %4}, p; }"
        :: "r"(d), "l"(adesc), "l"(bdesc), "r"(idesc), "r"(0u), "r"(en) : "memory");
}
__device__ __forceinline__ void tc_commit(uint32_t mbar) {
    asm volatile(
        "tcgen05.commit.cta_group::1.mbarrier::arrive::one.shared::cluster.b64 [%0];"
        :: "r"(mbar) : "memory");
}
__device__ __forceinline__ void tc_commit_mc_cg2(uint32_t mbar, uint16_t mask) {
    asm volatile(
        "tcgen05.commit.cta_group::2.mbarrier::arrive::one.shared::cluster.multicast::cluster.b64 "
        "[%0], %1;"
        :: "r"(mbar), "h"(mask) : "memory");
}
#define TC_ALLOC(smem_addr, ncols) \
    asm volatile("tcgen05.alloc.cta_group::1.sync.aligned.shared::cta.b32 [%0], %1;" \
                 :: "r"(smem_addr), "r"(ncols) : "memory")
#define TC_RELINQ() \
    asm volatile("tcgen05.relinquish_alloc_permit.cta_group::1.sync.aligned;")
#define TC_DEALLOC(tmem, ncols) \
    asm volatile("tcgen05.dealloc.cta_group::1.sync.aligned.b32 %0, %1;" :: "r"(tmem), "r"(ncols))
#define TC_ALLOC_CG2(smem_addr, ncols) \
    asm volatile("tcgen05.alloc.cta_group::2.sync.aligned.shared::cta.b32 [%0], %1;" \
                 :: "r"(smem_addr), "r"(ncols) : "memory")
#define TC_RELINQ_CG2() \
    asm volatile("tcgen05.relinquish_alloc_permit.cta_group::2.sync.aligned;")
#define TC_DEALLOC_CG2(tmem, ncols) \
    asm volatile("tcgen05.dealloc.cta_group::2.sync.aligned.b32 %0, %1;" :: "r"(tmem), "r"(ncols))
#define TC_FENCE_AFTER()  asm volatile("tcgen05.fence::after_thread_sync;" ::: "memory")
#define TC_WAIT_LD()      asm volatile("tcgen05.wait::ld.sync.aligned;" ::: "memory")
#define TC_LD_X32(r, addr) \
    asm volatile("tcgen05.ld.sync.aligned.32x32b.x32.b32 " \
        "{%0, %1, %2, %3, %4, %5, %6, %7, %8, %9, %10, %11, %12, %13, %14, %15, " \
        " %16, %17, %18, %19, %20, %21, %22, %23, %24, %25, %26, %27, %28, %29, %30, %31}, [%32];" \
        : "=r"((r)[0]), "=r"((r)[1]), "=r"((r)[2]), "=r"((r)[3]), \
          "=r"((r)[4]), "=r"((r)[5]), "=r"((r)[6]), "=r"((r)[7]), \
          "=r"((r)[8]), "=r"((r)[9]), "=r"((r)[10]), "=r"((r)[11]), \
          "=r"((r)[12]), "=r"((r)[13]), "=r"((r)[14]), "=r"((r)[15]), \
          "=r"((r)[16]), "=r"((r)[17]), "=r"((r)[18]), "=r"((r)[19]), \
          "=r"((r)[20]), "=r"((r)[21]), "=r"((r)[22]), "=r"((r)[23]), \
          "=r"((r)[24]), "=r"((r)[25]), "=r"((r)[26]), "=r"((r)[27]), \
          "=r"((r)[28]), "=r"((r)[29]), "=r"((r)[30]), "=r"((r)[31]) \
        : "r"(addr))

__device__ __forceinline__ uint64_t smem_desc_sw128(uint32_t addr) {
    return ((uint64_t)2 << 61) | ((uint64_t)1 << 46) | ((uint64_t)64 << 32) |
           ((uint64_t)1 << 16) | (((uint64_t)addr >> 4) & 0x3FFF);
}
__device__ __forceinline__ constexpr uint32_t idesc_f16(int bn, int m) {
    return (1u << 4) | ((uint32_t)(bn / 8) << 17) | ((uint32_t)(m / 16) << 24);
}
#endif  // TC_OK

#if TC_OK
template <int EPI>
__device__ __forceinline__ void epi_write_chunk(const uint32_t* r, int row, int colbase,
                                                const float* __restrict__ bias,
                                                const float* __restrict__ res,
                                                void* __restrict__ Cv, int N) {
    if (EPI == 1) {
        __half* Ch = (__half*)Cv;
        __half2* dst = reinterpret_cast<__half2*>(&Ch[(size_t)row * N + colbase]);
        #pragma unroll
        for (int j = 0; j < 32; j += 2) {
            float v0 = fmaxf(__uint_as_float(r[j + 0]) + bias[colbase + j + 0], 0.f);
            float v1 = fmaxf(__uint_as_float(r[j + 1]) + bias[colbase + j + 1], 0.f);
            dst[j / 2] = __floats2half2_rn(v0, v1);
        }
    } else {
        float* C = (float*)Cv;
        float4* dst = reinterpret_cast<float4*>(&C[(size_t)row * N + colbase]);
        #pragma unroll
        for (int j = 0; j < 32; j += 4) {
            float4 v;
            v.x = __uint_as_float(r[j + 0]);
            v.y = __uint_as_float(r[j + 1]);
            v.z = __uint_as_float(r[j + 2]);
            v.w = __uint_as_float(r[j + 3]);
            if (EPI == 2) {
                v.x += bias[colbase + j + 0]; v.y += bias[colbase + j + 1];
                v.z += bias[colbase + j + 2]; v.w += bias[colbase + j + 3];
                float4 rv = *reinterpret_cast<const float4*>(&res[(size_t)row * N + colbase + j]);
                v.x += rv.x; v.y += rv.y; v.z += rv.z; v.w += rv.w;
            }
            dst[j / 4] = v;
        }
    }
}
#endif

// ================= plain warp-specialized tcgen05 fp16 GEMM (GEMM1) =================
template <int EPI, int BN_, int STG>
__global__ __launch_bounds__(256)
void tc_gemm_plain(const __grid_constant__ CUtensorMap tmA,
                   const __grid_constant__ CUtensorMap tmB,
                   const float* __restrict__ bias, const float* __restrict__ res,
                   void* __restrict__ C, int N, int NC) {
#if TC_OK
    constexpr int CA = 128 * 128;
    constexpr int CB = BN_ * 128;
    constexpr int CBYTES = CA + CB;
    constexpr int TCOLS = BN_;

    extern __shared__ __align__(1024) char smem[];
    const int tid  = threadIdx.x;
    const int warp = tid >> 5;
    const int lane = tid & 31;

    uint32_t sb = (smem_u32(smem) + 1023u) & ~1023u;
    const uint32_t tmem_ptr_addr = sb;
    const uint32_t mb_all = sb + 8 + 16 * STG;
    uint32_t mb_full[STG], mb_done[STG], bufA[STG], bufB[STG];
    #pragma unroll
    for (int s = 0; s < STG; s++) {
        mb_full[s] = sb + 8 + 8 * s;
        mb_done[s] = sb + 8 + 8 * STG + 8 * s;
        bufA[s] = sb + 1024 + s * CBYTES;
        bufB[s] = bufA[s] + CA;
    }

    if (warp == 0) { TC_ALLOC(tmem_ptr_addr, TCOLS); TC_RELINQ(); }
    if (tid == 0) {
        #pragma unroll
        for (int s = 0; s < STG; s++) { mbar_init(mb_full[s], 1); mbar_init(mb_done[s], 1); }
        mbar_init(mb_all, 1);
    }
    __syncthreads();

    uint32_t tmem;
    asm volatile("ld.shared.b32 %0, [%1];" : "=r"(tmem) : "r"(tmem_ptr_addr));

    const int tile_m = blockIdx.y * 128;
    const int tile_n = blockIdx.x * BN_;

    if (warp == 1 && elect_one()) {
        uint32_t phd = 0;
        for (int j = 0; j < NC; j++) {
            const int s = j % STG;
            if (j >= STG) { mbar_wait(mb_done[s], (phd >> s) & 1); phd ^= 1u << s; }
            mbar_expect_tx(mb_full[s], CBYTES);
            tma_2d(bufA[s], &tmA, j * KE, tile_m, mb_full[s]);
            tma_2d(bufB[s], &tmB, j * KE, tile_n, mb_full[s]);
        }
    }
    if (warp == 0 && elect_one()) {
        uint64_t ad[STG], bd[STG];
        #pragma unroll
        for (int s = 0; s < STG; s++) {
            ad[s] = smem_desc_sw128(bufA[s]);
            bd[s] = smem_desc_sw128(bufB[s]);
        }
        uint32_t phf = 0;
        for (int kc = 0; kc < NC; kc++) {
            const int s = kc % STG;
            mbar_wait(mb_full[s], (phf >> s) & 1); phf ^= 1u << s;
            #pragma unroll
            for (int s2 = 0; s2 < 4; s2++) {
                const uint32_t en = (kc > 0 || s2 > 0) ? 1u : 0u;
                mma_f16_ss(tmem, ad[s] + 2 * s2, bd[s] + 2 * s2, idesc_f16(BN_, 128), en);
            }
            tc_commit(mb_done[s]);
        }
        tc_commit(mb_all);
        mbar_wait(mb_all, 0);
    }
    __syncthreads();
    TC_FENCE_AFTER();
    {
        const int half_ = warp >> 2;
        const uint32_t dbase = tmem + half_ * (BN_ / 2);
        const int row = tile_m + (warp & 3) * 32 + lane;
        const int col0 = tile_n + half_ * (BN_ / 2);
        #pragma unroll 1
        for (int cc = 0; cc < BN_ / 64; cc++) {
            uint32_t r[32];
            TC_LD_X32(r, dbase + cc * 32);
            TC_WAIT_LD();
            epi_write_chunk<EPI>(r, row, col0 + cc * 32, bias, res, C, N);
        }
    }
    __syncthreads();
    if (warp == 0) TC_DEALLOC(tmem, TCOLS);
#endif
}

// ================= cg2 pair GEMM: 512(M) x 256(N) per 2-CTA cluster =================
template <int EPI>
__global__ __launch_bounds__(256) __cluster_dims__(2, 1, 1)
void tc_gemm_cg2(const __grid_constant__ CUtensorMap tmA,
                 const __grid_constant__ CUtensorMap tmB,
                 const float* __restrict__ bias, const float* __restrict__ res,
                 void* __restrict__ C, int N, int NC) {
#if TC_OK
    constexpr int STG = 4;
    constexpr int CA = 2 * 128 * 128;
    constexpr int CB = 128 * 128;
    constexpr int CBYTES = CA + CB;
    constexpr int PAIR_BYTES = 2 * CBYTES;
    constexpr int TCOLS = 512;

    extern __shared__ __align__(1024) char smem[];
    const int tid  = threadIdx.x;
    const int warp = tid >> 5;
    const int lane = tid & 31;

    uint32_t sb = (smem_u32(smem) + 1023u) & ~1023u;
    const uint32_t tmem_ptr_addr = sb;
    const uint32_t mb_all = sb + 8 + 16 * STG;
    uint32_t mb_full[STG], mb_done[STG], bufA[STG], bufB[STG];
    #pragma unroll
    for (int s = 0; s < STG; s++) {
        mb_full[s] = sb + 8 + 8 * s;
        mb_done[s] = sb + 8 + 8 * STG + 8 * s;
        bufA[s] = sb + 1024 + s * CBYTES;
        bufB[s] = bufA[s] + CA;
    }

    if (warp == 0) { TC_ALLOC_CG2(tmem_ptr_addr, TCOLS); TC_RELINQ_CG2(); }
    if (tid == 0) {
        #pragma unroll
        for (int s = 0; s < STG; s++) { mbar_init(mb_full[s], 1); mbar_init(mb_done[s], 1); }
        mbar_init(mb_all, 1);
    }
    __syncthreads();
    CLUSTER_SYNC();

    uint32_t tmem;
    asm volatile("ld.shared.b32 %0, [%1];" : "=r"(tmem) : "r"(tmem_ptr_addr));

    const int rank  = (int)cluster_rank();
    const int tile_m = blockIdx.y * 512;
    const int tile_n = (blockIdx.x >> 1) * 256;

    if (warp == 1 && elect_one()) {
        uint32_t phd = 0;
        const int rowA0 = tile_m + rank * 128;
        const int rowA1 = tile_m + 256 + rank * 128;
        const int rowB  = tile_n + rank * 128;
        for (int j = 0; j < NC; j++) {
            const int s = j % STG;
            if (j >= STG) { mbar_wait(mb_done[s], (phd >> s) & 1); phd ^= 1u << s; }
            if (rank == 0) mbar_expect_tx(mb_full[s], PAIR_BYTES);
            tma_3d_cg2(bufA[s],         &tmA, j * KE, rowA0, mb_full[s]);
            tma_3d_cg2(bufA[s] + 16384, &tmA, j * KE, rowA1, mb_full[s]);
            tma_3d_cg2(bufB[s],         &tmB, j * KE, rowB,  mb_full[s]);
        }
    }
    if (rank == 0 && warp == 0 && elect_one()) {
        uint64_t adLo[STG], adHi[STG], bd[STG];
        #pragma unroll
        for (int s = 0; s < STG; s++) {
            adLo[s] = smem_desc_sw128(bufA[s]);
            adHi[s] = smem_desc_sw128(bufA[s] + 16384);
            bd[s]   = smem_desc_sw128(bufB[s]);
        }
        uint32_t phf = 0;
        for (int kc = 0; kc < NC; kc++) {
            const int s = kc % STG;
            mbar_wait(mb_full[s], (phf >> s) & 1); phf ^= 1u << s;
            #pragma unroll
            for (int s2 = 0; s2 < 4; s2++) {
                const uint32_t en = (kc > 0 || s2 > 0) ? 1u : 0u;
                mma_f16_ss_cg2(tmem,       adLo[s] + 2 * s2, bd[s] + 2 * s2,
                               idesc_f16(256, 256), en);
                mma_f16_ss_cg2(tmem + 256, adHi[s] + 2 * s2, bd[s] + 2 * s2,
                               idesc_f16(256, 256), en);
            }
            tc_commit_mc_cg2(mb_done[s], 0x3);
        }
        tc_commit_mc_cg2(mb_all, 0x3);
    }
    __syncthreads();
    mbar_wait(mb_all, 0);
    TC_FENCE_AFTER();

    {
        const int half_ = warp >> 2;
        const uint32_t dbase = tmem + half_ * 256;
        const int row = tile_m + half_ * 256 + rank * 128 + (warp & 3) * 32 + lane;
        #pragma unroll 1
        for (int cc = 0; cc < 8; cc++) {
            uint32_t r[32];
            TC_LD_X32(r, dbase + cc * 32);
            TC_WAIT_LD();
            epi_write_chunk<EPI>(r, row, tile_n + cc * 32, bias, res, C, N);
        }
    }
    __syncthreads();
    if (warp == 0) TC_DEALLOC_CG2(tmem, TCOLS);
    CLUSTER_SYNC();
#endif
}

// ================= fused prep: x->fp16 + all three fp16 transposes =================
// block roles (blockIdx.x): [0, 16384) f2h; then t_wlin 128; t_fc1 2048; t_fc2 2048.
#define F2H_BLOCKS 16384
#define TW_BLOCKS  128
#define T1_BLOCKS  2048
#define T2_BLOCKS  2048
#define PREP_BLOCKS (F2H_BLOCKS + TW_BLOCKS + T1_BLOCKS + T2_BLOCKS)

__global__ void prep_kernel(const float* __restrict__ x, __half* __restrict__ xh,
                            const float* __restrict__ w_lin, __half* __restrict__ wlinT,
                            const float* __restrict__ fc1_w, __half* __restrict__ fc1wT,
                            const float* __restrict__ fc2_w, __half* __restrict__ fc2wT) {
    __shared__ float tile[64][33];
    const int tx = threadIdx.x, ty = threadIdx.y;
    int bid = blockIdx.x;

    if (bid < F2H_BLOCKS) {
        const int i = bid * 256 + ty * 32 + tx;
        float2 v = reinterpret_cast<const float2*>(x)[i];
        reinterpret_cast<__half2*>(xh)[i] = __floats2half2_rn(v.x, v.y);
        return;
    }
    bid -= F2H_BLOCKS;

    const float* in; __half* out;
    int R, Cc, Cp, gx;
    if (bid < TW_BLOCKS) {
        in = w_lin; out = wlinT; R = C_DIM; Cc = H_DIM * K_TAPS; Cp = NPAD; gx = NPAD / 32;
    } else if (bid < TW_BLOCKS + T1_BLOCKS) {
        bid -= TW_BLOCKS;
        in = fc1_w; out = fc1wT; R = C_DIM; Cc = F_DIM; Cp = F_DIM; gx = F_DIM / 32;
    } else {
        bid -= TW_BLOCKS + T1_BLOCKS;
        in = fc2_w; out = fc2wT; R = F_DIM; Cc = C_DIM; Cp = C_DIM; gx = C_DIM / 32;
    }
    const int c0 = (bid % gx) * 32;
    const int r0 = (bid / gx) * 64;

    #pragma unroll
    for (int i = 0; i < 64; i += 8) {
        const int y = r0 + ty + i;
        const int xq = c0 + tx;
        float v = 0.f;
        if (xq < Cc && y < R) v = in[(size_t)y * Cc + xq];
        tile[ty + i][tx] = v;
    }
    __syncthreads();
    #pragma unroll
    for (int i = 0; i < 32; i += 8) {
        const int oy = c0 + ty + i;
        const int ox = r0 + 2 * tx;
        if (oy < Cp) {
            __half2 v = __floats2half2_rn(tile[2 * tx][ty + i], tile[2 * tx + 1][ty + i]);
            *reinterpret_cast<__half2*>(&out[(size_t)oy * R + ox]) = v;
        }
    }
}

// ================= warp-per-timestep softmax + causal conv + LayerNorm =================
// TT=16: 16 warps, warp w owns lt=w. half2 accumul. storage (low regs), 2 CTAs/SM.
__global__ __launch_bounds__(512, 2)
void dynconv_ln_kernel(const __half* __restrict__ xh, const float* __restrict__ wraw,
                       const float* __restrict__ b_lin,
                       const float* __restrict__ ln_g, const float* __restrict__ ln_b,
                       float* __restrict__ y, __half* __restrict__ yh) {
    extern __shared__ char smc[];
    __half2* xs2 = reinterpret_cast<__half2*>(smc);                 // [30][512] half2
    float*   ws  = reinterpret_cast<float*>(smc + DC_WS_OFF);       // [16][240]
    float*   g_s = reinterpret_cast<float*>(smc + DC_G_OFF);
    float*   b_s = reinterpret_cast<float*>(smc + DC_B_OFF);

    const int t0  = blockIdx.x * TT;
    const int b   = blockIdx.y;
    const int tid = threadIdx.x;

    // stage x tile (fp16 raw copy)
    {
        uint4* dst = reinterpret_cast<uint4*>(smc);
        const int total = XS_ROWS * (C_DIM / 8);
        for (int i = tid; i < total; i += 512) {
            const int r = i / (C_DIM / 8);
            const int cc = i % (C_DIM / 8);
            const int t = t0 - HALO + r;
            uint4 v = make_uint4(0u, 0u, 0u, 0u);
            if (t >= 0)
                v = reinterpret_cast<const uint4*>(&xh[((size_t)(t * B_DIM + b)) * C_DIM])[cc];
            dst[i] = v;
        }
    }
    for (int i = tid; i < TT * (H_DIM * K_TAPS); i += 512) {
        const int lt = i / (H_DIM * K_TAPS);
        const int j  = i % (H_DIM * K_TAPS);
        ws[i] = wraw[(size_t)((t0 + lt) * B_DIM + b) * NPAD + j] + b_lin[j];
    }
    for (int i = tid; i < C_DIM; i += 512) { g_s[i] = ln_g[i]; b_s[i] = ln_b[i]; }
    __syncthreads();

    // softmax: 16 rows x 16 heads = 256 tasks
    if (tid < TT * H_DIM) {
        const int lt = tid >> 4;
        const int hd = tid & 15;
        float* p = ws + lt * (H_DIM * K_TAPS) + hd * K_TAPS;
        float mx = -1e30f;
        #pragma unroll
        for (int k = 0; k < K_TAPS; k++) mx = fmaxf(mx, p[k]);
        float e[K_TAPS]; float s = 0.f;
        #pragma unroll
        for (int k = 0; k < K_TAPS; k++) { e[k] = expf(p[k] - mx); s += e[k]; }
        const float inv = 1.0f / s;
        #pragma unroll
        for (int k = 0; k < K_TAPS; k++) p[k] = e[k] * inv;
    }
    __syncthreads();

    const int w    = tid >> 5;     // 0..15 = lt
    const int lane = tid & 31;
    const float* wrow = ws + w * (H_DIM * K_TAPS);

    __half2 ah[16];
    float s1 = 0.f, s2 = 0.f;
    #pragma unroll
    for (int j = 0; j < 16; j++) {       // head h = j; channels 2*lane + 64*j, +1
        float acc0 = 0.f, acc1 = 0.f;
        #pragma unroll
        for (int k = 0; k < K_TAPS; k++) {
            const float wgt = wrow[j * K_TAPS + k];        // warp-broadcast LDS
            const float2 xv = __half22float2(xs2[(w + k) * (C_DIM / 2) + lane + 32 * j]);
            acc0 += wgt * xv.x;
            acc1 += wgt * xv.y;
        }
        ah[j] = __floats2half2_rn(acc0, acc1);
        s1 += acc0 + acc1;
        s2 += acc0 * acc0 + acc1 * acc1;
    }
    #pragma unroll
    for (int off = 16; off > 0; off >>= 1) {
        s1 += __shfl_xor_sync(0xFFFFFFFFu, s1, off);
        s2 += __shfl_xor_sync(0xFFFFFFFFu, s2, off);
    }
    const float mu   = s1 * (1.0f / C_DIM);
    const float var  = s2 * (1.0f / C_DIM) - mu * mu;
    const float rstd = rsqrtf(var + LN_EPS);

    const size_t base = (size_t)((t0 + w) * B_DIM + b) * C_DIM;
    #pragma unroll
    for (int j = 0; j < 16; j++) {
        const int c = 2 * lane + 64 * j;
        const float2 a = __half22float2(ah[j]);
        const float v0 = (a.x - mu) * rstd * g_s[c]     + b_s[c];
        const float v1 = (a.y - mu) * rstd * g_s[c + 1] + b_s[c + 1];
        *reinterpret_cast<float2*>(&y[base + c])   = make_float2(v0, v1);
        *reinterpret_cast<__half2*>(&yh[base + c]) = __floats2half2_rn(v0, v1);
    }
}

// ================= host side =================
typedef CUresult (*PFN_encodeTiled)(CUtensorMap*, CUtensorMapDataType, cuuint32_t, void*,
                                    const cuuint64_t*, const cuuint64_t*, const cuuint32_t*,
                                    const cuuint32_t*, CUtensorMapInterleave, CUtensorMapSwizzle,
                                    CUtensorMapL2promotion, CUtensorMapFloatOOBfill);

static PFN_encodeTiled get_encoder() {
    static PFN_encodeTiled fn = nullptr;
    if (!fn) {
        void* h = dlopen("libcuda.so.1", RTLD_LAZY | RTLD_GLOBAL);
        if (!h) h = dlopen("libcuda.so", RTLD_LAZY | RTLD_GLOBAL);
        if (h) fn = (PFN_encodeTiled)dlsym(h, "cuTensorMapEncodeTiled");
    }
    return fn;
}

static void make_map_h2(CUtensorMap* m, const void* ptr, uint64_t d0, uint64_t d1, uint32_t b1) {
    cuuint64_t dims[2] = { d0, d1 };
    cuuint64_t strides[1] = { d0 * 2 };
    cuuint32_t box[2] = { KE, b1 };
    cuuint32_t es[2] = { 1, 1 };
    PFN_encodeTiled enc = get_encoder();
    if (enc)
        enc(m, CU_TENSOR_MAP_DATA_TYPE_FLOAT16, 2, (void*)ptr, dims, strides, box, es,
            CU_TENSOR_MAP_INTERLEAVE_NONE, CU_TENSOR_MAP_SWIZZLE_128B,
            CU_TENSOR_MAP_L2_PROMOTION_L2_128B, CU_TENSOR_MAP_FLOAT_OOB_FILL_NONE);
}
static void make_map_h3(CUtensorMap* m, const void* ptr, uint64_t d0, uint64_t d1) {
    cuuint64_t dims[3] = { d0, d1, 1 };
    cuuint64_t strides[2] = { d0 * 2, d0 * d1 * 2 };
    cuuint32_t box[3] = { KE, 128, 1 };
    cuuint32_t es[3] = { 1, 1, 1 };
    PFN_encodeTiled enc = get_encoder();
    if (enc)
        enc(m, CU_TENSOR_MAP_DATA_TYPE_FLOAT16, 3, (void*)ptr, dims, strides, box, es,
            CU_TENSOR_MAP_INTERLEAVE_NONE, CU_TENSOR_MAP_SWIZZLE_128B,
            CU_TENSOR_MAP_L2_PROMOTION_L2_128B, CU_TENSOR_MAP_FLOAT_OOB_FILL_NONE);
}

extern "C" void kernel_launch(void* const* d_in, const int* in_sizes, int n_in,
                              void* d_out, int out_size) {
    const float* x     = (const float*)d_in[0];
    const float* w_lin = (const float*)d_in[1];
    const float* b_lin = (const float*)d_in[2];
    const float* ln_g  = (const float*)d_in[3];
    const float* ln_b  = (const float*)d_in[4];
    const float* fc1_w = (const float*)d_in[5];
    const float* fc1_b = (const float*)d_in[6];
    const float* fc2_w = (const float*)d_in[7];
    const float* fc2_b = (const float*)d_in[8];
    float* out = (float*)d_out;

    __half *xh, *wlinT, *fc1wT, *fc2wT, *yh, *h;
    float *wraw, *y;
    cudaGetSymbolAddress((void**)&xh, g_xh);
    cudaGetSymbolAddress((void**)&wlinT, g_wlinT);
    cudaGetSymbolAddress((void**)&fc1wT, g_fc1wT);
    cudaGetSymbolAddress((void**)&fc2wT, g_fc2wT);
    cudaGetSymbolAddress((void**)&wraw, g_wraw);
    cudaGetSymbolAddress((void**)&y, g_y);
    cudaGetSymbolAddress((void**)&yh, g_yh);
    cudaGetSymbolAddress((void**)&h, g_h);

    const int smem_g1  = 1024 + 5 * (128 * 128 + 128 * 128);
    const int smem_cg2 = 1024 + 4 * (2 * 128 * 128 + 128 * 128);
    cudaFuncSetAttribute((const void*)tc_gemm_plain<0, 128, 5>,
                         cudaFuncAttributeMaxDynamicSharedMemorySize, smem_g1);
    cudaFuncSetAttribute((const void*)tc_gemm_cg2<1>,
                         cudaFuncAttributeMaxDynamicSharedMemorySize, smem_cg2);
    cudaFuncSetAttribute((const void*)tc_gemm_cg2<2>,
                         cudaFuncAttributeMaxDynamicSharedMemorySize, smem_cg2);
    cudaFuncSetAttribute((const void*)dynconv_ln_kernel,
                         cudaFuncAttributeMaxDynamicSharedMemorySize, DC_SMEM);

    CUtensorMap mA1{}, mB1{}, mA2{}, mB2{}, mA3{}, mB3{};
    make_map_h2(&mA1, xh,    C_DIM, M_DIM, 128);
    make_map_h2(&mB1, wlinT, C_DIM, NPAD,  128);
    make_map_h3(&mA2, yh,    C_DIM, M_DIM);
    make_map_h3(&mB2, fc1wT, C_DIM, F_DIM);
    make_map_h3(&mA3, h,     F_DIM, M_DIM);
    make_map_h3(&mB3, fc2wT, F_DIM, C_DIM);

    // 1) fused prep (x->fp16 + 3 transposes)
    prep_kernel<<<PREP_BLOCKS, dim3(32, 8)>>>(x, xh, w_lin, wlinT, fc1_w, fc1wT, fc2_w, fc2wT);
    // 2) conv-weight projection
    tc_gemm_plain<0, 128, 5><<<dim3(NPAD / 128, M_DIM / 128), 256, smem_g1>>>(
        mA1, mB1, nullptr, nullptr, wraw, NPAD, C_DIM / KE);
    // 3) softmax + conv + LN
    dynconv_ln_kernel<<<dim3(T_DIM / TT, B_DIM), 512, DC_SMEM>>>(
        xh, wraw, b_lin, ln_g, ln_b, y, yh);
    // 4) fc1 + ReLU -> fp16 h    <-- launch #4 = profiled
    tc_gemm_cg2<1><<<dim3(2 * (F_DIM / 256), M_DIM / 512), 256, smem_cg2>>>(
        mA2, mB2, fc1_b, nullptr, h, F_DIM, C_DIM / KE);
    // 5) fc2 + bias + residual -> fp32 out
    tc_gemm_cg2<2><<<dim3(2 * (C_DIM / 256), M_DIM / 512), 256, smem_cg2>>>(
        mA3, mB3, fc2_b, y, out, C_DIM, F_DIM / KE);
}